// round 2
// baseline (speedup 1.0000x reference)
#include <cuda_runtime.h>
#include <cuda_bf16.h>

#define BB   4
#define NN   4096
#define DD   1024
#define AP   256
#define QS   0.06f

// Scratch (allocation-free rule: __device__ globals)
__device__ float g_Q[BB*NN*DD];   // 64 MB
__device__ float g_K[BB*NN*DD];
__device__ float g_V[BB*NN*DD];
__device__ float g_Y[BB*NN*DD];

// ---------------------------------------------------------------------------
// zero float4 region
// ---------------------------------------------------------------------------
__global__ void zero_f4(float4* __restrict__ p, int n4) {
    int i = blockIdx.x * blockDim.x + threadIdx.x;
    int stride = gridDim.x * blockDim.x;
    float4 z = make_float4(0.f, 0.f, 0.f, 0.f);
    for (; i < n4; i += stride) p[i] = z;
}

// ---------------------------------------------------------------------------
// C[M,Nc] = scale * A[M,Kd] @ B[Nc,Kd]^T   (both row-major, NT form)
// 64x64 tile, BK=16, 256 threads, 4x4 per thread
// ---------------------------------------------------------------------------
__global__ void __launch_bounds__(256) gemm_nt64(
    const float* __restrict__ A, const float* __restrict__ Bw,
    float* __restrict__ C, int M, int Nc, int Kd, float scale)
{
    __shared__ float As[16][64];
    __shared__ float Bs[16][64];
    const int tx = threadIdx.x & 15;
    const int ty = threadIdx.x >> 4;
    const int row0 = blockIdx.y * 64;
    const int col0 = blockIdx.x * 64;
    const int lr = threadIdx.x >> 2;          // 0..63
    const int lk = (threadIdx.x & 3) << 2;    // 0,4,8,12
    float acc[4][4] = {};
    const float* Ap = A  + (size_t)(row0 + lr) * Kd + lk;
    const float* Bp = Bw + (size_t)(col0 + lr) * Kd + lk;
    for (int k0 = 0; k0 < Kd; k0 += 16) {
        float4 av = *(const float4*)(Ap + k0);
        float4 bv = *(const float4*)(Bp + k0);
        __syncthreads();
        As[lk+0][lr]=av.x; As[lk+1][lr]=av.y; As[lk+2][lr]=av.z; As[lk+3][lr]=av.w;
        Bs[lk+0][lr]=bv.x; Bs[lk+1][lr]=bv.y; Bs[lk+2][lr]=bv.z; Bs[lk+3][lr]=bv.w;
        __syncthreads();
#pragma unroll
        for (int kk = 0; kk < 16; kk++) {
            float4 a = *(const float4*)&As[kk][ty<<2];
            float4 b = *(const float4*)&Bs[kk][tx<<2];
            acc[0][0]+=a.x*b.x; acc[0][1]+=a.x*b.y; acc[0][2]+=a.x*b.z; acc[0][3]+=a.x*b.w;
            acc[1][0]+=a.y*b.x; acc[1][1]+=a.y*b.y; acc[1][2]+=a.y*b.z; acc[1][3]+=a.y*b.w;
            acc[2][0]+=a.z*b.x; acc[2][1]+=a.z*b.y; acc[2][2]+=a.z*b.z; acc[2][3]+=a.z*b.w;
            acc[3][0]+=a.w*b.x; acc[3][1]+=a.w*b.y; acc[3][2]+=a.w*b.z; acc[3][3]+=a.w*b.w;
        }
    }
#pragma unroll
    for (int i = 0; i < 4; i++) {
        float4 o = make_float4(acc[i][0]*scale, acc[i][1]*scale,
                               acc[i][2]*scale, acc[i][3]*scale);
        *(float4*)&C[(size_t)(row0 + (ty<<2) + i) * Nc + col0 + (tx<<2)] = o;
    }
}

// ---------------------------------------------------------------------------
// Banded logits: att[b,i,j] = Q[b,i]·K[b,j] for |i-j| < AP
// One block = 64x64 tile near the diagonal; jt = it - 4 + blockIdx.x
// ---------------------------------------------------------------------------
__global__ void __launch_bounds__(256) band_logits(
    const float* __restrict__ Qg, const float* __restrict__ Kg,
    float* __restrict__ att)
{
    const int b  = blockIdx.z;
    const int it = blockIdx.y;
    const int jt = it + (int)blockIdx.x - 4;
    if (jt < 0 || jt >= NN/64) return;

    const float* A  = Qg + ((size_t)b << 22);  // b * 4096 * 1024
    const float* Bw = Kg + ((size_t)b << 22);
    float* attb = att + ((size_t)b << 24);     // b * 4096 * 4096

    __shared__ float As[16][64];
    __shared__ float Bs[16][64];
    const int tx = threadIdx.x & 15;
    const int ty = threadIdx.x >> 4;
    const int row0 = it * 64;
    const int col0 = jt * 64;
    const int lr = threadIdx.x >> 2;
    const int lk = (threadIdx.x & 3) << 2;
    float acc[4][4] = {};
    const float* Ap = A  + (size_t)(row0 + lr) * DD + lk;
    const float* Bp = Bw + (size_t)(col0 + lr) * DD + lk;
    for (int k0 = 0; k0 < DD; k0 += 16) {
        float4 av = *(const float4*)(Ap + k0);
        float4 bv = *(const float4*)(Bp + k0);
        __syncthreads();
        As[lk+0][lr]=av.x; As[lk+1][lr]=av.y; As[lk+2][lr]=av.z; As[lk+3][lr]=av.w;
        Bs[lk+0][lr]=bv.x; Bs[lk+1][lr]=bv.y; Bs[lk+2][lr]=bv.z; Bs[lk+3][lr]=bv.w;
        __syncthreads();
#pragma unroll
        for (int kk = 0; kk < 16; kk++) {
            float4 a = *(const float4*)&As[kk][ty<<2];
            float4 b4 = *(const float4*)&Bs[kk][tx<<2];
            acc[0][0]+=a.x*b4.x; acc[0][1]+=a.x*b4.y; acc[0][2]+=a.x*b4.z; acc[0][3]+=a.x*b4.w;
            acc[1][0]+=a.y*b4.x; acc[1][1]+=a.y*b4.y; acc[1][2]+=a.y*b4.z; acc[1][3]+=a.y*b4.w;
            acc[2][0]+=a.z*b4.x; acc[2][1]+=a.z*b4.y; acc[2][2]+=a.z*b4.z; acc[2][3]+=a.z*b4.w;
            acc[3][0]+=a.w*b4.x; acc[3][1]+=a.w*b4.y; acc[3][2]+=a.w*b4.z; acc[3][3]+=a.w*b4.w;
        }
    }
#pragma unroll
    for (int i = 0; i < 4; i++) {
        int gi = row0 + (ty<<2) + i;
#pragma unroll
        for (int j = 0; j < 4; j++) {
            int gj = col0 + (tx<<2) + j;
            int d = gi - gj;
            if (d > -AP && d < AP)
                attb[(size_t)gi * NN + gj] = acc[i][j];
        }
    }
}

// ---------------------------------------------------------------------------
// In-place band softmax, one block (128 thr) per row; <=511 valid elements
// ---------------------------------------------------------------------------
__global__ void __launch_bounds__(128) band_softmax(float* __restrict__ att) {
    __shared__ float red[4];
    const int gid = blockIdx.x;           // 0 .. B*N-1
    const int b = gid >> 12;
    const int i = gid & (NN - 1);
    float* row = att + ((size_t)b << 24) + ((size_t)i << 12);
    int jlo = i - (AP - 1); if (jlo < 0) jlo = 0;
    int jhi = i + (AP - 1); if (jhi > NN - 1) jhi = NN - 1;
    const int cnt = jhi - jlo + 1;        // <= 511

    float v[4];
    int nc = 0;
    float m = -1e30f;
    for (int t = threadIdx.x; t < cnt; t += 128) {
        v[nc] = row[jlo + t];
        m = fmaxf(m, v[nc]);
        nc++;
    }
    for (int o = 16; o > 0; o >>= 1) m = fmaxf(m, __shfl_xor_sync(0xffffffffu, m, o));
    const int w = threadIdx.x >> 5;
    if ((threadIdx.x & 31) == 0) red[w] = m;
    __syncthreads();
    m = fmaxf(fmaxf(red[0], red[1]), fmaxf(red[2], red[3]));
    __syncthreads();

    float s = 0.f;
    for (int c = 0; c < nc; c++) { v[c] = __expf(v[c] - m); s += v[c]; }
    for (int o = 16; o > 0; o >>= 1) s += __shfl_xor_sync(0xffffffffu, s, o);
    if ((threadIdx.x & 31) == 0) red[w] = s;
    __syncthreads();
    s = red[0] + red[1] + red[2] + red[3];
    const float inv = 1.0f / s;

    nc = 0;
    for (int t = threadIdx.x; t < cnt; t += 128) {
        row[jlo + t] = v[nc] * inv;
        nc++;
    }
}

// ---------------------------------------------------------------------------
// Y[b,n,o] = sum_m att[b,m,n] * V[b,m,o]   (transposed attention, banded)
// Block computes 64n x 64o output tile; m chunks of 16 over the band
// ---------------------------------------------------------------------------
__global__ void __launch_bounds__(256) ptv(
    const float* __restrict__ att, const float* __restrict__ Vg,
    float* __restrict__ Y)
{
    const int b  = blockIdx.z;
    const int nt = blockIdx.y;   // 0..63
    const int ot = blockIdx.x;   // 0..15
    const float* attb = att + ((size_t)b << 24);
    const float* Vb   = Vg  + ((size_t)b << 22);

    __shared__ float Ps[16][64];   // [m][n]
    __shared__ float Vs[16][64];   // [m][o]
    const int tx = threadIdx.x & 15;
    const int ty = threadIdx.x >> 4;
    const int mr = threadIdx.x >> 4;          // 0..15
    const int cc = (threadIdx.x & 15) << 2;   // 0..60
    const int n0 = nt << 6;
    const int o0 = ot << 6;
    float acc[4][4] = {};

    int mtlo = nt - 4; if (mtlo < 0)  mtlo = 0;
    int mthi = nt + 4; if (mthi > 63) mthi = 63;
    const int mend = (mthi << 6) + 48;

    for (int m0 = mtlo << 6; m0 <= mend; m0 += 16) {
        float4 pv = *(const float4*)&attb[(size_t)(m0 + mr) * NN + n0 + cc];
        float4 vv = *(const float4*)&Vb[(size_t)(m0 + mr) * DD + o0 + cc];
        __syncthreads();
        *(float4*)&Ps[mr][cc] = pv;
        *(float4*)&Vs[mr][cc] = vv;
        __syncthreads();
#pragma unroll
        for (int mm = 0; mm < 16; mm++) {
            float4 p = *(const float4*)&Ps[mm][ty<<2];
            float4 w = *(const float4*)&Vs[mm][tx<<2];
            acc[0][0]+=p.x*w.x; acc[0][1]+=p.x*w.y; acc[0][2]+=p.x*w.z; acc[0][3]+=p.x*w.w;
            acc[1][0]+=p.y*w.x; acc[1][1]+=p.y*w.y; acc[1][2]+=p.y*w.z; acc[1][3]+=p.y*w.w;
            acc[2][0]+=p.z*w.x; acc[2][1]+=p.z*w.y; acc[2][2]+=p.z*w.z; acc[2][3]+=p.z*w.w;
            acc[3][0]+=p.w*w.x; acc[3][1]+=p.w*w.y; acc[3][2]+=p.w*w.z; acc[3][3]+=p.w*w.w;
        }
    }
#pragma unroll
    for (int i = 0; i < 4; i++) {
        float4 o = make_float4(acc[i][0], acc[i][1], acc[i][2], acc[i][3]);
        *(float4*)&Y[((size_t)b << 22) + (size_t)(n0 + (ty<<2) + i) * DD + o0 + (tx<<2)] = o;
    }
}

// ---------------------------------------------------------------------------
extern "C" void kernel_launch(void* const* d_in, const int* in_sizes, int n_in,
                              void* d_out, int out_size)
{
    const float* x  = (const float*)d_in[0];
    const float* Wk = (const float*)d_in[1];
    const float* Wq = (const float*)d_in[2];
    const float* Wv = (const float*)d_in[3];
    const float* Wo = (const float*)d_in[4];

    float* y_out   = (float*)d_out;                      // [4,4096,1024]
    float* att_out = y_out + (size_t)BB * NN * DD;       // [4,4096,4096]

    float *Qp, *Kp, *Vp, *Yp;
    cudaGetSymbolAddress((void**)&Qp, g_Q);
    cudaGetSymbolAddress((void**)&Kp, g_K);
    cudaGetSymbolAddress((void**)&Vp, g_V);
    cudaGetSymbolAddress((void**)&Yp, g_Y);

    // 1. zero attention output (outside-band must be exactly 0)
    zero_f4<<<8192, 256>>>((float4*)att_out, (BB * NN * NN) / 4);

    // 2. projections: K = x Wk^T, Q = 0.06 * x Wq^T, V = x Wv^T
    dim3 gP(DD / 64, (BB * NN) / 64);
    gemm_nt64<<<gP, 256>>>(x, Wk, Kp, BB * NN, DD, DD, 1.0f);
    gemm_nt64<<<gP, 256>>>(x, Wq, Qp, BB * NN, DD, DD, QS);
    gemm_nt64<<<gP, 256>>>(x, Wv, Vp, BB * NN, DD, DD, 1.0f);

    // 3. banded logits into att_out
    band_logits<<<dim3(9, NN / 64, BB), 256>>>(Qp, Kp, att_out);

    // 4. in-place band softmax
    band_softmax<<<BB * NN, 128>>>(att_out);

    // 5. Y = att^T @ V (banded)
    ptv<<<dim3(DD / 64, NN / 64, BB), 256>>>(att_out, Vp, Yp);

    // 6. y_out = Y @ Wo^T
    gemm_nt64<<<gP, 256>>>(Yp, Wo, y_out, BB * NN, DD, DD, 1.0f);
}

// round 4
// speedup vs baseline: 2.6792x; 2.6792x over previous
#include <cuda_runtime.h>
#include <cuda_bf16.h>
#include <cstdint>

#define BB   4
#define NN   4096
#define DD   1024
#define AP   256
#define QS   0.06f

#define NSTAGE   3
#define CHUNK_B  32768          // bytes per stage: Ah|Al|Bh|Bl, 8KB each
#define SMEM_SZ  (NSTAGE*CHUNK_B)

// ---------------------------------------------------------------------------
// device scratch (allocation-free rule)
// ---------------------------------------------------------------------------
__device__ __align__(16) __nv_bfloat16 g_xh[BB*NN*DD], g_xl[BB*NN*DD];
__device__ __align__(16) __nv_bfloat16 g_Wkh[DD*DD], g_Wkl[DD*DD];
__device__ __align__(16) __nv_bfloat16 g_Wqh[DD*DD], g_Wql[DD*DD];
__device__ __align__(16) __nv_bfloat16 g_Wvh[DD*DD], g_Wvl[DD*DD];
__device__ __align__(16) __nv_bfloat16 g_Woh[DD*DD], g_Wol[DD*DD];
__device__ __align__(16) __nv_bfloat16 g_Qh[BB*NN*DD], g_Ql[BB*NN*DD];
__device__ __align__(16) __nv_bfloat16 g_Kh[BB*NN*DD], g_Kl[BB*NN*DD];
__device__ __align__(16) float g_V[BB*NN*DD];
__device__ __align__(16) float g_Yf[BB*NN*DD];
__device__ __align__(16) __nv_bfloat16 g_Yh[BB*NN*DD], g_Yl[BB*NN*DD];

// ---------------------------------------------------------------------------
// PTX helpers — baseline (non-arch-specific) instructions only
// ---------------------------------------------------------------------------
__device__ __forceinline__ uint32_t smem_u32(const void* p) {
    uint32_t a;
    asm("{ .reg .u64 t; cvta.to.shared.u64 t, %1; cvt.u32.u64 %0, t; }" : "=r"(a) : "l"(p));
    return a;
}
__device__ __forceinline__ void cp16(uint32_t s, const void* g) {
    asm volatile("cp.async.cg.shared.global [%0], [%1], 16;" :: "r"(s), "l"(g));
}
__device__ __forceinline__ void ldsm4(uint32_t* r, uint32_t a) {
    asm volatile("ldmatrix.sync.aligned.m8n8.x4.shared.b16 {%0,%1,%2,%3}, [%4];"
        : "=r"(r[0]), "=r"(r[1]), "=r"(r[2]), "=r"(r[3]) : "r"(a));
}
__device__ __forceinline__ void mma16816(float* d, const uint32_t* a, const uint32_t* b) {
    asm volatile("mma.sync.aligned.m16n8k16.row.col.f32.bf16.bf16.f32 "
        "{%0,%1,%2,%3}, {%4,%5,%6,%7}, {%8,%9}, {%0,%1,%2,%3};"
        : "+f"(d[0]), "+f"(d[1]), "+f"(d[2]), "+f"(d[3])
        : "r"(a[0]), "r"(a[1]), "r"(a[2]), "r"(a[3]), "r"(b[0]), "r"(b[1]));
}
#define SW64(off) ((off) ^ (((off) >> 3) & 0x30))

// ---------------------------------------------------------------------------
// load one K-chunk (128x32 of Ah,Al,Bh,Bl) into a stage buffer via cp.async
// ---------------------------------------------------------------------------
__device__ __forceinline__ void issue_chunk(
    uint32_t sbase, int tid,
    const __nv_bfloat16* pAh, const __nv_bfloat16* pAl,
    const __nv_bfloat16* pBh, const __nv_bfloat16* pBl,
    int Kd, int k0)
{
#pragma unroll
    for (int j = 0; j < 2; j++) {
        int e = tid + (j << 8);
        int r = e >> 2, c = e & 3;
        uint32_t off = (uint32_t)(r << 6) + (c << 4);
        uint32_t sw = SW64(off);
        size_t g = (size_t)r * Kd + k0 + (c << 3);
        cp16(sbase +          sw, pAh + g);
        cp16(sbase +  8192u + sw, pAl + g);
        cp16(sbase + 16384u + sw, pBh + g);
        cp16(sbase + 24576u + sw, pBl + g);
    }
    asm volatile("cp.async.commit_group;" ::: "memory");
}

// ---------------------------------------------------------------------------
// compute one chunk: acc += Ah*Bh^T + Ah*Bl^T + Al*Bh^T  (2x k16 steps)
// ---------------------------------------------------------------------------
__device__ __forceinline__ void compute_chunk(
    float acc[4][4][4], uint32_t sb, int lane, int warp_m, int warp_n)
{
#pragma unroll
    for (int ks = 0; ks < 2; ks++) {
        uint32_t ah[4][4], al[4][4], bh[4][2], bl[4][2];
#pragma unroll
        for (int mi = 0; mi < 4; mi++) {
            int row = warp_m*64 + mi*16 + ((lane >> 3) & 1)*8 + (lane & 7);
            int kb  = ks*32 + (lane >> 4)*16;
            uint32_t off = (uint32_t)(row << 6) + kb;
            uint32_t a = sb + SW64(off);
            ldsm4(ah[mi], a);
            ldsm4(al[mi], a + 8192u);
        }
#pragma unroll
        for (int nj = 0; nj < 2; nj++) {
            int nr = warp_n*32 + nj*16 + (lane >> 4)*8 + (lane & 7);
            int kb = ks*32 + ((lane >> 3) & 1)*16;
            uint32_t off = (uint32_t)(nr << 6) + kb;
            uint32_t a = sb + 16384u + SW64(off);
            uint32_t t[4];
            ldsm4(t, a);
            bh[nj*2][0] = t[0]; bh[nj*2][1] = t[1];
            bh[nj*2+1][0] = t[2]; bh[nj*2+1][1] = t[3];
            ldsm4(t, a + 8192u);
            bl[nj*2][0] = t[0]; bl[nj*2][1] = t[1];
            bl[nj*2+1][0] = t[2]; bl[nj*2+1][1] = t[3];
        }
#pragma unroll
        for (int mi = 0; mi < 4; mi++)
#pragma unroll
            for (int ni = 0; ni < 4; ni++) {
                mma16816(acc[mi][ni], ah[mi], bh[ni]);
                mma16816(acc[mi][ni], ah[mi], bl[ni]);
                mma16816(acc[mi][ni], al[mi], bh[ni]);
            }
    }
}

// ---------------------------------------------------------------------------
// full pipelined mainloop over K
// ---------------------------------------------------------------------------
__device__ __forceinline__ void hmma_loop(
    float acc[4][4][4], char* smem, int tid,
    const __nv_bfloat16* pAh, const __nv_bfloat16* pAl,
    const __nv_bfloat16* pBh, const __nv_bfloat16* pBl, int Kd)
{
    const int lane = tid & 31, wid = tid >> 5;
    const int warp_m = wid >> 2, warp_n = wid & 3;
    uint32_t sb0 = smem_u32(smem);
    const int KC = Kd >> 5;

    issue_chunk(sb0,           tid, pAh, pAl, pBh, pBl, Kd, 0);
    issue_chunk(sb0 + CHUNK_B, tid, pAh, pAl, pBh, pBl, Kd, 32);

    for (int i = 0; i < KC; i++) {
        if (i + 2 < KC) {
            issue_chunk(sb0 + ((i + 2) % NSTAGE)*CHUNK_B, tid,
                        pAh, pAl, pBh, pBl, Kd, (i + 2) << 5);
            asm volatile("cp.async.wait_group 2;" ::: "memory");
        } else {
            asm volatile("cp.async.wait_group 0;" ::: "memory");
        }
        __syncthreads();
        compute_chunk(acc, sb0 + (i % NSTAGE)*CHUNK_B, lane, warp_m, warp_n);
        __syncthreads();
    }
}

// ---------------------------------------------------------------------------
// NT GEMM: C[M,Nc] = scale*(A@B^T), split-bf16.  mode 0: fp32 out; 1: h/l out
// grid = (Nc/128, M/128), 256 threads
// ---------------------------------------------------------------------------
__global__ void __launch_bounds__(256, 1) gemm_tc(
    const __nv_bfloat16* __restrict__ Ah, const __nv_bfloat16* __restrict__ Al,
    const __nv_bfloat16* __restrict__ Bh, const __nv_bfloat16* __restrict__ Bl,
    float* __restrict__ Cf, __nv_bfloat16* __restrict__ Ch, __nv_bfloat16* __restrict__ Cl,
    int Kd, int Cstride, float scale, int mode)
{
    extern __shared__ char smem[];
    const int tid = threadIdx.x, lane = tid & 31, wid = tid >> 5;
    const int warp_m = wid >> 2, warp_n = wid & 3;
    const int row0 = blockIdx.y << 7, col0 = blockIdx.x << 7;

    float acc[4][4][4] = {};
    hmma_loop(acc, smem, tid,
              Ah + (size_t)row0 * Kd, Al + (size_t)row0 * Kd,
              Bh + (size_t)col0 * Kd, Bl + (size_t)col0 * Kd, Kd);

    const int rb = row0 + warp_m*64 + (lane >> 2);
    const int cb = col0 + warp_n*32 + (lane & 3)*2;
#pragma unroll
    for (int mi = 0; mi < 4; mi++) {
#pragma unroll
        for (int ni = 0; ni < 4; ni++) {
            int r = rb + mi*16;
            int c = cb + ni*8;
            if (mode == 0) {
                float2 lo = make_float2(acc[mi][ni][0]*scale, acc[mi][ni][1]*scale);
                float2 hi = make_float2(acc[mi][ni][2]*scale, acc[mi][ni][3]*scale);
                *(float2*)&Cf[(size_t)r * Cstride + c]       = lo;
                *(float2*)&Cf[(size_t)(r + 8) * Cstride + c] = hi;
            } else {
#pragma unroll
                for (int h = 0; h < 2; h++) {
                    float v0 = acc[mi][ni][2*h + 0] * scale;
                    float v1 = acc[mi][ni][2*h + 1] * scale;
                    __nv_bfloat16 h0 = __float2bfloat16(v0);
                    __nv_bfloat16 h1 = __float2bfloat16(v1);
                    __nv_bfloat16 l0 = __float2bfloat16(v0 - __bfloat162float(h0));
                    __nv_bfloat16 l1 = __float2bfloat16(v1 - __bfloat162float(h1));
                    size_t o = (size_t)(r + 8*h) * Cstride + c;
                    *(__nv_bfloat162*)&Ch[o] = __nv_bfloat162(h0, h1);
                    *(__nv_bfloat162*)&Cl[o] = __nv_bfloat162(l0, l1);
                }
            }
        }
    }
}

// ---------------------------------------------------------------------------
// banded logits: att[b,i,j] = Q[b,i]·K[b,j] for |i-j| < AP
// grid = (5, NN/128, BB), 256 threads
// ---------------------------------------------------------------------------
__global__ void __launch_bounds__(256, 1) band_tc(
    const __nv_bfloat16* __restrict__ Qh, const __nv_bfloat16* __restrict__ Ql,
    const __nv_bfloat16* __restrict__ Kh, const __nv_bfloat16* __restrict__ Kl,
    float* __restrict__ att)
{
    const int it = blockIdx.y;
    const int jt = it + (int)blockIdx.x - 2;
    if (jt < 0 || jt >= (NN >> 7)) return;
    const int bz = blockIdx.z;

    extern __shared__ char smem[];
    const int tid = threadIdx.x, lane = tid & 31, wid = tid >> 5;
    const int warp_m = wid >> 2, warp_n = wid & 3;
    const int row0 = it << 7, col0 = jt << 7;
    const size_t boff = (size_t)bz << 22;

    float acc[4][4][4] = {};
    hmma_loop(acc, smem, tid,
              Qh + boff + (size_t)row0 * DD, Ql + boff + (size_t)row0 * DD,
              Kh + boff + (size_t)col0 * DD, Kl + boff + (size_t)col0 * DD, DD);

    float* attb = att + ((size_t)bz << 24);
    const int rb = row0 + warp_m*64 + (lane >> 2);
    const int cb = col0 + warp_n*32 + (lane & 3)*2;
#pragma unroll
    for (int mi = 0; mi < 4; mi++)
#pragma unroll
        for (int ni = 0; ni < 4; ni++)
#pragma unroll
            for (int h = 0; h < 2; h++) {
                int gi = rb + mi*16 + 8*h;
#pragma unroll
                for (int q = 0; q < 2; q++) {
                    int gj = cb + ni*8 + q;
                    int d = gi - gj;
                    if (d > -AP && d < AP)
                        attb[(size_t)gi * NN + gj] = acc[mi][ni][2*h + q];
                }
            }
}

// ---------------------------------------------------------------------------
__global__ void split_f32(const float* __restrict__ in,
                          __nv_bfloat16* __restrict__ h, __nv_bfloat16* __restrict__ l, int n)
{
    int i = blockIdx.x * blockDim.x + threadIdx.x;
    int st = gridDim.x * blockDim.x;
    for (; i < n; i += st) {
        float v = in[i];
        __nv_bfloat16 hi = __float2bfloat16(v);
        h[i] = hi;
        l[i] = __float2bfloat16(v - __bfloat162float(hi));
    }
}

__global__ void zero_f4(float4* __restrict__ p, int n4) {
    int i = blockIdx.x * blockDim.x + threadIdx.x;
    int stride = gridDim.x * blockDim.x;
    float4 z = make_float4(0.f, 0.f, 0.f, 0.f);
    for (; i < n4; i += stride) p[i] = z;
}

// ---------------------------------------------------------------------------
// in-place band softmax, one block (128 thr) per row
// ---------------------------------------------------------------------------
__global__ void __launch_bounds__(128) band_softmax(float* __restrict__ att) {
    __shared__ float red[4];
    const int gid = blockIdx.x;
    const int b = gid >> 12;
    const int i = gid & (NN - 1);
    float* row = att + ((size_t)b << 24) + ((size_t)i << 12);
    int jlo = i - (AP - 1); if (jlo < 0) jlo = 0;
    int jhi = i + (AP - 1); if (jhi > NN - 1) jhi = NN - 1;
    const int cnt = jhi - jlo + 1;

    float v[4];
    int nc = 0;
    float m = -1e30f;
    for (int t = threadIdx.x; t < cnt; t += 128) { v[nc] = row[jlo + t]; m = fmaxf(m, v[nc]); nc++; }
    for (int o = 16; o > 0; o >>= 1) m = fmaxf(m, __shfl_xor_sync(0xffffffffu, m, o));
    const int w = threadIdx.x >> 5;
    if ((threadIdx.x & 31) == 0) red[w] = m;
    __syncthreads();
    m = fmaxf(fmaxf(red[0], red[1]), fmaxf(red[2], red[3]));
    __syncthreads();

    float s = 0.f;
    for (int c = 0; c < nc; c++) { v[c] = __expf(v[c] - m); s += v[c]; }
    for (int o = 16; o > 0; o >>= 1) s += __shfl_xor_sync(0xffffffffu, s, o);
    if ((threadIdx.x & 31) == 0) red[w] = s;
    __syncthreads();
    s = red[0] + red[1] + red[2] + red[3];
    const float inv = 1.0f / s;

    nc = 0;
    for (int t = threadIdx.x; t < cnt; t += 128) { row[jlo + t] = v[nc] * inv; nc++; }
}

// ---------------------------------------------------------------------------
// Y[b,n,o] = sum_m att[b,m,n] * V[b,m,o]  (banded, fp32; 128n x 64o tile)
// grid = (16, 32, 4), 256 threads, 8x4 per-thread tile
// ---------------------------------------------------------------------------
__global__ void __launch_bounds__(256) ptv(
    const float* __restrict__ att, const float* __restrict__ Vg,
    float* __restrict__ Y)
{
    const int b  = blockIdx.z;
    const int n0 = blockIdx.y << 7;
    const int o0 = blockIdx.x << 6;
    const float* attb = att + ((size_t)b << 24);
    const float* Vb   = Vg  + ((size_t)b << 22);

    __shared__ float Ps[16][128];
    __shared__ float Vs[16][64];
    const int tid = threadIdx.x;
    const int tx = tid & 15;       // o, x4
    const int ty = tid >> 4;       // n, x8
    float acc[8][4] = {};

    int mlo = n0 - (AP - 1); if (mlo < 0) mlo = 0;
    mlo &= ~15;
    int mend = n0 + 127 + (AP - 1); if (mend > NN - 1) mend = NN - 1;

    for (int m0 = mlo; m0 <= mend; m0 += 16) {
#pragma unroll
        for (int j = 0; j < 2; j++) {
            int e = tid + (j << 8);
            int r = e >> 5, c = (e & 31) << 2;
            *(float4*)&Ps[r][c] = *(const float4*)&attb[(size_t)(m0 + r) * NN + n0 + c];
        }
        {
            int r = tid >> 4, c = (tid & 15) << 2;
            *(float4*)&Vs[r][c] = *(const float4*)&Vb[(size_t)(m0 + r) * DD + o0 + c];
        }
        __syncthreads();
#pragma unroll
        for (int kk = 0; kk < 16; kk++) {
            float4 a0 = *(const float4*)&Ps[kk][ty << 3];
            float4 a1 = *(const float4*)&Ps[kk][(ty << 3) + 4];
            float4 bv = *(const float4*)&Vs[kk][tx << 2];
            float av[8] = {a0.x,a0.y,a0.z,a0.w,a1.x,a1.y,a1.z,a1.w};
#pragma unroll
            for (int i = 0; i < 8; i++) {
                acc[i][0] += av[i]*bv.x; acc[i][1] += av[i]*bv.y;
                acc[i][2] += av[i]*bv.z; acc[i][3] += av[i]*bv.w;
            }
        }
        __syncthreads();
    }
#pragma unroll
    for (int i = 0; i < 8; i++) {
        float4 o = make_float4(acc[i][0], acc[i][1], acc[i][2], acc[i][3]);
        *(float4*)&Y[((size_t)b << 22) + (size_t)(n0 + (ty << 3) + i) * DD + o0 + (tx << 2)] = o;
    }
}

// ---------------------------------------------------------------------------
extern "C" void kernel_launch(void* const* d_in, const int* in_sizes, int n_in,
                              void* d_out, int out_size)
{
    const float* x  = (const float*)d_in[0];
    const float* Wk = (const float*)d_in[1];
    const float* Wq = (const float*)d_in[2];
    const float* Wv = (const float*)d_in[3];
    const float* Wo = (const float*)d_in[4];

    float* y_out   = (float*)d_out;
    float* att_out = y_out + (size_t)BB * NN * DD;

    __nv_bfloat16 *xh, *xl, *Wkh, *Wkl, *Wqh, *Wql, *Wvh, *Wvl, *Woh, *Wol;
    __nv_bfloat16 *Qh, *Ql, *Kh, *Kl, *Yh, *Yl;
    float *Vp, *Yp;
    cudaGetSymbolAddress((void**)&xh,  g_xh);  cudaGetSymbolAddress((void**)&xl,  g_xl);
    cudaGetSymbolAddress((void**)&Wkh, g_Wkh); cudaGetSymbolAddress((void**)&Wkl, g_Wkl);
    cudaGetSymbolAddress((void**)&Wqh, g_Wqh); cudaGetSymbolAddress((void**)&Wql, g_Wql);
    cudaGetSymbolAddress((void**)&Wvh, g_Wvh); cudaGetSymbolAddress((void**)&Wvl, g_Wvl);
    cudaGetSymbolAddress((void**)&Woh, g_Woh); cudaGetSymbolAddress((void**)&Wol, g_Wol);
    cudaGetSymbolAddress((void**)&Qh,  g_Qh);  cudaGetSymbolAddress((void**)&Ql,  g_Ql);
    cudaGetSymbolAddress((void**)&Kh,  g_Kh);  cudaGetSymbolAddress((void**)&Kl,  g_Kl);
    cudaGetSymbolAddress((void**)&Yh,  g_Yh);  cudaGetSymbolAddress((void**)&Yl,  g_Yl);
    cudaGetSymbolAddress((void**)&Vp,  g_V);   cudaGetSymbolAddress((void**)&Yp,  g_Yf);

    cudaFuncSetAttribute(gemm_tc, cudaFuncAttributeMaxDynamicSharedMemorySize, SMEM_SZ);
    cudaFuncSetAttribute(band_tc, cudaFuncAttributeMaxDynamicSharedMemorySize, SMEM_SZ);

    const int NE = BB * NN * DD;
    const int WE = DD * DD;

    // 1. zero attention output (out-of-band must be 0; ptv also reads zeros)
    zero_f4<<<8192, 256>>>((float4*)att_out, (BB * NN * NN) / 4);

    // 2. split inputs to bf16 hi/lo
    split_f32<<<8192, 256>>>(x,  xh,  xl,  NE);
    split_f32<<<1024, 256>>>(Wk, Wkh, Wkl, WE);
    split_f32<<<1024, 256>>>(Wq, Wqh, Wql, WE);
    split_f32<<<1024, 256>>>(Wv, Wvh, Wvl, WE);
    split_f32<<<1024, 256>>>(Wo, Woh, Wol, WE);

    // 3. projections (HMMA tensor cores, split-3)
    dim3 gP(DD / 128, (BB * NN) / 128);
    gemm_tc<<<gP, 256, SMEM_SZ>>>(xh, xl, Wkh, Wkl, nullptr, Kh, Kl, DD, DD, 1.0f, 1);
    gemm_tc<<<gP, 256, SMEM_SZ>>>(xh, xl, Wqh, Wql, nullptr, Qh, Ql, DD, DD, QS,   1);
    gemm_tc<<<gP, 256, SMEM_SZ>>>(xh, xl, Wvh, Wvl, Vp, nullptr, nullptr, DD, DD, 1.0f, 0);

    // 4. banded logits
    band_tc<<<dim3(5, NN / 128, BB), 256, SMEM_SZ>>>(Qh, Ql, Kh, Kl, att_out);

    // 5. in-place band softmax
    band_softmax<<<BB * NN, 128>>>(att_out);

    // 6. Y = att^T @ V (banded, fp32)
    ptv<<<dim3(DD / 64, NN / 128, BB), 256>>>(att_out, Vp, Yp);

    // 7. output projection
    split_f32<<<8192, 256>>>(Yp, Yh, Yl, NE);
    gemm_tc<<<gP, 256, SMEM_SZ>>>(Yh, Yl, Woh, Wol, y_out, nullptr, nullptr, DD, DD, 1.0f, 0);
}

// round 5
// speedup vs baseline: 3.0325x; 1.1318x over previous
#include <cuda_runtime.h>
#include <cuda_bf16.h>
#include <cstdint>

#define BB   4
#define NN   4096
#define DD   1024
#define AP   256
#define QS   0.06f

#define NSTAGE   3
#define CHUNK_B  32768          // bytes per stage (both pipelines)
#define SMEM_SZ  (NSTAGE*CHUNK_B)

// ---------------------------------------------------------------------------
// device scratch (allocation-free rule)
// ---------------------------------------------------------------------------
__device__ __align__(16) __nv_bfloat16 g_xh[BB*NN*DD], g_xl[BB*NN*DD];
__device__ __align__(16) __nv_bfloat16 g_Wkh[DD*DD], g_Wkl[DD*DD];
__device__ __align__(16) __nv_bfloat16 g_Wqh[DD*DD], g_Wql[DD*DD];
__device__ __align__(16) __nv_bfloat16 g_Wvh[DD*DD], g_Wvl[DD*DD];
__device__ __align__(16) __nv_bfloat16 g_Woh[DD*DD], g_Wol[DD*DD];
__device__ __align__(16) __nv_bfloat16 g_Qh[BB*NN*DD], g_Ql[BB*NN*DD];
__device__ __align__(16) __nv_bfloat16 g_Kh[BB*NN*DD], g_Kl[BB*NN*DD];
__device__ __align__(16) __nv_bfloat16 g_Vh[BB*NN*DD], g_Vl[BB*NN*DD];
__device__ __align__(16) __nv_bfloat16 g_Yh[BB*NN*DD], g_Yl[BB*NN*DD];
__device__ __align__(16) __nv_bfloat16 g_Ph[(size_t)BB*NN*NN], g_Pl[(size_t)BB*NN*NN];

// ---------------------------------------------------------------------------
// PTX helpers — baseline (non-arch-specific) instructions only
// ---------------------------------------------------------------------------
__device__ __forceinline__ uint32_t smem_u32(const void* p) {
    uint32_t a;
    asm("{ .reg .u64 t; cvta.to.shared.u64 t, %1; cvt.u32.u64 %0, t; }" : "=r"(a) : "l"(p));
    return a;
}
__device__ __forceinline__ void cp16(uint32_t s, const void* g) {
    asm volatile("cp.async.cg.shared.global [%0], [%1], 16;" :: "r"(s), "l"(g));
}
__device__ __forceinline__ void ldsm4(uint32_t* r, uint32_t a) {
    asm volatile("ldmatrix.sync.aligned.m8n8.x4.shared.b16 {%0,%1,%2,%3}, [%4];"
        : "=r"(r[0]), "=r"(r[1]), "=r"(r[2]), "=r"(r[3]) : "r"(a));
}
__device__ __forceinline__ void ldsm4t(uint32_t* r, uint32_t a) {
    asm volatile("ldmatrix.sync.aligned.m8n8.x4.trans.shared.b16 {%0,%1,%2,%3}, [%4];"
        : "=r"(r[0]), "=r"(r[1]), "=r"(r[2]), "=r"(r[3]) : "r"(a));
}
__device__ __forceinline__ void mma16816(float* d, const uint32_t* a, const uint32_t* b) {
    asm volatile("mma.sync.aligned.m16n8k16.row.col.f32.bf16.bf16.f32 "
        "{%0,%1,%2,%3}, {%4,%5,%6,%7}, {%8,%9}, {%0,%1,%2,%3};"
        : "+f"(d[0]), "+f"(d[1]), "+f"(d[2]), "+f"(d[3])
        : "r"(a[0]), "r"(a[1]), "r"(a[2]), "r"(a[3]), "r"(b[0]), "r"(b[1]));
}
#define SW64(off)  ((off) ^ (((off) >> 3) & 0x30))
#define SW256(off) ((off) ^ (((off) >> 4) & 0x70))

// ===========================================================================
// dense NT GEMM pipeline (64B smem rows, K-chunks of 32)
// ===========================================================================
__device__ __forceinline__ void issue_chunk(
    uint32_t sbase, int tid,
    const __nv_bfloat16* pAh, const __nv_bfloat16* pAl,
    const __nv_bfloat16* pBh, const __nv_bfloat16* pBl,
    int Kd, int k0)
{
#pragma unroll
    for (int j = 0; j < 2; j++) {
        int e = tid + (j << 8);
        int r = e >> 2, c = e & 3;
        uint32_t off = (uint32_t)(r << 6) + (c << 4);
        uint32_t sw = SW64(off);
        size_t g = (size_t)r * Kd + k0 + (c << 3);
        cp16(sbase +          sw, pAh + g);
        cp16(sbase +  8192u + sw, pAl + g);
        cp16(sbase + 16384u + sw, pBh + g);
        cp16(sbase + 24576u + sw, pBl + g);
    }
    asm volatile("cp.async.commit_group;" ::: "memory");
}

__device__ __forceinline__ void compute_chunk(
    float acc[4][4][4], uint32_t sb, int lane, int warp_m, int warp_n)
{
#pragma unroll
    for (int ks = 0; ks < 2; ks++) {
        uint32_t ah[4][4], al[4][4], bh[4][2], bl[4][2];
#pragma unroll
        for (int mi = 0; mi < 4; mi++) {
            int row = warp_m*64 + mi*16 + ((lane >> 3) & 1)*8 + (lane & 7);
            int kb  = ks*32 + (lane >> 4)*16;
            uint32_t off = (uint32_t)(row << 6) + kb;
            uint32_t a = sb + SW64(off);
            ldsm4(ah[mi], a);
            ldsm4(al[mi], a + 8192u);
        }
#pragma unroll
        for (int nj = 0; nj < 2; nj++) {
            int nr = warp_n*32 + nj*16 + (lane >> 4)*8 + (lane & 7);
            int kb = ks*32 + ((lane >> 3) & 1)*16;
            uint32_t off = (uint32_t)(nr << 6) + kb;
            uint32_t a = sb + 16384u + SW64(off);
            uint32_t t[4];
            ldsm4(t, a);
            bh[nj*2][0] = t[0]; bh[nj*2][1] = t[1];
            bh[nj*2+1][0] = t[2]; bh[nj*2+1][1] = t[3];
            ldsm4(t, a + 8192u);
            bl[nj*2][0] = t[0]; bl[nj*2][1] = t[1];
            bl[nj*2+1][0] = t[2]; bl[nj*2+1][1] = t[3];
        }
#pragma unroll
        for (int mi = 0; mi < 4; mi++)
#pragma unroll
            for (int ni = 0; ni < 4; ni++) {
                mma16816(acc[mi][ni], ah[mi], bh[ni]);
                mma16816(acc[mi][ni], ah[mi], bl[ni]);
                mma16816(acc[mi][ni], al[mi], bh[ni]);
            }
    }
}

__device__ __forceinline__ void hmma_loop(
    float acc[4][4][4], char* smem, int tid,
    const __nv_bfloat16* pAh, const __nv_bfloat16* pAl,
    const __nv_bfloat16* pBh, const __nv_bfloat16* pBl, int Kd)
{
    const int lane = tid & 31, wid = tid >> 5;
    const int warp_m = wid >> 2, warp_n = wid & 3;
    uint32_t sb0 = smem_u32(smem);
    const int KC = Kd >> 5;

    issue_chunk(sb0,           tid, pAh, pAl, pBh, pBl, Kd, 0);
    issue_chunk(sb0 + CHUNK_B, tid, pAh, pAl, pBh, pBl, Kd, 32);

    for (int i = 0; i < KC; i++) {
        if (i + 2 < KC) {
            issue_chunk(sb0 + ((i + 2) % NSTAGE)*CHUNK_B, tid,
                        pAh, pAl, pBh, pBl, Kd, (i + 2) << 5);
            asm volatile("cp.async.wait_group 2;" ::: "memory");
        } else {
            asm volatile("cp.async.wait_group 0;" ::: "memory");
        }
        __syncthreads();
        compute_chunk(acc, sb0 + (i % NSTAGE)*CHUNK_B, lane, warp_m, warp_n);
        __syncthreads();
    }
}

// ---------------------------------------------------------------------------
// NT GEMM: C[M,Nc] = scale*(A@B^T), split-bf16. mode 0: fp32 out; 1: h/l out
// ---------------------------------------------------------------------------
__global__ void __launch_bounds__(256, 1) gemm_tc(
    const __nv_bfloat16* __restrict__ Ah, const __nv_bfloat16* __restrict__ Al,
    const __nv_bfloat16* __restrict__ Bh, const __nv_bfloat16* __restrict__ Bl,
    float* __restrict__ Cf, __nv_bfloat16* __restrict__ Ch, __nv_bfloat16* __restrict__ Cl,
    int Kd, int Cstride, float scale, int mode)
{
    extern __shared__ char smem[];
    const int tid = threadIdx.x, lane = tid & 31, wid = tid >> 5;
    const int warp_m = wid >> 2, warp_n = wid & 3;
    const int row0 = blockIdx.y << 7, col0 = blockIdx.x << 7;

    float acc[4][4][4] = {};
    hmma_loop(acc, smem, tid,
              Ah + (size_t)row0 * Kd, Al + (size_t)row0 * Kd,
              Bh + (size_t)col0 * Kd, Bl + (size_t)col0 * Kd, Kd);

    const int rb = row0 + warp_m*64 + (lane >> 2);
    const int cb = col0 + warp_n*32 + (lane & 3)*2;
#pragma unroll
    for (int mi = 0; mi < 4; mi++) {
#pragma unroll
        for (int ni = 0; ni < 4; ni++) {
            int r = rb + mi*16;
            int c = cb + ni*8;
            if (mode == 0) {
                float2 lo = make_float2(acc[mi][ni][0]*scale, acc[mi][ni][1]*scale);
                float2 hi = make_float2(acc[mi][ni][2]*scale, acc[mi][ni][3]*scale);
                *(float2*)&Cf[(size_t)r * Cstride + c]       = lo;
                *(float2*)&Cf[(size_t)(r + 8) * Cstride + c] = hi;
            } else {
#pragma unroll
                for (int h = 0; h < 2; h++) {
                    float v0 = acc[mi][ni][2*h + 0] * scale;
                    float v1 = acc[mi][ni][2*h + 1] * scale;
                    __nv_bfloat16 h0 = __float2bfloat16(v0);
                    __nv_bfloat16 h1 = __float2bfloat16(v1);
                    __nv_bfloat16 l0 = __float2bfloat16(v0 - __bfloat162float(h0));
                    __nv_bfloat16 l1 = __float2bfloat16(v1 - __bfloat162float(h1));
                    size_t o = (size_t)(r + 8*h) * Cstride + c;
                    *(__nv_bfloat162*)&Ch[o] = __nv_bfloat162(h0, h1);
                    *(__nv_bfloat162*)&Cl[o] = __nv_bfloat162(l0, l1);
                }
            }
        }
    }
}

// ---------------------------------------------------------------------------
// banded logits
// ---------------------------------------------------------------------------
__global__ void __launch_bounds__(256, 1) band_tc(
    const __nv_bfloat16* __restrict__ Qh, const __nv_bfloat16* __restrict__ Ql,
    const __nv_bfloat16* __restrict__ Kh, const __nv_bfloat16* __restrict__ Kl,
    float* __restrict__ att)
{
    const int it = blockIdx.y;
    const int jt = it + (int)blockIdx.x - 2;
    if (jt < 0 || jt >= (NN >> 7)) return;
    const int bz = blockIdx.z;

    extern __shared__ char smem[];
    const int tid = threadIdx.x, lane = tid & 31, wid = tid >> 5;
    const int warp_m = wid >> 2, warp_n = wid & 3;
    const int row0 = it << 7, col0 = jt << 7;
    const size_t boff = (size_t)bz << 22;

    float acc[4][4][4] = {};
    hmma_loop(acc, smem, tid,
              Qh + boff + (size_t)row0 * DD, Ql + boff + (size_t)row0 * DD,
              Kh + boff + (size_t)col0 * DD, Kl + boff + (size_t)col0 * DD, DD);

    float* attb = att + ((size_t)bz << 24);
    const int rb = row0 + warp_m*64 + (lane >> 2);
    const int cb = col0 + warp_n*32 + (lane & 3)*2;
#pragma unroll
    for (int mi = 0; mi < 4; mi++)
#pragma unroll
        for (int ni = 0; ni < 4; ni++)
#pragma unroll
            for (int h = 0; h < 2; h++) {
                int gi = rb + mi*16 + 8*h;
#pragma unroll
                for (int q = 0; q < 2; q++) {
                    int gj = cb + ni*8 + q;
                    int d = gi - gj;
                    if (d > -AP && d < AP)
                        attb[(size_t)gi * NN + gj] = acc[mi][ni][2*h + q];
                }
            }
}

// ---------------------------------------------------------------------------
__global__ void split_f32(const float* __restrict__ in,
                          __nv_bfloat16* __restrict__ h, __nv_bfloat16* __restrict__ l, int n)
{
    int i = blockIdx.x * blockDim.x + threadIdx.x;
    int st = gridDim.x * blockDim.x;
    for (; i < n; i += st) {
        float v = in[i];
        __nv_bfloat16 hi = __float2bfloat16(v);
        h[i] = hi;
        l[i] = __float2bfloat16(v - __bfloat162float(hi));
    }
}

__global__ void zero_f4(float4* __restrict__ p, int n4) {
    int i = blockIdx.x * blockDim.x + threadIdx.x;
    int stride = gridDim.x * blockDim.x;
    float4 z = make_float4(0.f, 0.f, 0.f, 0.f);
    for (; i < n4; i += stride) p[i] = z;
}

// ---------------------------------------------------------------------------
// band softmax + split-bf16 P emit over 128-aligned padded window
// ---------------------------------------------------------------------------
__global__ void __launch_bounds__(128) band_softmax(
    float* __restrict__ att,
    __nv_bfloat16* __restrict__ Ph, __nv_bfloat16* __restrict__ Pl)
{
    __shared__ float red[4];
    const int gid = blockIdx.x;
    const int b = gid >> 12;
    const int i = gid & (NN - 1);
    const size_t rowbase = ((size_t)b << 24) + ((size_t)i << 12);
    float* row = att + rowbase;
    int jlo = i - (AP - 1); if (jlo < 0) jlo = 0;
    int jhi = i + (AP - 1); if (jhi > NN - 1) jhi = NN - 1;
    const int cnt = jhi - jlo + 1;

    float v[4];
    int nc = 0;
    float m = -1e30f;
    for (int t = threadIdx.x; t < cnt; t += 128) { v[nc] = row[jlo + t]; m = fmaxf(m, v[nc]); nc++; }
    for (int o = 16; o > 0; o >>= 1) m = fmaxf(m, __shfl_xor_sync(0xffffffffu, m, o));
    const int w = threadIdx.x >> 5;
    if ((threadIdx.x & 31) == 0) red[w] = m;
    __syncthreads();
    m = fmaxf(fmaxf(red[0], red[1]), fmaxf(red[2], red[3]));
    __syncthreads();

    float s = 0.f;
    for (int c = 0; c < nc; c++) { v[c] = __expf(v[c] - m); s += v[c]; }
    for (int o = 16; o > 0; o >>= 1) s += __shfl_xor_sync(0xffffffffu, s, o);
    if ((threadIdx.x & 31) == 0) red[w] = s;
    __syncthreads();
    s = red[0] + red[1] + red[2] + red[3];
    const float inv = 1.0f / s;

    nc = 0;
    for (int t = threadIdx.x; t < cnt; t += 128) { row[jlo + t] = v[nc] * inv; nc++; }
    __syncthreads();   // make fp32 row visible to all threads in block

    // padded window split-bf16 emit (out-of-band reads zero_f4's zeros)
    int wlo = i - 256; wlo &= ~127; if (wlo < 0) wlo = 0;
    int whi = (i + 384) & ~127; if (whi > NN) whi = NN;
    for (int n = wlo + threadIdx.x; n < whi; n += 128) {
        float f = row[n];
        __nv_bfloat16 h = __float2bfloat16(f);
        __nv_bfloat16 l = __float2bfloat16(f - __bfloat162float(h));
        Ph[rowbase + n] = h;
        Pl[rowbase + n] = l;
    }
}

// ===========================================================================
// ptv_tc: Y[b,n,o] = sum_m P[b,m,n] * V[b,m,o]  (banded, HMMA via trans-ldsm)
// tile 128n x 128o; m chunks of 32; 256B smem rows swizzled SW256
// stage layout: Ph[32][128] | Pl | Vh | Vl  (8KB each)
// ===========================================================================
__device__ __forceinline__ void ptv_issue(
    uint32_t sbase, int tid,
    const __nv_bfloat16* Phg, const __nv_bfloat16* Plg,
    const __nv_bfloat16* Vhg, const __nv_bfloat16* Vlg,
    int m0, int n0, int o0)
{
#pragma unroll
    for (int j = 0; j < 2; j++) {
        int e = tid + (j << 8);
        int r = e >> 4, c16 = e & 15;
        uint32_t off = (uint32_t)(r << 8) + (c16 << 4);
        uint32_t sw = SW256(off);
        size_t gp = (size_t)(m0 + r) * NN + n0 + (c16 << 3);
        size_t gv = (size_t)(m0 + r) * DD + o0 + (c16 << 3);
        cp16(sbase +          sw, Phg + gp);
        cp16(sbase +  8192u + sw, Plg + gp);
        cp16(sbase + 16384u + sw, Vhg + gv);
        cp16(sbase + 24576u + sw, Vlg + gv);
    }
    asm volatile("cp.async.commit_group;" ::: "memory");
}

__device__ __forceinline__ void ptv_compute(
    float acc[4][4][4], uint32_t sb, int lane, int warp_m, int warp_n)
{
#pragma unroll
    for (int ks = 0; ks < 2; ks++) {
        const int m16 = ks << 4;
        uint32_t ah[4][4], al[4][4], bh[4][2], bl[4][2];
        // A = P^T fragments: tiles t: row_m = m16 + (t>>1)*8 + r, col_n = nb + (t&1)*8
        const int ar = m16 + ((lane >> 4) << 3) + (lane & 7);
        const int acsel = ((lane >> 3) & 1) << 3;
#pragma unroll
        for (int mi = 0; mi < 4; mi++) {
            int nb = warp_m*64 + mi*16 + acsel;
            uint32_t off = (uint32_t)(ar << 8) + (nb << 1);
            uint32_t a = sb + SW256(off);
            ldsm4t(ah[mi], a);
            ldsm4t(al[mi], a + 8192u);
        }
        // B = V^T fragments: tiles t: row_m = m16 + (t&1)*8 + r, col_o = ob + (t>>1)*8
        const int br = m16 + (((lane >> 3) & 1) << 3) + (lane & 7);
        const int bcsel = (lane >> 4) << 3;
#pragma unroll
        for (int jb = 0; jb < 2; jb++) {
            int ob = warp_n*32 + jb*16 + bcsel;
            uint32_t off = (uint32_t)(br << 8) + (ob << 1);
            uint32_t a = sb + 16384u + SW256(off);
            uint32_t t4[4];
            ldsm4t(t4, a);
            bh[jb*2][0] = t4[0]; bh[jb*2][1] = t4[1];
            bh[jb*2+1][0] = t4[2]; bh[jb*2+1][1] = t4[3];
            ldsm4t(t4, a + 8192u);
            bl[jb*2][0] = t4[0]; bl[jb*2][1] = t4[1];
            bl[jb*2+1][0] = t4[2]; bl[jb*2+1][1] = t4[3];
        }
#pragma unroll
        for (int mi = 0; mi < 4; mi++)
#pragma unroll
            for (int ni = 0; ni < 4; ni++) {
                mma16816(acc[mi][ni], ah[mi], bh[ni]);
                mma16816(acc[mi][ni], ah[mi], bl[ni]);
                mma16816(acc[mi][ni], al[mi], bh[ni]);
            }
    }
}

__global__ void __launch_bounds__(256, 1) ptv_tc(
    const __nv_bfloat16* __restrict__ Phg, const __nv_bfloat16* __restrict__ Plg,
    const __nv_bfloat16* __restrict__ Vhg, const __nv_bfloat16* __restrict__ Vlg,
    __nv_bfloat16* __restrict__ Yh, __nv_bfloat16* __restrict__ Yl)
{
    const int bz = blockIdx.z;
    const int n0 = blockIdx.y << 7;
    const int o0 = blockIdx.x << 7;
    const __nv_bfloat16* Pb_h = Phg + ((size_t)bz << 24);
    const __nv_bfloat16* Pb_l = Plg + ((size_t)bz << 24);
    const __nv_bfloat16* Vb_h = Vhg + ((size_t)bz << 22);
    const __nv_bfloat16* Vb_l = Vlg + ((size_t)bz << 22);

    extern __shared__ char smem[];
    uint32_t sb0 = smem_u32(smem);
    const int tid = threadIdx.x, lane = tid & 31, wid = tid >> 5;
    const int warp_m = wid >> 2, warp_n = wid & 3;

    int mlo = n0 - 256; if (mlo < 0) mlo = 0;
    int mhe = n0 + 384; if (mhe > NN) mhe = NN;
    const int NC = (mhe - mlo) >> 5;

    float acc[4][4][4] = {};

    ptv_issue(sb0,           tid, Pb_h, Pb_l, Vb_h, Vb_l, mlo,      n0, o0);
    ptv_issue(sb0 + CHUNK_B, tid, Pb_h, Pb_l, Vb_h, Vb_l, mlo + 32, n0, o0);

    for (int i = 0; i < NC; i++) {
        if (i + 2 < NC) {
            ptv_issue(sb0 + ((i + 2) % NSTAGE)*CHUNK_B, tid,
                      Pb_h, Pb_l, Vb_h, Vb_l, mlo + ((i + 2) << 5), n0, o0);
            asm volatile("cp.async.wait_group 2;" ::: "memory");
        } else {
            asm volatile("cp.async.wait_group 0;" ::: "memory");
        }
        __syncthreads();
        ptv_compute(acc, sb0 + (i % NSTAGE)*CHUNK_B, lane, warp_m, warp_n);
        __syncthreads();
    }

    // epilogue: split-bf16 Y
    __nv_bfloat16* Ybh = Yh + ((size_t)bz << 22);
    __nv_bfloat16* Ybl = Yl + ((size_t)bz << 22);
    const int rb = n0 + warp_m*64 + (lane >> 2);
    const int cb = o0 + warp_n*32 + (lane & 3)*2;
#pragma unroll
    for (int mi = 0; mi < 4; mi++)
#pragma unroll
        for (int ni = 0; ni < 4; ni++)
#pragma unroll
            for (int h = 0; h < 2; h++) {
                float v0 = acc[mi][ni][2*h + 0];
                float v1 = acc[mi][ni][2*h + 1];
                __nv_bfloat16 h0 = __float2bfloat16(v0);
                __nv_bfloat16 h1 = __float2bfloat16(v1);
                __nv_bfloat16 l0 = __float2bfloat16(v0 - __bfloat162float(h0));
                __nv_bfloat16 l1 = __float2bfloat16(v1 - __bfloat162float(h1));
                size_t off = (size_t)(rb + mi*16 + 8*h) * DD + cb + ni*8;
                *(__nv_bfloat162*)&Ybh[off] = __nv_bfloat162(h0, h1);
                *(__nv_bfloat162*)&Ybl[off] = __nv_bfloat162(l0, l1);
            }
}

// ---------------------------------------------------------------------------
extern "C" void kernel_launch(void* const* d_in, const int* in_sizes, int n_in,
                              void* d_out, int out_size)
{
    const float* x  = (const float*)d_in[0];
    const float* Wk = (const float*)d_in[1];
    const float* Wq = (const float*)d_in[2];
    const float* Wv = (const float*)d_in[3];
    const float* Wo = (const float*)d_in[4];

    float* y_out   = (float*)d_out;
    float* att_out = y_out + (size_t)BB * NN * DD;

    __nv_bfloat16 *xh, *xl, *Wkh, *Wkl, *Wqh, *Wql, *Wvh, *Wvl, *Woh, *Wol;
    __nv_bfloat16 *Qh, *Ql, *Kh, *Kl, *Vh, *Vl, *Yh, *Yl, *Ph, *Pl;
    cudaGetSymbolAddress((void**)&xh,  g_xh);  cudaGetSymbolAddress((void**)&xl,  g_xl);
    cudaGetSymbolAddress((void**)&Wkh, g_Wkh); cudaGetSymbolAddress((void**)&Wkl, g_Wkl);
    cudaGetSymbolAddress((void**)&Wqh, g_Wqh); cudaGetSymbolAddress((void**)&Wql, g_Wql);
    cudaGetSymbolAddress((void**)&Wvh, g_Wvh); cudaGetSymbolAddress((void**)&Wvl, g_Wvl);
    cudaGetSymbolAddress((void**)&Woh, g_Woh); cudaGetSymbolAddress((void**)&Wol, g_Wol);
    cudaGetSymbolAddress((void**)&Qh,  g_Qh);  cudaGetSymbolAddress((void**)&Ql,  g_Ql);
    cudaGetSymbolAddress((void**)&Kh,  g_Kh);  cudaGetSymbolAddress((void**)&Kl,  g_Kl);
    cudaGetSymbolAddress((void**)&Vh,  g_Vh);  cudaGetSymbolAddress((void**)&Vl,  g_Vl);
    cudaGetSymbolAddress((void**)&Yh,  g_Yh);  cudaGetSymbolAddress((void**)&Yl,  g_Yl);
    cudaGetSymbolAddress((void**)&Ph,  g_Ph);  cudaGetSymbolAddress((void**)&Pl,  g_Pl);

    cudaFuncSetAttribute(gemm_tc, cudaFuncAttributeMaxDynamicSharedMemorySize, SMEM_SZ);
    cudaFuncSetAttribute(band_tc, cudaFuncAttributeMaxDynamicSharedMemorySize, SMEM_SZ);
    cudaFuncSetAttribute(ptv_tc,  cudaFuncAttributeMaxDynamicSharedMemorySize, SMEM_SZ);

    const int NE = BB * NN * DD;
    const int WE = DD * DD;

    // 1. zero attention output (out-of-band must be 0; softmax pass2 reads zeros)
    zero_f4<<<8192, 256>>>((float4*)att_out, (BB * NN * NN) / 4);

    // 2. split inputs to bf16 hi/lo
    split_f32<<<8192, 256>>>(x,  xh,  xl,  NE);
    split_f32<<<1024, 256>>>(Wk, Wkh, Wkl, WE);
    split_f32<<<1024, 256>>>(Wq, Wqh, Wql, WE);
    split_f32<<<1024, 256>>>(Wv, Wvh, Wvl, WE);
    split_f32<<<1024, 256>>>(Wo, Woh, Wol, WE);

    // 3. projections
    dim3 gP(DD / 128, (BB * NN) / 128);
    gemm_tc<<<gP, 256, SMEM_SZ>>>(xh, xl, Wkh, Wkl, nullptr, Kh, Kl, DD, DD, 1.0f, 1);
    gemm_tc<<<gP, 256, SMEM_SZ>>>(xh, xl, Wqh, Wql, nullptr, Qh, Ql, DD, DD, QS,   1);
    gemm_tc<<<gP, 256, SMEM_SZ>>>(xh, xl, Wvh, Wvl, nullptr, Vh, Vl, DD, DD, 1.0f, 1);

    // 4. banded logits
    band_tc<<<dim3(5, NN / 128, BB), 256, SMEM_SZ>>>(Qh, Ql, Kh, Kl, att_out);

    // 5. band softmax + split-bf16 P emit
    band_softmax<<<BB * NN, 128>>>(att_out, Ph, Pl);

    // 6. Y = P^T @ V (banded, HMMA)
    ptv_tc<<<dim3(DD / 128, NN / 128, BB), 256, SMEM_SZ>>>(Ph, Pl, Vh, Vl, Yh, Yl);

    // 7. output projection
    gemm_tc<<<gP, 256, SMEM_SZ>>>(Yh, Yl, Woh, Wol, y_out, nullptr, nullptr, DD, DD, 1.0f, 0);
}

// round 6
// speedup vs baseline: 4.3311x; 1.4282x over previous
#include <cuda_runtime.h>
#include <cuda_fp16.h>
#include <cstdint>

#define BB   4
#define NN   4096
#define DD   1024
#define AP   256
#define QS   0.06f

#define NSTAGE 3
#define ST3    32768      // stage bytes, 3-term: Ah|Al|Bh|Bl (8KB each)
#define ST2    24576      // stage bytes, 2-term: Ah|Al|Bh
#define SM3    (NSTAGE*ST3)
#define SM2    (NSTAGE*ST2)

// ---------------------------------------------------------------------------
// device scratch (allocation-free rule)
// ---------------------------------------------------------------------------
__device__ __align__(16) __half g_xh[BB*NN*DD], g_xl[BB*NN*DD];
__device__ __align__(16) __half g_WkTh[DD*DD], g_WkTl[DD*DD];
__device__ __align__(16) __half g_WqTh[DD*DD], g_WqTl[DD*DD];
__device__ __align__(16) __half g_Wvh[DD*DD];
__device__ __align__(16) __half g_Woh[DD*DD];
__device__ __align__(16) __half g_Gh[DD*DD], g_Gl[DD*DD];
__device__ __align__(16) __half g_Zh[BB*NN*DD], g_Zl[BB*NN*DD];
__device__ __align__(16) __half g_Vh[BB*NN*DD];
__device__ __align__(16) __half g_Yh[BB*NN*DD], g_Yl[BB*NN*DD];
__device__ __align__(16) __half g_Ph[(size_t)BB*NN*NN], g_Pl[(size_t)BB*NN*NN];

// ---------------------------------------------------------------------------
// PTX helpers — baseline (non-arch-specific) instructions only
// ---------------------------------------------------------------------------
__device__ __forceinline__ uint32_t smem_u32(const void* p) {
    uint32_t a;
    asm("{ .reg .u64 t; cvta.to.shared.u64 t, %1; cvt.u32.u64 %0, t; }" : "=r"(a) : "l"(p));
    return a;
}
__device__ __forceinline__ void cp16(uint32_t s, const void* g) {
    asm volatile("cp.async.cg.shared.global [%0], [%1], 16;" :: "r"(s), "l"(g));
}
__device__ __forceinline__ void ldsm4(uint32_t* r, uint32_t a) {
    asm volatile("ldmatrix.sync.aligned.m8n8.x4.shared.b16 {%0,%1,%2,%3}, [%4];"
        : "=r"(r[0]), "=r"(r[1]), "=r"(r[2]), "=r"(r[3]) : "r"(a));
}
__device__ __forceinline__ void ldsm4t(uint32_t* r, uint32_t a) {
    asm volatile("ldmatrix.sync.aligned.m8n8.x4.trans.shared.b16 {%0,%1,%2,%3}, [%4];"
        : "=r"(r[0]), "=r"(r[1]), "=r"(r[2]), "=r"(r[3]) : "r"(a));
}
__device__ __forceinline__ void mmah(float* d, const uint32_t* a, const uint32_t* b) {
    asm volatile("mma.sync.aligned.m16n8k16.row.col.f32.f16.f16.f32 "
        "{%0,%1,%2,%3}, {%4,%5,%6,%7}, {%8,%9}, {%0,%1,%2,%3};"
        : "+f"(d[0]), "+f"(d[1]), "+f"(d[2]), "+f"(d[3])
        : "r"(a[0]), "r"(a[1]), "r"(a[2]), "r"(a[3]), "r"(b[0]), "r"(b[1]));
}
#define SW64(off)  ((off) ^ (((off) >> 3) & 0x30))
#define SW256(off) ((off) ^ (((off) >> 4) & 0x70))

// ===========================================================================
// dense NT GEMM pipeline (fp16 split; 64B smem rows, K-chunks of 32)
// ===========================================================================
template<int TERMS>
__device__ __forceinline__ void issue_chunk(
    uint32_t sbase, int tid,
    const __half* pAh, const __half* pAl, const __half* pBh, const __half* pBl,
    int Kd, int k0)
{
#pragma unroll
    for (int j = 0; j < 2; j++) {
        int e = tid + (j << 8);
        int r = e >> 2, c = e & 3;
        uint32_t sw = SW64((uint32_t)(r << 6) + (c << 4));
        size_t g = (size_t)r * Kd + k0 + (c << 3);
        cp16(sbase +          sw, pAh + g);
        cp16(sbase +  8192u + sw, pAl + g);
        cp16(sbase + 16384u + sw, pBh + g);
        if (TERMS == 3) cp16(sbase + 24576u + sw, pBl + g);
    }
    asm volatile("cp.async.commit_group;" ::: "memory");
}

template<int TERMS>
__device__ __forceinline__ void compute_chunk(
    float acc[4][4][4], uint32_t sb, int lane, int warp_m, int warp_n)
{
#pragma unroll
    for (int ks = 0; ks < 2; ks++) {
        uint32_t ah[4][4], al[4][4], bh[4][2], bl[4][2];
#pragma unroll
        for (int mi = 0; mi < 4; mi++) {
            int row = warp_m*64 + mi*16 + ((lane >> 3) & 1)*8 + (lane & 7);
            int kb  = ks*32 + (lane >> 4)*16;
            uint32_t a = sb + SW64((uint32_t)(row << 6) + kb);
            ldsm4(ah[mi], a);
            ldsm4(al[mi], a + 8192u);
        }
#pragma unroll
        for (int nj = 0; nj < 2; nj++) {
            int nr = warp_n*32 + nj*16 + (lane >> 4)*8 + (lane & 7);
            int kb = ks*32 + ((lane >> 3) & 1)*16;
            uint32_t a = sb + 16384u + SW64((uint32_t)(nr << 6) + kb);
            uint32_t t[4];
            ldsm4(t, a);
            bh[nj*2][0] = t[0]; bh[nj*2][1] = t[1];
            bh[nj*2+1][0] = t[2]; bh[nj*2+1][1] = t[3];
            if (TERMS == 3) {
                ldsm4(t, a + 8192u);
                bl[nj*2][0] = t[0]; bl[nj*2][1] = t[1];
                bl[nj*2+1][0] = t[2]; bl[nj*2+1][1] = t[3];
            }
        }
#pragma unroll
        for (int mi = 0; mi < 4; mi++)
#pragma unroll
            for (int ni = 0; ni < 4; ni++) {
                mmah(acc[mi][ni], ah[mi], bh[ni]);
                mmah(acc[mi][ni], al[mi], bh[ni]);
                if (TERMS == 3) mmah(acc[mi][ni], ah[mi], bl[ni]);
            }
    }
}

template<int TERMS>
__device__ __forceinline__ void hmma_loop(
    float acc[4][4][4], char* smem, int tid,
    const __half* pAh, const __half* pAl,
    const __half* pBh, const __half* pBl, int Kd)
{
    const int lane = tid & 31, wid = tid >> 5;
    const int warp_m = wid >> 2, warp_n = wid & 3;
    const uint32_t STG = (TERMS == 3) ? ST3 : ST2;
    uint32_t sb0 = smem_u32(smem);
    const int KC = Kd >> 5;

    issue_chunk<TERMS>(sb0,       tid, pAh, pAl, pBh, pBl, Kd, 0);
    issue_chunk<TERMS>(sb0 + STG, tid, pAh, pAl, pBh, pBl, Kd, 32);

    for (int i = 0; i < KC; i++) {
        if (i + 2 < KC) {
            issue_chunk<TERMS>(sb0 + ((i + 2) % NSTAGE)*STG, tid,
                               pAh, pAl, pBh, pBl, Kd, (i + 2) << 5);
            asm volatile("cp.async.wait_group 2;" ::: "memory");
        } else {
            asm volatile("cp.async.wait_group 0;" ::: "memory");
        }
        __syncthreads();
        compute_chunk<TERMS>(acc, sb0 + (i % NSTAGE)*STG, lane, warp_m, warp_n);
        __syncthreads();
    }
}

// ---------------------------------------------------------------------------
// NT GEMM: C = scale*(A@B^T). MODE 0: fp32 out; 1: split h/l; 2: single h
// ---------------------------------------------------------------------------
template<int TERMS, int MODE>
__global__ void __launch_bounds__(256, 1) gemm_tc(
    const __half* __restrict__ Ah, const __half* __restrict__ Al,
    const __half* __restrict__ Bh, const __half* __restrict__ Bl,
    float* __restrict__ Cf, __half* __restrict__ Ch, __half* __restrict__ Cl,
    int Kd, int Cstride, float scale)
{
    extern __shared__ char smem[];
    const int tid = threadIdx.x, lane = tid & 31, wid = tid >> 5;
    const int warp_m = wid >> 2, warp_n = wid & 3;
    const int row0 = blockIdx.y << 7, col0 = blockIdx.x << 7;

    float acc[4][4][4] = {};
    hmma_loop<TERMS>(acc, smem, tid,
                     Ah + (size_t)row0 * Kd, Al + (size_t)row0 * Kd,
                     Bh + (size_t)col0 * Kd, (TERMS == 3) ? Bl + (size_t)col0 * Kd : Bh, Kd);

    const int rb = row0 + warp_m*64 + (lane >> 2);
    const int cb = col0 + warp_n*32 + (lane & 3)*2;
#pragma unroll
    for (int mi = 0; mi < 4; mi++)
#pragma unroll
        for (int ni = 0; ni < 4; ni++)
#pragma unroll
            for (int h = 0; h < 2; h++) {
                int r = rb + mi*16 + 8*h;
                int c = cb + ni*8;
                float v0 = acc[mi][ni][2*h + 0] * scale;
                float v1 = acc[mi][ni][2*h + 1] * scale;
                if (MODE == 0) {
                    *(float2*)&Cf[(size_t)r * Cstride + c] = make_float2(v0, v1);
                } else if (MODE == 1) {
                    __half h0 = __float2half(v0), h1 = __float2half(v1);
                    __half l0 = __float2half(v0 - __half2float(h0));
                    __half l1 = __float2half(v1 - __half2float(h1));
                    size_t o = (size_t)r * Cstride + c;
                    *(__half2*)&Ch[o] = __halves2half2(h0, h1);
                    *(__half2*)&Cl[o] = __halves2half2(l0, l1);
                } else {
                    size_t o = (size_t)r * Cstride + c;
                    *(__half2*)&Ch[o] = __halves2half2(__float2half(v0), __float2half(v1));
                }
            }
}

// ---------------------------------------------------------------------------
// banded logits: att[b,n,m] = QS * Z[b,n]·x[b,m], |n-m| < AP  (3-term)
// ---------------------------------------------------------------------------
__global__ void __launch_bounds__(256, 1) band_tc(
    const __half* __restrict__ Zh, const __half* __restrict__ Zl,
    const __half* __restrict__ xh, const __half* __restrict__ xl,
    float* __restrict__ att)
{
    const int it = blockIdx.y;
    const int jt = it + (int)blockIdx.x - 2;
    if (jt < 0 || jt >= (NN >> 7)) return;
    const int bz = blockIdx.z;

    extern __shared__ char smem[];
    const int tid = threadIdx.x, lane = tid & 31, wid = tid >> 5;
    const int warp_m = wid >> 2, warp_n = wid & 3;
    const int row0 = it << 7, col0 = jt << 7;
    const size_t boff = (size_t)bz << 22;

    float acc[4][4][4] = {};
    hmma_loop<3>(acc, smem, tid,
                 Zh + boff + (size_t)row0 * DD, Zl + boff + (size_t)row0 * DD,
                 xh + boff + (size_t)col0 * DD, xl + boff + (size_t)col0 * DD, DD);

    float* attb = att + ((size_t)bz << 24);
    const int rb = row0 + warp_m*64 + (lane >> 2);
    const int cb = col0 + warp_n*32 + (lane & 3)*2;
#pragma unroll
    for (int mi = 0; mi < 4; mi++)
#pragma unroll
        for (int ni = 0; ni < 4; ni++)
#pragma unroll
            for (int h = 0; h < 2; h++) {
                int gi = rb + mi*16 + 8*h;
#pragma unroll
                for (int q = 0; q < 2; q++) {
                    int gj = cb + ni*8 + q;
                    int d = gi - gj;
                    if (d > -AP && d < AP)
                        attb[(size_t)gi * NN + gj] = acc[mi][ni][2*h + q] * QS;
                }
            }
}

// ---------------------------------------------------------------------------
// splits & transpose
// ---------------------------------------------------------------------------
__global__ void split2(const float* __restrict__ in,
                       __half* __restrict__ h, __half* __restrict__ l, int n2)
{
    int i = blockIdx.x * blockDim.x + threadIdx.x;
    int st = gridDim.x * blockDim.x;
    for (; i < n2; i += st) {
        float2 v = ((const float2*)in)[i];
        __half hx = __float2half(v.x), hy = __float2half(v.y);
        ((__half2*)h)[i] = __halves2half2(hx, hy);
        ((__half2*)l)[i] = __halves2half2(__float2half(v.x - __half2float(hx)),
                                          __float2half(v.y - __half2float(hy)));
    }
}
__global__ void round1(const float* __restrict__ in, __half* __restrict__ h, int n2)
{
    int i = blockIdx.x * blockDim.x + threadIdx.x;
    int st = gridDim.x * blockDim.x;
    for (; i < n2; i += st) {
        float2 v = ((const float2*)in)[i];
        ((__half2*)h)[i] = __halves2half2(__float2half(v.x), __float2half(v.y));
    }
}
// out[r][c] = in[c][r], split h/l  (1024x1024)
__global__ void transpose_split(const float* __restrict__ in,
                                __half* __restrict__ th, __half* __restrict__ tl)
{
    __shared__ float t[32][33];
    int bx = blockIdx.x << 5, by = blockIdx.y << 5;
#pragma unroll
    for (int k = 0; k < 32; k += 8)
        t[threadIdx.y + k][threadIdx.x] = in[(size_t)(by + threadIdx.y + k) * DD + bx + threadIdx.x];
    __syncthreads();
#pragma unroll
    for (int k = 0; k < 32; k += 8) {
        int r = bx + threadIdx.y + k, c = by + threadIdx.x;
        float v = t[threadIdx.x][threadIdx.y + k];
        __half h = __float2half(v);
        th[(size_t)r * DD + c] = h;
        tl[(size_t)r * DD + c] = __float2half(v - __half2float(h));
    }
}

// ---------------------------------------------------------------------------
// fused: zero row + band softmax + split-fp16 P emit over padded window
// ---------------------------------------------------------------------------
__global__ void __launch_bounds__(128) band_softmax(
    float* __restrict__ att, __half* __restrict__ Ph, __half* __restrict__ Pl)
{
    __shared__ float red[4];
    const int gid = blockIdx.x;
    const int b = gid >> 12;
    const int i = gid & (NN - 1);
    const size_t rowbase = ((size_t)b << 24) + ((size_t)i << 12);
    float* row = att + rowbase;
    int jlo = i - (AP - 1); if (jlo < 0) jlo = 0;
    int jhi = i + (AP - 1); if (jhi > NN - 1) jhi = NN - 1;
    const int cnt = jhi - jlo + 1;

    float v[4];
    int nc = 0;
    float m = -1e30f;
    for (int t = threadIdx.x; t < cnt; t += 128) { v[nc] = row[jlo + t]; m = fmaxf(m, v[nc]); nc++; }
    for (int o = 16; o > 0; o >>= 1) m = fmaxf(m, __shfl_xor_sync(0xffffffffu, m, o));
    const int w = threadIdx.x >> 5;
    if ((threadIdx.x & 31) == 0) red[w] = m;
    __syncthreads();
    m = fmaxf(fmaxf(red[0], red[1]), fmaxf(red[2], red[3]));
    __syncthreads();

    float s = 0.f;
    for (int c = 0; c < nc; c++) { v[c] = __expf(v[c] - m); s += v[c]; }
    for (int o = 16; o > 0; o >>= 1) s += __shfl_xor_sync(0xffffffffu, s, o);
    if ((threadIdx.x & 31) == 0) red[w] = s;
    __syncthreads();
    s = red[0] + red[1] + red[2] + red[3];
    const float inv = 1.0f / s;

    // zero whole row (out-of-band must be exactly 0) — logits already in regs
    float4 z4 = make_float4(0.f, 0.f, 0.f, 0.f);
    for (int t = threadIdx.x; t < (NN >> 2); t += 128) ((float4*)row)[t] = z4;
    __syncthreads();
    nc = 0;
    for (int t = threadIdx.x; t < cnt; t += 128) { row[jlo + t] = v[nc] * inv; nc++; }
    __syncthreads();

    // split-fp16 P over 128-aligned window (reads zeros out-of-band)
    int wlo = i - 256; wlo &= ~127; if (wlo < 0) wlo = 0;
    int whi = (i + 384) & ~127; if (whi > NN) whi = NN;
    for (int n = wlo + threadIdx.x; n < whi; n += 128) {
        float f = row[n];
        __half h = __float2half(f);
        Ph[rowbase + n] = h;
        Pl[rowbase + n] = __float2half(f - __half2float(h));
    }
}

// ===========================================================================
// ptv: Y[b,n,o] = sum_m P[b,m,n] * V[b,m,o]  (banded, 2-term, trans-ldsm)
// stage: Ph[32][128] | Pl | Vh  (8KB each)
// ===========================================================================
__device__ __forceinline__ void ptv_issue(
    uint32_t sbase, int tid,
    const __half* Phg, const __half* Plg, const __half* Vhg,
    int m0, int n0, int o0)
{
#pragma unroll
    for (int j = 0; j < 2; j++) {
        int e = tid + (j << 8);
        int r = e >> 4, c16 = e & 15;
        uint32_t sw = SW256((uint32_t)(r << 8) + (c16 << 4));
        size_t gp = (size_t)(m0 + r) * NN + n0 + (c16 << 3);
        size_t gv = (size_t)(m0 + r) * DD + o0 + (c16 << 3);
        cp16(sbase +          sw, Phg + gp);
        cp16(sbase +  8192u + sw, Plg + gp);
        cp16(sbase + 16384u + sw, Vhg + gv);
    }
    asm volatile("cp.async.commit_group;" ::: "memory");
}

__device__ __forceinline__ void ptv_compute(
    float acc[4][4][4], uint32_t sb, int lane, int warp_m, int warp_n)
{
#pragma unroll
    for (int ks = 0; ks < 2; ks++) {
        const int m16 = ks << 4;
        uint32_t ah[4][4], al[4][4], bh[4][2];
        const int ar = m16 + ((lane >> 4) << 3) + (lane & 7);
        const int acsel = ((lane >> 3) & 1) << 3;
#pragma unroll
        for (int mi = 0; mi < 4; mi++) {
            int nb = warp_m*64 + mi*16 + acsel;
            uint32_t a = sb + SW256((uint32_t)(ar << 8) + (nb << 1));
            ldsm4t(ah[mi], a);
            ldsm4t(al[mi], a + 8192u);
        }
        const int br = m16 + (((lane >> 3) & 1) << 3) + (lane & 7);
        const int bcsel = (lane >> 4) << 3;
#pragma unroll
        for (int jb = 0; jb < 2; jb++) {
            int ob = warp_n*32 + jb*16 + bcsel;
            uint32_t a = sb + 16384u + SW256((uint32_t)(br << 8) + (ob << 1));
            uint32_t t4[4];
            ldsm4t(t4, a);
            bh[jb*2][0] = t4[0]; bh[jb*2][1] = t4[1];
            bh[jb*2+1][0] = t4[2]; bh[jb*2+1][1] = t4[3];
        }
#pragma unroll
        for (int mi = 0; mi < 4; mi++)
#pragma unroll
            for (int ni = 0; ni < 4; ni++) {
                mmah(acc[mi][ni], ah[mi], bh[ni]);
                mmah(acc[mi][ni], al[mi], bh[ni]);
            }
    }
}

__global__ void __launch_bounds__(256, 1) ptv_tc(
    const __half* __restrict__ Phg, const __half* __restrict__ Plg,
    const __half* __restrict__ Vhg,
    __half* __restrict__ Yh, __half* __restrict__ Yl)
{
    const int bz = blockIdx.z;
    const int n0 = blockIdx.y << 7;
    const int o0 = blockIdx.x << 7;
    const __half* Pb_h = Phg + ((size_t)bz << 24);
    const __half* Pb_l = Plg + ((size_t)bz << 24);
    const __half* Vb_h = Vhg + ((size_t)bz << 22);

    extern __shared__ char smem[];
    uint32_t sb0 = smem_u32(smem);
    const int tid = threadIdx.x, lane = tid & 31, wid = tid >> 5;
    const int warp_m = wid >> 2, warp_n = wid & 3;

    int mlo = n0 - 256; if (mlo < 0) mlo = 0;
    int mhe = n0 + 384; if (mhe > NN) mhe = NN;
    const int NC = (mhe - mlo) >> 5;

    float acc[4][4][4] = {};

    ptv_issue(sb0,       tid, Pb_h, Pb_l, Vb_h, mlo,      n0, o0);
    ptv_issue(sb0 + ST2, tid, Pb_h, Pb_l, Vb_h, mlo + 32, n0, o0);

    for (int i = 0; i < NC; i++) {
        if (i + 2 < NC) {
            ptv_issue(sb0 + ((i + 2) % NSTAGE)*ST2, tid,
                      Pb_h, Pb_l, Vb_h, mlo + ((i + 2) << 5), n0, o0);
            asm volatile("cp.async.wait_group 2;" ::: "memory");
        } else {
            asm volatile("cp.async.wait_group 0;" ::: "memory");
        }
        __syncthreads();
        ptv_compute(acc, sb0 + (i % NSTAGE)*ST2, lane, warp_m, warp_n);
        __syncthreads();
    }

    __half* Ybh = Yh + ((size_t)bz << 22);
    __half* Ybl = Yl + ((size_t)bz << 22);
    const int rb = n0 + warp_m*64 + (lane >> 2);
    const int cb = o0 + warp_n*32 + (lane & 3)*2;
#pragma unroll
    for (int mi = 0; mi < 4; mi++)
#pragma unroll
        for (int ni = 0; ni < 4; ni++)
#pragma unroll
            for (int h = 0; h < 2; h++) {
                float v0 = acc[mi][ni][2*h + 0];
                float v1 = acc[mi][ni][2*h + 1];
                __half h0 = __float2half(v0), h1 = __float2half(v1);
                __half l0 = __float2half(v0 - __half2float(h0));
                __half l1 = __float2half(v1 - __half2float(h1));
                size_t off = (size_t)(rb + mi*16 + 8*h) * DD + cb + ni*8;
                *(__half2*)&Ybh[off] = __halves2half2(h0, h1);
                *(__half2*)&Ybl[off] = __halves2half2(l0, l1);
            }
}

// ---------------------------------------------------------------------------
extern "C" void kernel_launch(void* const* d_in, const int* in_sizes, int n_in,
                              void* d_out, int out_size)
{
    const float* x  = (const float*)d_in[0];
    const float* Wk = (const float*)d_in[1];
    const float* Wq = (const float*)d_in[2];
    const float* Wv = (const float*)d_in[3];
    const float* Wo = (const float*)d_in[4];

    float* y_out   = (float*)d_out;
    float* att_out = y_out + (size_t)BB * NN * DD;

    __half *xh, *xl, *WkTh, *WkTl, *WqTh, *WqTl, *Wvh, *Woh;
    __half *Gh, *Gl, *Zh, *Zl, *Vh, *Yh, *Yl, *Ph, *Pl;
    cudaGetSymbolAddress((void**)&xh,   g_xh);   cudaGetSymbolAddress((void**)&xl,   g_xl);
    cudaGetSymbolAddress((void**)&WkTh, g_WkTh); cudaGetSymbolAddress((void**)&WkTl, g_WkTl);
    cudaGetSymbolAddress((void**)&WqTh, g_WqTh); cudaGetSymbolAddress((void**)&WqTl, g_WqTl);
    cudaGetSymbolAddress((void**)&Wvh,  g_Wvh);  cudaGetSymbolAddress((void**)&Woh,  g_Woh);
    cudaGetSymbolAddress((void**)&Gh,   g_Gh);   cudaGetSymbolAddress((void**)&Gl,   g_Gl);
    cudaGetSymbolAddress((void**)&Zh,   g_Zh);   cudaGetSymbolAddress((void**)&Zl,   g_Zl);
    cudaGetSymbolAddress((void**)&Vh,   g_Vh);
    cudaGetSymbolAddress((void**)&Yh,   g_Yh);   cudaGetSymbolAddress((void**)&Yl,   g_Yl);
    cudaGetSymbolAddress((void**)&Ph,   g_Ph);   cudaGetSymbolAddress((void**)&Pl,   g_Pl);

    cudaFuncSetAttribute((const void*)gemm_tc<3,1>, cudaFuncAttributeMaxDynamicSharedMemorySize, SM3);
    cudaFuncSetAttribute((const void*)gemm_tc<2,2>, cudaFuncAttributeMaxDynamicSharedMemorySize, SM2);
    cudaFuncSetAttribute((const void*)gemm_tc<2,0>, cudaFuncAttributeMaxDynamicSharedMemorySize, SM2);
    cudaFuncSetAttribute((const void*)band_tc,      cudaFuncAttributeMaxDynamicSharedMemorySize, SM3);
    cudaFuncSetAttribute((const void*)ptv_tc,       cudaFuncAttributeMaxDynamicSharedMemorySize, SM2);

    // 1. operand prep
    split2<<<4096, 256>>>(x, xh, xl, (BB * NN * DD) / 2);
    transpose_split<<<dim3(32, 32), dim3(32, 8)>>>(Wk, WkTh, WkTl);
    transpose_split<<<dim3(32, 32), dim3(32, 8)>>>(Wq, WqTh, WqTl);
    round1<<<512, 256>>>(Wv, Wvh, (DD * DD) / 2);
    round1<<<512, 256>>>(Wo, Woh, (DD * DD) / 2);

    // 2. G[d2,d1] = sum_o WkT[d2,o]*WqT[d1,o]   (3-term)
    gemm_tc<3,1><<<dim3(8, 8), 256, SM3>>>(WkTh, WkTl, WqTh, WqTl,
                                           nullptr, Gh, Gl, DD, DD, 1.0f);

    // 3. Z[n,d2] = sum_d1 x[n,d1]*G[d2,d1]      (3-term)
    dim3 gP(DD / 128, (BB * NN) / 128);
    gemm_tc<3,1><<<gP, 256, SM3>>>(xh, xl, Gh, Gl, nullptr, Zh, Zl, DD, DD, 1.0f);

    // 4. V[n,o] = sum_d x[n,d]*Wv[o,d]          (2-term, single-h out)
    gemm_tc<2,2><<<gP, 256, SM2>>>(xh, xl, Wvh, nullptr, nullptr, Vh, nullptr, DD, DD, 1.0f);

    // 5. banded logits = QS * Z·x^T             (3-term)
    band_tc<<<dim3(5, NN / 128, BB), 256, SM3>>>(Zh, Zl, xh, xl, att_out);

    // 6. fused zero + softmax + P split emit
    band_softmax<<<BB * NN, 128>>>(att_out, Ph, Pl);

    // 7. Y = P^T @ V (banded, 2-term)
    ptv_tc<<<dim3(DD / 128, NN / 128, BB), 256, SM2>>>(Ph, Pl, Vh, Yh, Yl);

    // 8. y = Y @ Wo^T                           (2-term, fp32 out)
    gemm_tc<2,0><<<gP, 256, SM2>>>(Yh, Yl, Woh, nullptr, y_out, nullptr, nullptr, DD, DD, 1.0f);
}

// round 7
// speedup vs baseline: 5.4934x; 1.2684x over previous
#include <cuda_runtime.h>
#include <cuda_fp16.h>
#include <cstdint>

#define BB   4
#define NN   4096
#define DD   1024
#define AP   256
#define QS   0.06f

#define NSTAGE 3
#define ST_OF(T) ((T)==3 ? 32768u : (T)==2 ? 24576u : 16384u)
#define SM3    (NSTAGE*32768)
#define SM2    (NSTAGE*24576)
#define SM1    (NSTAGE*16384)

// ---------------------------------------------------------------------------
// device scratch (allocation-free rule)
// ---------------------------------------------------------------------------
__device__ __align__(16) __half g_xh[BB*NN*DD], g_xl[BB*NN*DD];
__device__ __align__(16) __half g_WkTh[DD*DD], g_WkTl[DD*DD];
__device__ __align__(16) __half g_WqTh[DD*DD], g_WqTl[DD*DD];
__device__ __align__(16) __half g_Wvh[DD*DD];
__device__ __align__(16) __half g_Woh[DD*DD];
__device__ __align__(16) __half g_Gh[DD*DD];
__device__ __align__(16) __half g_Zh[BB*NN*DD], g_Zl[BB*NN*DD];
__device__ __align__(16) __half g_Vh[BB*NN*DD];
__device__ __align__(16) __half g_Yh[BB*NN*DD];
__device__ __align__(16) __half g_Ph[(size_t)BB*NN*NN];

// ---------------------------------------------------------------------------
// PTX helpers — baseline (non-arch-specific) instructions only
// ---------------------------------------------------------------------------
__device__ __forceinline__ uint32_t smem_u32(const void* p) {
    uint32_t a;
    asm("{ .reg .u64 t; cvta.to.shared.u64 t, %1; cvt.u32.u64 %0, t; }" : "=r"(a) : "l"(p));
    return a;
}
__device__ __forceinline__ void cp16(uint32_t s, const void* g) {
    asm volatile("cp.async.cg.shared.global [%0], [%1], 16;" :: "r"(s), "l"(g));
}
__device__ __forceinline__ void ldsm4(uint32_t* r, uint32_t a) {
    asm volatile("ldmatrix.sync.aligned.m8n8.x4.shared.b16 {%0,%1,%2,%3}, [%4];"
        : "=r"(r[0]), "=r"(r[1]), "=r"(r[2]), "=r"(r[3]) : "r"(a));
}
__device__ __forceinline__ void ldsm4t(uint32_t* r, uint32_t a) {
    asm volatile("ldmatrix.sync.aligned.m8n8.x4.trans.shared.b16 {%0,%1,%2,%3}, [%4];"
        : "=r"(r[0]), "=r"(r[1]), "=r"(r[2]), "=r"(r[3]) : "r"(a));
}
__device__ __forceinline__ void mmah(float* d, const uint32_t* a, const uint32_t* b) {
    asm volatile("mma.sync.aligned.m16n8k16.row.col.f32.f16.f16.f32 "
        "{%0,%1,%2,%3}, {%4,%5,%6,%7}, {%8,%9}, {%0,%1,%2,%3};"
        : "+f"(d[0]), "+f"(d[1]), "+f"(d[2]), "+f"(d[3])
        : "r"(a[0]), "r"(a[1]), "r"(a[2]), "r"(a[3]), "r"(b[0]), "r"(b[1]));
}
#define SW64(off)  ((off) ^ (((off) >> 3) & 0x30))
#define SW256(off) ((off) ^ (((off) >> 4) & 0x70))

// ===========================================================================
// dense NT GEMM pipeline (fp16 split; 64B smem rows, K-chunks of 32)
// TERMS==3: Ah·Bh + Al·Bh + Ah·Bl  | TERMS==2: Ah·Bh + Al·Bh | TERMS==1: Ah·Bh
// stage layout: Ah | (Al) | Bh | (Bl), 8KB each
// ===========================================================================
template<int TERMS>
__device__ __forceinline__ void issue_chunk(
    uint32_t sbase, int tid,
    const __half* pAh, const __half* pAl, const __half* pBh, const __half* pBl,
    int Kd, int k0)
{
    const uint32_t BOFF = (TERMS >= 2) ? 16384u : 8192u;
#pragma unroll
    for (int j = 0; j < 2; j++) {
        int e = tid + (j << 8);
        int r = e >> 2, c = e & 3;
        uint32_t sw = SW64((uint32_t)(r << 6) + (c << 4));
        size_t g = (size_t)r * Kd + k0 + (c << 3);
        cp16(sbase + sw, pAh + g);
        if (TERMS >= 2) cp16(sbase + 8192u + sw, pAl + g);
        cp16(sbase + BOFF + sw, pBh + g);
        if (TERMS == 3) cp16(sbase + 24576u + sw, pBl + g);
    }
    asm volatile("cp.async.commit_group;" ::: "memory");
}

template<int TERMS>
__device__ __forceinline__ void compute_chunk(
    float acc[4][4][4], uint32_t sb, int lane, int warp_m, int warp_n)
{
    const uint32_t BOFF = (TERMS >= 2) ? 16384u : 8192u;
#pragma unroll
    for (int ks = 0; ks < 2; ks++) {
        uint32_t ah[4][4], al[4][4], bh[4][2], bl[4][2];
#pragma unroll
        for (int mi = 0; mi < 4; mi++) {
            int row = warp_m*64 + mi*16 + ((lane >> 3) & 1)*8 + (lane & 7);
            int kb  = ks*32 + (lane >> 4)*16;
            uint32_t a = sb + SW64((uint32_t)(row << 6) + kb);
            ldsm4(ah[mi], a);
            if (TERMS >= 2) ldsm4(al[mi], a + 8192u);
        }
#pragma unroll
        for (int nj = 0; nj < 2; nj++) {
            int nr = warp_n*32 + nj*16 + (lane >> 4)*8 + (lane & 7);
            int kb = ks*32 + ((lane >> 3) & 1)*16;
            uint32_t a = sb + BOFF + SW64((uint32_t)(nr << 6) + kb);
            uint32_t t[4];
            ldsm4(t, a);
            bh[nj*2][0] = t[0]; bh[nj*2][1] = t[1];
            bh[nj*2+1][0] = t[2]; bh[nj*2+1][1] = t[3];
            if (TERMS == 3) {
                ldsm4(t, a + 8192u);
                bl[nj*2][0] = t[0]; bl[nj*2][1] = t[1];
                bl[nj*2+1][0] = t[2]; bl[nj*2+1][1] = t[3];
            }
        }
#pragma unroll
        for (int mi = 0; mi < 4; mi++)
#pragma unroll
            for (int ni = 0; ni < 4; ni++) {
                mmah(acc[mi][ni], ah[mi], bh[ni]);
                if (TERMS >= 2) mmah(acc[mi][ni], al[mi], bh[ni]);
                if (TERMS == 3) mmah(acc[mi][ni], ah[mi], bl[ni]);
            }
    }
}

template<int TERMS>
__device__ __forceinline__ void hmma_loop(
    float acc[4][4][4], char* smem, int tid,
    const __half* pAh, const __half* pAl,
    const __half* pBh, const __half* pBl, int Kd)
{
    const int lane = tid & 31, wid = tid >> 5;
    const int warp_m = wid >> 2, warp_n = wid & 3;
    const uint32_t STG = ST_OF(TERMS);
    uint32_t sb0 = smem_u32(smem);
    const int KC = Kd >> 5;

    issue_chunk<TERMS>(sb0,       tid, pAh, pAl, pBh, pBl, Kd, 0);
    issue_chunk<TERMS>(sb0 + STG, tid, pAh, pAl, pBh, pBl, Kd, 32);

    for (int i = 0; i < KC; i++) {
        if (i + 2 < KC) {
            issue_chunk<TERMS>(sb0 + ((i + 2) % NSTAGE)*STG, tid,
                               pAh, pAl, pBh, pBl, Kd, (i + 2) << 5);
            asm volatile("cp.async.wait_group 2;" ::: "memory");
        } else {
            asm volatile("cp.async.wait_group 0;" ::: "memory");
        }
        __syncthreads();
        compute_chunk<TERMS>(acc, sb0 + (i % NSTAGE)*STG, lane, warp_m, warp_n);
        __syncthreads();
    }
}

// ---------------------------------------------------------------------------
// NT GEMM: C = scale*(A@B^T). MODE 0: fp32 out; 1: split h/l; 2: single h
// ---------------------------------------------------------------------------
template<int TERMS, int MODE>
__global__ void __launch_bounds__(256, 1) gemm_tc(
    const __half* __restrict__ Ah, const __half* __restrict__ Al,
    const __half* __restrict__ Bh, const __half* __restrict__ Bl,
    float* __restrict__ Cf, __half* __restrict__ Ch, __half* __restrict__ Cl,
    int Kd, int Cstride, float scale)
{
    extern __shared__ char smem[];
    const int tid = threadIdx.x, lane = tid & 31, wid = tid >> 5;
    const int warp_m = wid >> 2, warp_n = wid & 3;
    const int row0 = blockIdx.y << 7, col0 = blockIdx.x << 7;

    float acc[4][4][4] = {};
    hmma_loop<TERMS>(acc, smem, tid,
                     Ah + (size_t)row0 * Kd,
                     (TERMS >= 2) ? Al + (size_t)row0 * Kd : Ah,
                     Bh + (size_t)col0 * Kd,
                     (TERMS == 3) ? Bl + (size_t)col0 * Kd : Bh, Kd);

    const int rb = row0 + warp_m*64 + (lane >> 2);
    const int cb = col0 + warp_n*32 + (lane & 3)*2;
#pragma unroll
    for (int mi = 0; mi < 4; mi++)
#pragma unroll
        for (int ni = 0; ni < 4; ni++)
#pragma unroll
            for (int h = 0; h < 2; h++) {
                int r = rb + mi*16 + 8*h;
                int c = cb + ni*8;
                float v0 = acc[mi][ni][2*h + 0] * scale;
                float v1 = acc[mi][ni][2*h + 1] * scale;
                if (MODE == 0) {
                    *(float2*)&Cf[(size_t)r * Cstride + c] = make_float2(v0, v1);
                } else if (MODE == 1) {
                    __half h0 = __float2half(v0), h1 = __float2half(v1);
                    __half l0 = __float2half(v0 - __half2float(h0));
                    __half l1 = __float2half(v1 - __half2float(h1));
                    size_t o = (size_t)r * Cstride + c;
                    *(__half2*)&Ch[o] = __halves2half2(h0, h1);
                    *(__half2*)&Cl[o] = __halves2half2(l0, l1);
                } else {
                    size_t o = (size_t)r * Cstride + c;
                    *(__half2*)&Ch[o] = __halves2half2(__float2half(v0), __float2half(v1));
                }
            }
}

// ---------------------------------------------------------------------------
// banded logits: att[b,n,m] = QS * Z[b,n]·x[b,m], |n-m| < AP  (2-term over Z)
// ---------------------------------------------------------------------------
__global__ void __launch_bounds__(256, 1) band_tc(
    const __half* __restrict__ Zh, const __half* __restrict__ Zl,
    const __half* __restrict__ xh,
    float* __restrict__ att)
{
    const int it = blockIdx.y;
    const int jt = it + (int)blockIdx.x - 2;
    if (jt < 0 || jt >= (NN >> 7)) return;
    const int bz = blockIdx.z;

    extern __shared__ char smem[];
    const int tid = threadIdx.x, lane = tid & 31, wid = tid >> 5;
    const int warp_m = wid >> 2, warp_n = wid & 3;
    const int row0 = it << 7, col0 = jt << 7;
    const size_t boff = (size_t)bz << 22;

    float acc[4][4][4] = {};
    hmma_loop<2>(acc, smem, tid,
                 Zh + boff + (size_t)row0 * DD, Zl + boff + (size_t)row0 * DD,
                 xh + boff + (size_t)col0 * DD, nullptr, DD);

    float* attb = att + ((size_t)bz << 24);
    const int rb = row0 + warp_m*64 + (lane >> 2);
    const int cb = col0 + warp_n*32 + (lane & 3)*2;
#pragma unroll
    for (int mi = 0; mi < 4; mi++)
#pragma unroll
        for (int ni = 0; ni < 4; ni++)
#pragma unroll
            for (int h = 0; h < 2; h++) {
                int gi = rb + mi*16 + 8*h;
#pragma unroll
                for (int q = 0; q < 2; q++) {
                    int gj = cb + ni*8 + q;
                    int d = gi - gj;
                    if (d > -AP && d < AP)
                        attb[(size_t)gi * NN + gj] = acc[mi][ni][2*h + q] * QS;
                }
            }
}

// ---------------------------------------------------------------------------
// splits & transpose
// ---------------------------------------------------------------------------
__global__ void split2(const float* __restrict__ in,
                       __half* __restrict__ h, __half* __restrict__ l, int n2)
{
    int i = blockIdx.x * blockDim.x + threadIdx.x;
    int st = gridDim.x * blockDim.x;
    for (; i < n2; i += st) {
        float2 v = ((const float2*)in)[i];
        __half hx = __float2half(v.x), hy = __float2half(v.y);
        ((__half2*)h)[i] = __halves2half2(hx, hy);
        ((__half2*)l)[i] = __halves2half2(__float2half(v.x - __half2float(hx)),
                                          __float2half(v.y - __half2float(hy)));
    }
}
__global__ void round1(const float* __restrict__ in, __half* __restrict__ h, int n2)
{
    int i = blockIdx.x * blockDim.x + threadIdx.x;
    int st = gridDim.x * blockDim.x;
    for (; i < n2; i += st) {
        float2 v = ((const float2*)in)[i];
        ((__half2*)h)[i] = __halves2half2(__float2half(v.x), __float2half(v.y));
    }
}
__global__ void transpose_split(const float* __restrict__ in,
                                __half* __restrict__ th, __half* __restrict__ tl)
{
    __shared__ float t[32][33];
    int bx = blockIdx.x << 5, by = blockIdx.y << 5;
#pragma unroll
    for (int k = 0; k < 32; k += 8)
        t[threadIdx.y + k][threadIdx.x] = in[(size_t)(by + threadIdx.y + k) * DD + bx + threadIdx.x];
    __syncthreads();
#pragma unroll
    for (int k = 0; k < 32; k += 8) {
        int r = bx + threadIdx.y + k, c = by + threadIdx.x;
        float v = t[threadIdx.x][threadIdx.y + k];
        __half h = __float2half(v);
        th[(size_t)r * DD + c] = h;
        tl[(size_t)r * DD + c] = __float2half(v - __half2float(h));
    }
}

// ---------------------------------------------------------------------------
// fused: zero row + band softmax + fp16 P emit over padded window
// ---------------------------------------------------------------------------
__global__ void __launch_bounds__(128) band_softmax(
    float* __restrict__ att, __half* __restrict__ Ph)
{
    __shared__ float red[4];
    const int gid = blockIdx.x;
    const int b = gid >> 12;
    const int i = gid & (NN - 1);
    const size_t rowbase = ((size_t)b << 24) + ((size_t)i << 12);
    float* row = att + rowbase;
    int jlo = i - (AP - 1); if (jlo < 0) jlo = 0;
    int jhi = i + (AP - 1); if (jhi > NN - 1) jhi = NN - 1;
    const int cnt = jhi - jlo + 1;

    float v[4];
    int nc = 0;
    float m = -1e30f;
    for (int t = threadIdx.x; t < cnt; t += 128) { v[nc] = row[jlo + t]; m = fmaxf(m, v[nc]); nc++; }
    for (int o = 16; o > 0; o >>= 1) m = fmaxf(m, __shfl_xor_sync(0xffffffffu, m, o));
    const int w = threadIdx.x >> 5;
    if ((threadIdx.x & 31) == 0) red[w] = m;
    __syncthreads();
    m = fmaxf(fmaxf(red[0], red[1]), fmaxf(red[2], red[3]));
    __syncthreads();

    float s = 0.f;
    for (int c = 0; c < nc; c++) { v[c] = __expf(v[c] - m); s += v[c]; }
    for (int o = 16; o > 0; o >>= 1) s += __shfl_xor_sync(0xffffffffu, s, o);
    if ((threadIdx.x & 31) == 0) red[w] = s;
    __syncthreads();
    s = red[0] + red[1] + red[2] + red[3];
    const float inv = 1.0f / s;

    // zero whole row (out-of-band must be exactly 0) — logits held in regs
    float4 z4 = make_float4(0.f, 0.f, 0.f, 0.f);
    for (int t = threadIdx.x; t < (NN >> 2); t += 128) ((float4*)row)[t] = z4;
    __syncthreads();
    nc = 0;
    for (int t = threadIdx.x; t < cnt; t += 128) { row[jlo + t] = v[nc] * inv; nc++; }
    __syncthreads();

    // fp16 P over 128-aligned window (reads zeros out-of-band)
    int wlo = i - 256; wlo &= ~127; if (wlo < 0) wlo = 0;
    int whi = (i + 384) & ~127; if (whi > NN) whi = NN;
    for (int n = wlo + threadIdx.x; n < whi; n += 128)
        Ph[rowbase + n] = __float2half(row[n]);
}

// ===========================================================================
// ptv: Y[b,n,o] = sum_m P[b,m,n] * V[b,m,o]  (banded, 1-term, trans-ldsm)
// stage: Ph[32][128] | Vh  (8KB each, 16KB total)
// ===========================================================================
__device__ __forceinline__ void ptv_issue(
    uint32_t sbase, int tid,
    const __half* Phg, const __half* Vhg, int m0, int n0, int o0)
{
#pragma unroll
    for (int j = 0; j < 2; j++) {
        int e = tid + (j << 8);
        int r = e >> 4, c16 = e & 15;
        uint32_t sw = SW256((uint32_t)(r << 8) + (c16 << 4));
        cp16(sbase +         sw, Phg + (size_t)(m0 + r) * NN + n0 + (c16 << 3));
        cp16(sbase + 8192u + sw, Vhg + (size_t)(m0 + r) * DD + o0 + (c16 << 3));
    }
    asm volatile("cp.async.commit_group;" ::: "memory");
}

__device__ __forceinline__ void ptv_compute(
    float acc[4][4][4], uint32_t sb, int lane, int warp_m, int warp_n)
{
#pragma unroll
    for (int ks = 0; ks < 2; ks++) {
        const int m16 = ks << 4;
        uint32_t ah[4][4], bh[4][2];
        const int ar = m16 + ((lane >> 4) << 3) + (lane & 7);
        const int acsel = ((lane >> 3) & 1) << 3;
#pragma unroll
        for (int mi = 0; mi < 4; mi++) {
            int nb = warp_m*64 + mi*16 + acsel;
            ldsm4t(ah[mi], sb + SW256((uint32_t)(ar << 8) + (nb << 1)));
        }
        const int br = m16 + (((lane >> 3) & 1) << 3) + (lane & 7);
        const int bcsel = (lane >> 4) << 3;
#pragma unroll
        for (int jb = 0; jb < 2; jb++) {
            int ob = warp_n*32 + jb*16 + bcsel;
            uint32_t t4[4];
            ldsm4t(t4, sb + 8192u + SW256((uint32_t)(br << 8) + (ob << 1)));
            bh[jb*2][0] = t4[0]; bh[jb*2][1] = t4[1];
            bh[jb*2+1][0] = t4[2]; bh[jb*2+1][1] = t4[3];
        }
#pragma unroll
        for (int mi = 0; mi < 4; mi++)
#pragma unroll
            for (int ni = 0; ni < 4; ni++)
                mmah(acc[mi][ni], ah[mi], bh[ni]);
    }
}

__global__ void __launch_bounds__(256, 1) ptv_tc(
    const __half* __restrict__ Phg, const __half* __restrict__ Vhg,
    __half* __restrict__ Yh)
{
    const int bz = blockIdx.z;
    const int n0 = blockIdx.y << 7;
    const int o0 = blockIdx.x << 7;
    const __half* Pb = Phg + ((size_t)bz << 24);
    const __half* Vb = Vhg + ((size_t)bz << 22);

    extern __shared__ char smem[];
    uint32_t sb0 = smem_u32(smem);
    const int tid = threadIdx.x, lane = tid & 31, wid = tid >> 5;
    const int warp_m = wid >> 2, warp_n = wid & 3;

    int mlo = n0 - 256; if (mlo < 0) mlo = 0;
    int mhe = n0 + 384; if (mhe > NN) mhe = NN;
    const int NC = (mhe - mlo) >> 5;

    float acc[4][4][4] = {};

    ptv_issue(sb0,          tid, Pb, Vb, mlo,      n0, o0);
    ptv_issue(sb0 + 16384u, tid, Pb, Vb, mlo + 32, n0, o0);

    for (int i = 0; i < NC; i++) {
        if (i + 2 < NC) {
            ptv_issue(sb0 + ((i + 2) % NSTAGE)*16384u, tid,
                      Pb, Vb, mlo + ((i + 2) << 5), n0, o0);
            asm volatile("cp.async.wait_group 2;" ::: "memory");
        } else {
            asm volatile("cp.async.wait_group 0;" ::: "memory");
        }
        __syncthreads();
        ptv_compute(acc, sb0 + (i % NSTAGE)*16384u, lane, warp_m, warp_n);
        __syncthreads();
    }

    __half* Yb = Yh + ((size_t)bz << 22);
    const int rb = n0 + warp_m*64 + (lane >> 2);
    const int cb = o0 + warp_n*32 + (lane & 3)*2;
#pragma unroll
    for (int mi = 0; mi < 4; mi++)
#pragma unroll
        for (int ni = 0; ni < 4; ni++)
#pragma unroll
            for (int h = 0; h < 2; h++) {
                size_t off = (size_t)(rb + mi*16 + 8*h) * DD + cb + ni*8;
                *(__half2*)&Yb[off] = __halves2half2(
                    __float2half(acc[mi][ni][2*h + 0]),
                    __float2half(acc[mi][ni][2*h + 1]));
            }
}

// ---------------------------------------------------------------------------
extern "C" void kernel_launch(void* const* d_in, const int* in_sizes, int n_in,
                              void* d_out, int out_size)
{
    const float* x  = (const float*)d_in[0];
    const float* Wk = (const float*)d_in[1];
    const float* Wq = (const float*)d_in[2];
    const float* Wv = (const float*)d_in[3];
    const float* Wo = (const float*)d_in[4];

    float* y_out   = (float*)d_out;
    float* att_out = y_out + (size_t)BB * NN * DD;

    __half *xh, *xl, *WkTh, *WkTl, *WqTh, *WqTl, *Wvh, *Woh;
    __half *Gh, *Zh, *Zl, *Vh, *Yh, *Ph;
    cudaGetSymbolAddress((void**)&xh,   g_xh);   cudaGetSymbolAddress((void**)&xl,   g_xl);
    cudaGetSymbolAddress((void**)&WkTh, g_WkTh); cudaGetSymbolAddress((void**)&WkTl, g_WkTl);
    cudaGetSymbolAddress((void**)&WqTh, g_WqTh); cudaGetSymbolAddress((void**)&WqTl, g_WqTl);
    cudaGetSymbolAddress((void**)&Wvh,  g_Wvh);  cudaGetSymbolAddress((void**)&Woh,  g_Woh);
    cudaGetSymbolAddress((void**)&Gh,   g_Gh);
    cudaGetSymbolAddress((void**)&Zh,   g_Zh);   cudaGetSymbolAddress((void**)&Zl,   g_Zl);
    cudaGetSymbolAddress((void**)&Vh,   g_Vh);   cudaGetSymbolAddress((void**)&Yh,   g_Yh);
    cudaGetSymbolAddress((void**)&Ph,   g_Ph);

    cudaFuncSetAttribute((const void*)gemm_tc<3,2>, cudaFuncAttributeMaxDynamicSharedMemorySize, SM3);
    cudaFuncSetAttribute((const void*)gemm_tc<2,1>, cudaFuncAttributeMaxDynamicSharedMemorySize, SM2);
    cudaFuncSetAttribute((const void*)gemm_tc<2,2>, cudaFuncAttributeMaxDynamicSharedMemorySize, SM2);
    cudaFuncSetAttribute((const void*)gemm_tc<1,0>, cudaFuncAttributeMaxDynamicSharedMemorySize, SM1);
    cudaFuncSetAttribute((const void*)band_tc,      cudaFuncAttributeMaxDynamicSharedMemorySize, SM2);
    cudaFuncSetAttribute((const void*)ptv_tc,       cudaFuncAttributeMaxDynamicSharedMemorySize, SM1);

    // 1. operand prep
    split2<<<4096, 256>>>(x, xh, xl, (BB * NN * DD) / 2);
    transpose_split<<<dim3(32, 32), dim3(32, 8)>>>(Wk, WkTh, WkTl);
    transpose_split<<<dim3(32, 32), dim3(32, 8)>>>(Wq, WqTh, WqTl);
    round1<<<512, 256>>>(Wv, Wvh, (DD * DD) / 2);
    round1<<<512, 256>>>(Wo, Woh, (DD * DD) / 2);

    // 2. G[d2,d1] = sum_o WkT[d2,o]*WqT[d1,o]   (3-term, high-only out)
    gemm_tc<3,2><<<dim3(8, 8), 256, SM3>>>(WkTh, WkTl, WqTh, WqTl,
                                           nullptr, Gh, nullptr, DD, DD, 1.0f);

    // 3. Z[n,d2] = sum_d1 x[n,d1]*G[d2,d1]      (2-term, split out)
    dim3 gP(DD / 128, (BB * NN) / 128);
    gemm_tc<2,1><<<gP, 256, SM2>>>(xh, xl, Gh, nullptr, nullptr, Zh, Zl, DD, DD, 1.0f);

    // 4. V[n,o] = sum_d x[n,d]*Wv[o,d]          (2-term, single-h out)
    gemm_tc<2,2><<<gP, 256, SM2>>>(xh, xl, Wvh, nullptr, nullptr, Vh, nullptr, DD, DD, 1.0f);

    // 5. banded logits = QS * Z·x^T             (2-term over Z)
    band_tc<<<dim3(5, NN / 128, BB), 256, SM2>>>(Zh, Zl, xh, att_out);

    // 6. fused zero + softmax + P emit
    band_softmax<<<BB * NN, 128>>>(att_out, Ph);

    // 7. Y = P^T @ V (banded, 1-term)
    ptv_tc<<<dim3(DD / 128, NN / 128, BB), 256, SM1>>>(Ph, Vh, Yh);

    // 8. y = Y @ Wo^T                           (1-term, fp32 out)
    gemm_tc<1,0><<<gP, 256, SM1>>>(Yh, nullptr, Woh, nullptr, y_out, nullptr, nullptr, DD, DD, 1.0f);
}

// round 8
// speedup vs baseline: 5.9969x; 1.0917x over previous
#include <cuda_runtime.h>
#include <cuda_fp16.h>
#include <cstdint>

#define BB   4
#define NN   4096
#define DD   1024
#define AP   256
#define QS   0.06f

#define NSTAGE 3
#define ST_OF(T) ((T)==3 ? 32768u : (T)==2 ? 24576u : 16384u)
#define SM3    (NSTAGE*32768)
#define SM2    (NSTAGE*24576)
#define SM1    (NSTAGE*16384)

// ---------------------------------------------------------------------------
// device scratch (allocation-free rule)
// ---------------------------------------------------------------------------
__device__ __align__(16) __half g_xh[BB*NN*DD], g_xl[BB*NN*DD];
__device__ __align__(16) __half g_WkTh[DD*DD], g_WkTl[DD*DD];
__device__ __align__(16) __half g_WqTh[DD*DD], g_WqTl[DD*DD];
__device__ __align__(16) __half g_Wvh[DD*DD];
__device__ __align__(16) __half g_Woh[DD*DD];
__device__ __align__(16) __half g_Gh[DD*DD];
__device__ __align__(16) __half g_Zh[BB*NN*DD], g_Zl[BB*NN*DD];
__device__ __align__(16) __half g_Vh[BB*NN*DD];
__device__ __align__(16) __half g_Yh[BB*NN*DD];
__device__ __align__(16) __half g_Ph[(size_t)BB*NN*NN];

// ---------------------------------------------------------------------------
// PTX helpers — baseline (non-arch-specific) instructions only
// ---------------------------------------------------------------------------
__device__ __forceinline__ uint32_t smem_u32(const void* p) {
    uint32_t a;
    asm("{ .reg .u64 t; cvta.to.shared.u64 t, %1; cvt.u32.u64 %0, t; }" : "=r"(a) : "l"(p));
    return a;
}
__device__ __forceinline__ void cp16(uint32_t s, const void* g) {
    asm volatile("cp.async.cg.shared.global [%0], [%1], 16;" :: "r"(s), "l"(g));
}
__device__ __forceinline__ void ldsm4(uint32_t* r, uint32_t a) {
    asm volatile("ldmatrix.sync.aligned.m8n8.x4.shared.b16 {%0,%1,%2,%3}, [%4];"
        : "=r"(r[0]), "=r"(r[1]), "=r"(r[2]), "=r"(r[3]) : "r"(a));
}
__device__ __forceinline__ void ldsm4t(uint32_t* r, uint32_t a) {
    asm volatile("ldmatrix.sync.aligned.m8n8.x4.trans.shared.b16 {%0,%1,%2,%3}, [%4];"
        : "=r"(r[0]), "=r"(r[1]), "=r"(r[2]), "=r"(r[3]) : "r"(a));
}
__device__ __forceinline__ void mmah(float* d, const uint32_t* a, const uint32_t* b) {
    asm volatile("mma.sync.aligned.m16n8k16.row.col.f32.f16.f16.f32 "
        "{%0,%1,%2,%3}, {%4,%5,%6,%7}, {%8,%9}, {%0,%1,%2,%3};"
        : "+f"(d[0]), "+f"(d[1]), "+f"(d[2]), "+f"(d[3])
        : "r"(a[0]), "r"(a[1]), "r"(a[2]), "r"(a[3]), "r"(b[0]), "r"(b[1]));
}
#define SW64(off)  ((off) ^ (((off) >> 3) & 0x30))
#define SW256(off) ((off) ^ (((off) >> 4) & 0x70))

// ===========================================================================
// dense NT GEMM pipeline (fp16 split; 64B smem rows, K-chunks of 32)
// TERMS==3: Ah·Bh + Al·Bh + Ah·Bl  | TERMS==2: Ah·Bh + Al·Bh | TERMS==1: Ah·Bh
// ===========================================================================
template<int TERMS>
__device__ __forceinline__ void issue_chunk(
    uint32_t sbase, int tid,
    const __half* pAh, const __half* pAl, const __half* pBh, const __half* pBl,
    int Kd, int k0)
{
    const uint32_t BOFF = (TERMS >= 2) ? 16384u : 8192u;
#pragma unroll
    for (int j = 0; j < 2; j++) {
        int e = tid + (j << 8);
        int r = e >> 2, c = e & 3;
        uint32_t sw = SW64((uint32_t)(r << 6) + (c << 4));
        size_t g = (size_t)r * Kd + k0 + (c << 3);
        cp16(sbase + sw, pAh + g);
        if (TERMS >= 2) cp16(sbase + 8192u + sw, pAl + g);
        cp16(sbase + BOFF + sw, pBh + g);
        if (TERMS == 3) cp16(sbase + 24576u + sw, pBl + g);
    }
    asm volatile("cp.async.commit_group;" ::: "memory");
}

template<int TERMS>
__device__ __forceinline__ void compute_chunk(
    float acc[4][4][4], uint32_t sb, int lane, int warp_m, int warp_n)
{
    const uint32_t BOFF = (TERMS >= 2) ? 16384u : 8192u;
#pragma unroll
    for (int ks = 0; ks < 2; ks++) {
        uint32_t ah[4][4], al[4][4], bh[4][2], bl[4][2];
#pragma unroll
        for (int mi = 0; mi < 4; mi++) {
            int row = warp_m*64 + mi*16 + ((lane >> 3) & 1)*8 + (lane & 7);
            int kb  = ks*32 + (lane >> 4)*16;
            uint32_t a = sb + SW64((uint32_t)(row << 6) + kb);
            ldsm4(ah[mi], a);
            if (TERMS >= 2) ldsm4(al[mi], a + 8192u);
        }
#pragma unroll
        for (int nj = 0; nj < 2; nj++) {
            int nr = warp_n*32 + nj*16 + (lane >> 4)*8 + (lane & 7);
            int kb = ks*32 + ((lane >> 3) & 1)*16;
            uint32_t a = sb + BOFF + SW64((uint32_t)(nr << 6) + kb);
            uint32_t t[4];
            ldsm4(t, a);
            bh[nj*2][0] = t[0]; bh[nj*2][1] = t[1];
            bh[nj*2+1][0] = t[2]; bh[nj*2+1][1] = t[3];
            if (TERMS == 3) {
                ldsm4(t, a + 8192u);
                bl[nj*2][0] = t[0]; bl[nj*2][1] = t[1];
                bl[nj*2+1][0] = t[2]; bl[nj*2+1][1] = t[3];
            }
        }
#pragma unroll
        for (int mi = 0; mi < 4; mi++)
#pragma unroll
            for (int ni = 0; ni < 4; ni++) {
                mmah(acc[mi][ni], ah[mi], bh[ni]);
                if (TERMS >= 2) mmah(acc[mi][ni], al[mi], bh[ni]);
                if (TERMS == 3) mmah(acc[mi][ni], ah[mi], bl[ni]);
            }
    }
}

template<int TERMS>
__device__ __forceinline__ void hmma_loop(
    float acc[4][4][4], char* smem, int tid,
    const __half* pAh, const __half* pAl,
    const __half* pBh, const __half* pBl, int Kd)
{
    const int lane = tid & 31, wid = tid >> 5;
    const int warp_m = wid >> 2, warp_n = wid & 3;
    const uint32_t STG = ST_OF(TERMS);
    uint32_t sb0 = smem_u32(smem);
    const int KC = Kd >> 5;

    issue_chunk<TERMS>(sb0,       tid, pAh, pAl, pBh, pBl, Kd, 0);
    issue_chunk<TERMS>(sb0 + STG, tid, pAh, pAl, pBh, pBl, Kd, 32);

    for (int i = 0; i < KC; i++) {
        if (i + 2 < KC) {
            issue_chunk<TERMS>(sb0 + ((i + 2) % NSTAGE)*STG, tid,
                               pAh, pAl, pBh, pBl, Kd, (i + 2) << 5);
            asm volatile("cp.async.wait_group 2;" ::: "memory");
        } else {
            asm volatile("cp.async.wait_group 0;" ::: "memory");
        }
        __syncthreads();
        compute_chunk<TERMS>(acc, sb0 + (i % NSTAGE)*STG, lane, warp_m, warp_n);
        __syncthreads();
    }
}

// ---------------------------------------------------------------------------
// NT GEMM: C = scale*(A@B^T). MODE 0: fp32 out; 1: split h/l; 2: single h
// ---------------------------------------------------------------------------
template<int TERMS, int MODE>
__global__ void __launch_bounds__(256, 1) gemm_tc(
    const __half* __restrict__ Ah, const __half* __restrict__ Al,
    const __half* __restrict__ Bh, const __half* __restrict__ Bl,
    float* __restrict__ Cf, __half* __restrict__ Ch, __half* __restrict__ Cl,
    int Kd, int Cstride, float scale)
{
    extern __shared__ char smem[];
    const int tid = threadIdx.x, lane = tid & 31, wid = tid >> 5;
    const int warp_m = wid >> 2, warp_n = wid & 3;
    const int row0 = blockIdx.y << 7, col0 = blockIdx.x << 7;

    float acc[4][4][4] = {};
    hmma_loop<TERMS>(acc, smem, tid,
                     Ah + (size_t)row0 * Kd,
                     (TERMS >= 2) ? Al + (size_t)row0 * Kd : Ah,
                     Bh + (size_t)col0 * Kd,
                     (TERMS == 3) ? Bl + (size_t)col0 * Kd : Bh, Kd);

    const int rb = row0 + warp_m*64 + (lane >> 2);
    const int cb = col0 + warp_n*32 + (lane & 3)*2;
#pragma unroll
    for (int mi = 0; mi < 4; mi++)
#pragma unroll
        for (int ni = 0; ni < 4; ni++)
#pragma unroll
            for (int h = 0; h < 2; h++) {
                int r = rb + mi*16 + 8*h;
                int c = cb + ni*8;
                float v0 = acc[mi][ni][2*h + 0] * scale;
                float v1 = acc[mi][ni][2*h + 1] * scale;
                if (MODE == 0) {
                    *(float2*)&Cf[(size_t)r * Cstride + c] = make_float2(v0, v1);
                } else if (MODE == 1) {
                    __half h0 = __float2half(v0), h1 = __float2half(v1);
                    __half l0 = __float2half(v0 - __half2float(h0));
                    __half l1 = __float2half(v1 - __half2float(h1));
                    size_t o = (size_t)r * Cstride + c;
                    *(__half2*)&Ch[o] = __halves2half2(h0, h1);
                    *(__half2*)&Cl[o] = __halves2half2(l0, l1);
                } else {
                    size_t o = (size_t)r * Cstride + c;
                    *(__half2*)&Ch[o] = __halves2half2(__float2half(v0), __float2half(v1));
                }
            }
}

// ---------------------------------------------------------------------------
// banded logits: att[b,n,m] = QS * Z[b,n]·x[b,m], |n-m| < AP  (2-term over Z)
// Writes 0 to in-window out-of-band cells; jt==it block also zeroes the
// out-of-window columns of its 128-row strip (replaces the serial zero pass).
// ---------------------------------------------------------------------------
__global__ void __launch_bounds__(256, 1) band_tc(
    const __half* __restrict__ Zh, const __half* __restrict__ Zl,
    const __half* __restrict__ xh,
    float* __restrict__ att)
{
    const int it = blockIdx.y;
    const int jt = it + (int)blockIdx.x - 2;
    const int bz = blockIdx.z;
    const int tid = threadIdx.x;
    float* attb = att + ((size_t)bz << 24);
    const int row0 = it << 7;

    // designated block zeroes out-of-window columns of this strip
    if (blockIdx.x == 2) {
        int lo_t = it - 2; if (lo_t < 0) lo_t = 0;
        int hi_t = it + 2; if (hi_t > 31) hi_t = 31;
        const int cL4 = (lo_t << 7) >> 2;         // left region float4 count
        const int cR0 = ((hi_t + 1) << 7) >> 2;   // right region float4 start
        float4 z4 = make_float4(0.f, 0.f, 0.f, 0.f);
        const int lane = tid & 31, w = tid >> 5;
        for (int r = w; r < 128; r += 8) {
            float4* rp = (float4*)(attb + (size_t)(row0 + r) * NN);
            for (int c = lane; c < cL4; c += 32) rp[c] = z4;
            for (int c = cR0 + lane; c < (NN >> 2); c += 32) rp[c] = z4;
        }
    }
    if (jt < 0 || jt >= (NN >> 7)) return;

    extern __shared__ char smem[];
    const int lane = tid & 31, wid = tid >> 5;
    const int warp_m = wid >> 2, warp_n = wid & 3;
    const int col0 = jt << 7;
    const size_t boff = (size_t)bz << 22;

    float acc[4][4][4] = {};
    hmma_loop<2>(acc, smem, tid,
                 Zh + boff + (size_t)row0 * DD, Zl + boff + (size_t)row0 * DD,
                 xh + boff + (size_t)col0 * DD, nullptr, DD);

    const int rb = row0 + warp_m*64 + (lane >> 2);
    const int cb = col0 + warp_n*32 + (lane & 3)*2;
#pragma unroll
    for (int mi = 0; mi < 4; mi++)
#pragma unroll
        for (int ni = 0; ni < 4; ni++)
#pragma unroll
            for (int h = 0; h < 2; h++) {
                int gi = rb + mi*16 + 8*h;
                int gj = cb + ni*8;
                int d0 = gi - gj, d1 = gi - gj - 1;
                float w0 = (d0 > -AP && d0 < AP) ? acc[mi][ni][2*h + 0] * QS : 0.f;
                float w1 = (d1 > -AP && d1 < AP) ? acc[mi][ni][2*h + 1] * QS : 0.f;
                *(float2*)&attb[(size_t)gi * NN + gj] = make_float2(w0, w1);
            }
}

// ---------------------------------------------------------------------------
// splits & transpose
// ---------------------------------------------------------------------------
__global__ void split2(const float* __restrict__ in,
                       __half* __restrict__ h, __half* __restrict__ l, int n2)
{
    int i = blockIdx.x * blockDim.x + threadIdx.x;
    int st = gridDim.x * blockDim.x;
    for (; i < n2; i += st) {
        float2 v = ((const float2*)in)[i];
        __half hx = __float2half(v.x), hy = __float2half(v.y);
        ((__half2*)h)[i] = __halves2half2(hx, hy);
        ((__half2*)l)[i] = __halves2half2(__float2half(v.x - __half2float(hx)),
                                          __float2half(v.y - __half2float(hy)));
    }
}
__global__ void round1(const float* __restrict__ in, __half* __restrict__ h, int n2)
{
    int i = blockIdx.x * blockDim.x + threadIdx.x;
    int st = gridDim.x * blockDim.x;
    for (; i < n2; i += st) {
        float2 v = ((const float2*)in)[i];
        ((__half2*)h)[i] = __halves2half2(__float2half(v.x), __float2half(v.y));
    }
}
__global__ void transpose_split(const float* __restrict__ in,
                                __half* __restrict__ th, __half* __restrict__ tl)
{
    __shared__ float t[32][33];
    int bx = blockIdx.x << 5, by = blockIdx.y << 5;
#pragma unroll
    for (int k = 0; k < 32; k += 8)
        t[threadIdx.y + k][threadIdx.x] = in[(size_t)(by + threadIdx.y + k) * DD + bx + threadIdx.x];
    __syncthreads();
#pragma unroll
    for (int k = 0; k < 32; k += 8) {
        int r = bx + threadIdx.y + k, c = by + threadIdx.x;
        float v = t[threadIdx.x][threadIdx.y + k];
        __half h = __float2half(v);
        th[(size_t)r * DD + c] = h;
        tl[(size_t)r * DD + c] = __float2half(v - __half2float(h));
    }
}

// ---------------------------------------------------------------------------
// band softmax + fp16 P emit over padded window (no zeroing — band_tc did it)
// ---------------------------------------------------------------------------
__global__ void __launch_bounds__(128) band_softmax(
    float* __restrict__ att, __half* __restrict__ Ph)
{
    __shared__ float red[4];
    const int gid = blockIdx.x;
    const int b = gid >> 12;
    const int i = gid & (NN - 1);
    const size_t rowbase = ((size_t)b << 24) + ((size_t)i << 12);
    float* row = att + rowbase;
    int jlo = i - (AP - 1); if (jlo < 0) jlo = 0;
    int jhi = i + (AP - 1); if (jhi > NN - 1) jhi = NN - 1;
    const int cnt = jhi - jlo + 1;

    float v[4];
    int nc = 0;
    float m = -1e30f;
    for (int t = threadIdx.x; t < cnt; t += 128) { v[nc] = row[jlo + t]; m = fmaxf(m, v[nc]); nc++; }
    for (int o = 16; o > 0; o >>= 1) m = fmaxf(m, __shfl_xor_sync(0xffffffffu, m, o));
    const int w = threadIdx.x >> 5;
    if ((threadIdx.x & 31) == 0) red[w] = m;
    __syncthreads();
    m = fmaxf(fmaxf(red[0], red[1]), fmaxf(red[2], red[3]));
    __syncthreads();

    float s = 0.f;
    for (int c = 0; c < nc; c++) { v[c] = __expf(v[c] - m); s += v[c]; }
    for (int o = 16; o > 0; o >>= 1) s += __shfl_xor_sync(0xffffffffu, s, o);
    if ((threadIdx.x & 31) == 0) red[w] = s;
    __syncthreads();
    s = red[0] + red[1] + red[2] + red[3];
    const float inv = 1.0f / s;

    nc = 0;
    for (int t = threadIdx.x; t < cnt; t += 128) { row[jlo + t] = v[nc] * inv; nc++; }
    __syncthreads();

    // fp16 P over 128-aligned window; out-of-band cells are 0 (no read)
    int wlo = i - 256; wlo &= ~127; if (wlo < 0) wlo = 0;
    int whi = (i + 384) & ~127; if (whi > NN) whi = NN;
    for (int n = wlo + threadIdx.x; n < whi; n += 128) {
        float f = (n >= jlo && n <= jhi) ? row[n] : 0.f;
        Ph[rowbase + n] = __float2half(f);
    }
}

// ===========================================================================
// ptv: Y[b,n,o] = sum_m P[b,m,n] * V[b,m,o]  (banded, 1-term, trans-ldsm)
// ===========================================================================
__device__ __forceinline__ void ptv_issue(
    uint32_t sbase, int tid,
    const __half* Phg, const __half* Vhg, int m0, int n0, int o0)
{
#pragma unroll
    for (int j = 0; j < 2; j++) {
        int e = tid + (j << 8);
        int r = e >> 4, c16 = e & 15;
        uint32_t sw = SW256((uint32_t)(r << 8) + (c16 << 4));
        cp16(sbase +         sw, Phg + (size_t)(m0 + r) * NN + n0 + (c16 << 3));
        cp16(sbase + 8192u + sw, Vhg + (size_t)(m0 + r) * DD + o0 + (c16 << 3));
    }
    asm volatile("cp.async.commit_group;" ::: "memory");
}

__device__ __forceinline__ void ptv_compute(
    float acc[4][4][4], uint32_t sb, int lane, int warp_m, int warp_n)
{
#pragma unroll
    for (int ks = 0; ks < 2; ks++) {
        const int m16 = ks << 4;
        uint32_t ah[4][4], bh[4][2];
        const int ar = m16 + ((lane >> 4) << 3) + (lane & 7);
        const int acsel = ((lane >> 3) & 1) << 3;
#pragma unroll
        for (int mi = 0; mi < 4; mi++) {
            int nb = warp_m*64 + mi*16 + acsel;
            ldsm4t(ah[mi], sb + SW256((uint32_t)(ar << 8) + (nb << 1)));
        }
        const int br = m16 + (((lane >> 3) & 1) << 3) + (lane & 7);
        const int bcsel = (lane >> 4) << 3;
#pragma unroll
        for (int jb = 0; jb < 2; jb++) {
            int ob = warp_n*32 + jb*16 + bcsel;
            uint32_t t4[4];
            ldsm4t(t4, sb + 8192u + SW256((uint32_t)(br << 8) + (ob << 1)));
            bh[jb*2][0] = t4[0]; bh[jb*2][1] = t4[1];
            bh[jb*2+1][0] = t4[2]; bh[jb*2+1][1] = t4[3];
        }
#pragma unroll
        for (int mi = 0; mi < 4; mi++)
#pragma unroll
            for (int ni = 0; ni < 4; ni++)
                mmah(acc[mi][ni], ah[mi], bh[ni]);
    }
}

__global__ void __launch_bounds__(256, 1) ptv_tc(
    const __half* __restrict__ Phg, const __half* __restrict__ Vhg,
    __half* __restrict__ Yh)
{
    const int bz = blockIdx.z;
    const int n0 = blockIdx.y << 7;
    const int o0 = blockIdx.x << 7;
    const __half* Pb = Phg + ((size_t)bz << 24);
    const __half* Vb = Vhg + ((size_t)bz << 22);

    extern __shared__ char smem[];
    uint32_t sb0 = smem_u32(smem);
    const int tid = threadIdx.x, lane = tid & 31, wid = tid >> 5;
    const int warp_m = wid >> 2, warp_n = wid & 3;

    int mlo = n0 - 256; if (mlo < 0) mlo = 0;
    int mhe = n0 + 384; if (mhe > NN) mhe = NN;
    const int NC = (mhe - mlo) >> 5;

    float acc[4][4][4] = {};

    ptv_issue(sb0,          tid, Pb, Vb, mlo,      n0, o0);
    ptv_issue(sb0 + 16384u, tid, Pb, Vb, mlo + 32, n0, o0);

    for (int i = 0; i < NC; i++) {
        if (i + 2 < NC) {
            ptv_issue(sb0 + ((i + 2) % NSTAGE)*16384u, tid,
                      Pb, Vb, mlo + ((i + 2) << 5), n0, o0);
            asm volatile("cp.async.wait_group 2;" ::: "memory");
        } else {
            asm volatile("cp.async.wait_group 0;" ::: "memory");
        }
        __syncthreads();
        ptv_compute(acc, sb0 + (i % NSTAGE)*16384u, lane, warp_m, warp_n);
        __syncthreads();
    }

    __half* Yb = Yh + ((size_t)bz << 22);
    const int rb = n0 + warp_m*64 + (lane >> 2);
    const int cb = o0 + warp_n*32 + (lane & 3)*2;
#pragma unroll
    for (int mi = 0; mi < 4; mi++)
#pragma unroll
        for (int ni = 0; ni < 4; ni++)
#pragma unroll
            for (int h = 0; h < 2; h++) {
                size_t off = (size_t)(rb + mi*16 + 8*h) * DD + cb + ni*8;
                *(__half2*)&Yb[off] = __halves2half2(
                    __float2half(acc[mi][ni][2*h + 0]),
                    __float2half(acc[mi][ni][2*h + 1]));
            }
}

// ---------------------------------------------------------------------------
extern "C" void kernel_launch(void* const* d_in, const int* in_sizes, int n_in,
                              void* d_out, int out_size)
{
    const float* x  = (const float*)d_in[0];
    const float* Wk = (const float*)d_in[1];
    const float* Wq = (const float*)d_in[2];
    const float* Wv = (const float*)d_in[3];
    const float* Wo = (const float*)d_in[4];

    float* y_out   = (float*)d_out;
    float* att_out = y_out + (size_t)BB * NN * DD;

    __half *xh, *xl, *WkTh, *WkTl, *WqTh, *WqTl, *Wvh, *Woh;
    __half *Gh, *Zh, *Zl, *Vh, *Yh, *Ph;
    cudaGetSymbolAddress((void**)&xh,   g_xh);   cudaGetSymbolAddress((void**)&xl,   g_xl);
    cudaGetSymbolAddress((void**)&WkTh, g_WkTh); cudaGetSymbolAddress((void**)&WkTl, g_WkTl);
    cudaGetSymbolAddress((void**)&WqTh, g_WqTh); cudaGetSymbolAddress((void**)&WqTl, g_WqTl);
    cudaGetSymbolAddress((void**)&Wvh,  g_Wvh);  cudaGetSymbolAddress((void**)&Woh,  g_Woh);
    cudaGetSymbolAddress((void**)&Gh,   g_Gh);
    cudaGetSymbolAddress((void**)&Zh,   g_Zh);   cudaGetSymbolAddress((void**)&Zl,   g_Zl);
    cudaGetSymbolAddress((void**)&Vh,   g_Vh);   cudaGetSymbolAddress((void**)&Yh,   g_Yh);
    cudaGetSymbolAddress((void**)&Ph,   g_Ph);

    cudaFuncSetAttribute((const void*)gemm_tc<3,2>, cudaFuncAttributeMaxDynamicSharedMemorySize, SM3);
    cudaFuncSetAttribute((const void*)gemm_tc<2,1>, cudaFuncAttributeMaxDynamicSharedMemorySize, SM2);
    cudaFuncSetAttribute((const void*)gemm_tc<1,2>, cudaFuncAttributeMaxDynamicSharedMemorySize, SM1);
    cudaFuncSetAttribute((const void*)gemm_tc<1,0>, cudaFuncAttributeMaxDynamicSharedMemorySize, SM1);
    cudaFuncSetAttribute((const void*)band_tc,      cudaFuncAttributeMaxDynamicSharedMemorySize, SM2);
    cudaFuncSetAttribute((const void*)ptv_tc,       cudaFuncAttributeMaxDynamicSharedMemorySize, SM1);

    // 1. operand prep
    split2<<<4096, 256>>>(x, xh, xl, (BB * NN * DD) / 2);
    transpose_split<<<dim3(32, 32), dim3(32, 8)>>>(Wk, WkTh, WkTl);
    transpose_split<<<dim3(32, 32), dim3(32, 8)>>>(Wq, WqTh, WqTl);
    round1<<<512, 256>>>(Wv, Wvh, (DD * DD) / 2);
    round1<<<512, 256>>>(Wo, Woh, (DD * DD) / 2);

    // 2. G[d2,d1] = sum_o WkT[d2,o]*WqT[d1,o]   (3-term, high-only out)
    gemm_tc<3,2><<<dim3(8, 8), 256, SM3>>>(WkTh, WkTl, WqTh, WqTl,
                                           nullptr, Gh, nullptr, DD, DD, 1.0f);

    // 3. Z[n,d2] = sum_d1 x[n,d1]*G[d2,d1]      (2-term, split out)
    dim3 gP(DD / 128, (BB * NN) / 128);
    gemm_tc<2,1><<<gP, 256, SM2>>>(xh, xl, Gh, nullptr, nullptr, Zh, Zl, DD, DD, 1.0f);

    // 4. V[n,o] = sum_d xh[n,d]*Wv[o,d]         (1-term, single-h out)
    gemm_tc<1,2><<<gP, 256, SM1>>>(xh, nullptr, Wvh, nullptr, nullptr, Vh, nullptr, DD, DD, 1.0f);

    // 5. banded logits = QS * Z·x^T  (2-term; also zeroes out-of-band att)
    band_tc<<<dim3(5, NN / 128, BB), 256, SM2>>>(Zh, Zl, xh, att_out);

    // 6. softmax + P emit (no zeroing)
    band_softmax<<<BB * NN, 128>>>(att_out, Ph);

    // 7. Y = P^T @ V (banded, 1-term)
    ptv_tc<<<dim3(DD / 128, NN / 128, BB), 256, SM1>>>(Ph, Vh, Yh);

    // 8. y = Y @ Wo^T                           (1-term, fp32 out)
    gemm_tc<1,0><<<gP, 256, SM1>>>(Yh, nullptr, Woh, nullptr, y_out, nullptr, nullptr, DD, DD, 1.0f);
}

// round 11
// speedup vs baseline: 6.7232x; 1.1211x over previous
#include <cuda_runtime.h>
#include <cuda_fp16.h>
#include <cstdint>

#define BB   4
#define NN   4096
#define DD   1024
#define AP   256
#define QS   0.06f

#define NSTAGE 3
#define ST_OF(T) ((T)==3 ? 32768u : (T)==2 ? 24576u : 16384u)
#define SM3    (NSTAGE*32768)
#define SM2    (NSTAGE*24576)
#define SM1    (NSTAGE*16384)

// ---------------------------------------------------------------------------
// device scratch (allocation-free rule)
// ---------------------------------------------------------------------------
__device__ __align__(16) __half g_xh[BB*NN*DD], g_xl[BB*NN*DD];
__device__ __align__(16) __half g_WkTh[DD*DD], g_WkTl[DD*DD];
__device__ __align__(16) __half g_WqTh[DD*DD], g_WqTl[DD*DD];
__device__ __align__(16) __half g_WvTh[DD*DD], g_WvTl[DD*DD];
__device__ __align__(16) __half g_Woh[DD*DD], g_Wol[DD*DD];
__device__ __align__(16) __half g_Gh[DD*DD];
__device__ __align__(16) __half g_W2h[DD*DD];
__device__ __align__(16) __half g_Zh[BB*NN*DD], g_Zl[BB*NN*DD];
__device__ __align__(16) __half g_Uh[BB*NN*DD];
__device__ __align__(16) __half g_Ph[(size_t)BB*NN*NN];

// ---------------------------------------------------------------------------
// PTX helpers — baseline (non-arch-specific) instructions only
// ---------------------------------------------------------------------------
__device__ __forceinline__ uint32_t smem_u32(const void* p) {
    uint32_t a;
    asm("{ .reg .u64 t; cvta.to.shared.u64 t, %1; cvt.u32.u64 %0, t; }" : "=r"(a) : "l"(p));
    return a;
}
__device__ __forceinline__ void cp16(uint32_t s, const void* g) {
    asm volatile("cp.async.cg.shared.global [%0], [%1], 16;" :: "r"(s), "l"(g));
}
__device__ __forceinline__ void ldsm4(uint32_t* r, uint32_t a) {
    asm volatile("ldmatrix.sync.aligned.m8n8.x4.shared.b16 {%0,%1,%2,%3}, [%4];"
        : "=r"(r[0]), "=r"(r[1]), "=r"(r[2]), "=r"(r[3]) : "r"(a));
}
__device__ __forceinline__ void ldsm4t(uint32_t* r, uint32_t a) {
    asm volatile("ldmatrix.sync.aligned.m8n8.x4.trans.shared.b16 {%0,%1,%2,%3}, [%4];"
        : "=r"(r[0]), "=r"(r[1]), "=r"(r[2]), "=r"(r[3]) : "r"(a));
}
__device__ __forceinline__ void mmah(float* d, const uint32_t* a, const uint32_t* b) {
    asm volatile("mma.sync.aligned.m16n8k16.row.col.f32.f16.f16.f32 "
        "{%0,%1,%2,%3}, {%4,%5,%6,%7}, {%8,%9}, {%0,%1,%2,%3};"
        : "+f"(d[0]), "+f"(d[1]), "+f"(d[2]), "+f"(d[3])
        : "r"(a[0]), "r"(a[1]), "r"(a[2]), "r"(a[3]), "r"(b[0]), "r"(b[1]));
}
#define SW64(off)  ((off) ^ (((off) >> 3) & 0x30))
#define SW256(off) ((off) ^ (((off) >> 4) & 0x70))

// ===========================================================================
// dense NT GEMM pipeline (fp16 split; 64B smem rows, K-chunks of 32)
// TERMS==3: Ah·Bh + Al·Bh + Ah·Bl  | TERMS==2: Ah·Bh + Al·Bh | TERMS==1: Ah·Bh
// ===========================================================================
template<int TERMS>
__device__ __forceinline__ void issue_chunk(
    uint32_t sbase, int tid,
    const __half* pAh, const __half* pAl, const __half* pBh, const __half* pBl,
    int Kd, int k0)
{
    const uint32_t BOFF = (TERMS >= 2) ? 16384u : 8192u;
#pragma unroll
    for (int j = 0; j < 2; j++) {
        int e = tid + (j << 8);
        int r = e >> 2, c = e & 3;
        uint32_t sw = SW64((uint32_t)(r << 6) + (c << 4));
        size_t g = (size_t)r * Kd + k0 + (c << 3);
        cp16(sbase + sw, pAh + g);
        if (TERMS >= 2) cp16(sbase + 8192u + sw, pAl + g);
        cp16(sbase + BOFF + sw, pBh + g);
        if (TERMS == 3) cp16(sbase + 24576u + sw, pBl + g);
    }
    asm volatile("cp.async.commit_group;" ::: "memory");
}

template<int TERMS>
__device__ __forceinline__ void compute_chunk(
    float acc[4][4][4], uint32_t sb, int lane, int warp_m, int warp_n)
{
    const uint32_t BOFF = (TERMS >= 2) ? 16384u : 8192u;
#pragma unroll
    for (int ks = 0; ks < 2; ks++) {
        uint32_t ah[4][4], al[4][4], bh[4][2], bl[4][2];
#pragma unroll
        for (int mi = 0; mi < 4; mi++) {
            int row = warp_m*64 + mi*16 + ((lane >> 3) & 1)*8 + (lane & 7);
            int kb  = ks*32 + (lane >> 4)*16;
            uint32_t a = sb + SW64((uint32_t)(row << 6) + kb);
            ldsm4(ah[mi], a);
            if (TERMS >= 2) ldsm4(al[mi], a + 8192u);
        }
#pragma unroll
        for (int nj = 0; nj < 2; nj++) {
            int nr = warp_n*32 + nj*16 + (lane >> 4)*8 + (lane & 7);
            int kb = ks*32 + ((lane >> 3) & 1)*16;
            uint32_t a = sb + BOFF + SW64((uint32_t)(nr << 6) + kb);
            uint32_t t[4];
            ldsm4(t, a);
            bh[nj*2][0] = t[0]; bh[nj*2][1] = t[1];
            bh[nj*2+1][0] = t[2]; bh[nj*2+1][1] = t[3];
            if (TERMS == 3) {
                ldsm4(t, a + 8192u);
                bl[nj*2][0] = t[0]; bl[nj*2][1] = t[1];
                bl[nj*2+1][0] = t[2]; bl[nj*2+1][1] = t[3];
            }
        }
#pragma unroll
        for (int mi = 0; mi < 4; mi++)
#pragma unroll
            for (int ni = 0; ni < 4; ni++) {
                mmah(acc[mi][ni], ah[mi], bh[ni]);
                if (TERMS >= 2) mmah(acc[mi][ni], al[mi], bh[ni]);
                if (TERMS == 3) mmah(acc[mi][ni], ah[mi], bl[ni]);
            }
    }
}

template<int TERMS>
__device__ __forceinline__ void hmma_loop(
    float acc[4][4][4], char* smem, int tid,
    const __half* pAh, const __half* pAl,
    const __half* pBh, const __half* pBl, int Kd)
{
    const int lane = tid & 31, wid = tid >> 5;
    const int warp_m = wid >> 2, warp_n = wid & 3;
    const uint32_t STG = ST_OF(TERMS);
    uint32_t sb0 = smem_u32(smem);
    const int KC = Kd >> 5;

    issue_chunk<TERMS>(sb0,       tid, pAh, pAl, pBh, pBl, Kd, 0);
    issue_chunk<TERMS>(sb0 + STG, tid, pAh, pAl, pBh, pBl, Kd, 32);

    for (int i = 0; i < KC; i++) {
        if (i + 2 < KC) {
            issue_chunk<TERMS>(sb0 + ((i + 2) % NSTAGE)*STG, tid,
                               pAh, pAl, pBh, pBl, Kd, (i + 2) << 5);
            asm volatile("cp.async.wait_group 2;" ::: "memory");
        } else {
            asm volatile("cp.async.wait_group 0;" ::: "memory");
        }
        __syncthreads();
        compute_chunk<TERMS>(acc, sb0 + (i % NSTAGE)*STG, lane, warp_m, warp_n);
        __syncthreads();
    }
}

// ---------------------------------------------------------------------------
// NT GEMM: C = scale*(A@B^T). MODE 0: fp32 out; 1: split h/l; 2: single h
// ---------------------------------------------------------------------------
template<int TERMS, int MODE>
__global__ void __launch_bounds__(256, 1) gemm_tc(
    const __half* __restrict__ Ah, const __half* __restrict__ Al,
    const __half* __restrict__ Bh, const __half* __restrict__ Bl,
    float* __restrict__ Cf, __half* __restrict__ Ch, __half* __restrict__ Cl,
    int Kd, int Cstride, float scale)
{
    extern __shared__ char smem[];
    const int tid = threadIdx.x, lane = tid & 31, wid = tid >> 5;
    const int warp_m = wid >> 2, warp_n = wid & 3;
    const int row0 = blockIdx.y << 7, col0 = blockIdx.x << 7;

    float acc[4][4][4] = {};
    hmma_loop<TERMS>(acc, smem, tid,
                     Ah + (size_t)row0 * Kd,
                     (TERMS >= 2) ? Al + (size_t)row0 * Kd : Ah,
                     Bh + (size_t)col0 * Kd,
                     (TERMS == 3) ? Bl + (size_t)col0 * Kd : Bh, Kd);

    const int rb = row0 + warp_m*64 + (lane >> 2);
    const int cb = col0 + warp_n*32 + (lane & 3)*2;
#pragma unroll
    for (int mi = 0; mi < 4; mi++)
#pragma unroll
        for (int ni = 0; ni < 4; ni++)
#pragma unroll
            for (int h = 0; h < 2; h++) {
                int r = rb + mi*16 + 8*h;
                int c = cb + ni*8;
                float v0 = acc[mi][ni][2*h + 0] * scale;
                float v1 = acc[mi][ni][2*h + 1] * scale;
                if (MODE == 0) {
                    *(float2*)&Cf[(size_t)r * Cstride + c] = make_float2(v0, v1);
                } else if (MODE == 1) {
                    __half h0 = __float2half(v0), h1 = __float2half(v1);
                    __half l0 = __float2half(v0 - __half2float(h0));
                    __half l1 = __float2half(v1 - __half2float(h1));
                    size_t o = (size_t)r * Cstride + c;
                    *(__half2*)&Ch[o] = __halves2half2(h0, h1);
                    *(__half2*)&Cl[o] = __halves2half2(l0, l1);
                } else {
                    size_t o = (size_t)r * Cstride + c;
                    *(__half2*)&Ch[o] = __halves2half2(__float2half(v0), __float2half(v1));
                }
            }
}

// ---------------------------------------------------------------------------
// banded logits: att[b,n,m] = QS * Z[b,n]·x[b,m], |n-m| < AP  (2-term over Z)
// Writes 0 to in-window out-of-band cells; jt==it block also zeroes the
// out-of-window columns of its 128-row strip.
// ---------------------------------------------------------------------------
__global__ void __launch_bounds__(256, 1) band_tc(
    const __half* __restrict__ Zh, const __half* __restrict__ Zl,
    const __half* __restrict__ xh,
    float* __restrict__ att)
{
    const int it = blockIdx.y;
    const int jt = it + (int)blockIdx.x - 2;
    const int bz = blockIdx.z;
    const int tid = threadIdx.x;
    float* attb = att + ((size_t)bz << 24);
    const int row0 = it << 7;

    if (blockIdx.x == 2) {
        int lo_t = it - 2; if (lo_t < 0) lo_t = 0;
        int hi_t = it + 2; if (hi_t > 31) hi_t = 31;
        const int cL4 = (lo_t << 7) >> 2;
        const int cR0 = ((hi_t + 1) << 7) >> 2;
        float4 z4 = make_float4(0.f, 0.f, 0.f, 0.f);
        const int lane = tid & 31, w = tid >> 5;
        for (int r = w; r < 128; r += 8) {
            float4* rp = (float4*)(attb + (size_t)(row0 + r) * NN);
            for (int c = lane; c < cL4; c += 32) rp[c] = z4;
            for (int c = cR0 + lane; c < (NN >> 2); c += 32) rp[c] = z4;
        }
    }
    if (jt < 0 || jt >= (NN >> 7)) return;

    extern __shared__ char smem[];
    const int lane = tid & 31, wid = tid >> 5;
    const int warp_m = wid >> 2, warp_n = wid & 3;
    const int col0 = jt << 7;
    const size_t boff = (size_t)bz << 22;

    float acc[4][4][4] = {};
    hmma_loop<2>(acc, smem, tid,
                 Zh + boff + (size_t)row0 * DD, Zl + boff + (size_t)row0 * DD,
                 xh + boff + (size_t)col0 * DD, nullptr, DD);

    const int rb = row0 + warp_m*64 + (lane >> 2);
    const int cb = col0 + warp_n*32 + (lane & 3)*2;
#pragma unroll
    for (int mi = 0; mi < 4; mi++)
#pragma unroll
        for (int ni = 0; ni < 4; ni++)
#pragma unroll
            for (int h = 0; h < 2; h++) {
                int gi = rb + mi*16 + 8*h;
                int gj = cb + ni*8;
                int d0 = gi - gj, d1 = gi - gj - 1;
                float w0 = (d0 > -AP && d0 < AP) ? acc[mi][ni][2*h + 0] * QS : 0.f;
                float w1 = (d1 > -AP && d1 < AP) ? acc[mi][ni][2*h + 1] * QS : 0.f;
                *(float2*)&attb[(size_t)gi * NN + gj] = make_float2(w0, w1);
            }
}

// ---------------------------------------------------------------------------
// splits & transpose
// ---------------------------------------------------------------------------
__global__ void split2(const float* __restrict__ in,
                       __half* __restrict__ h, __half* __restrict__ l, int n2)
{
    int i = blockIdx.x * blockDim.x + threadIdx.x;
    int st = gridDim.x * blockDim.x;
    for (; i < n2; i += st) {
        float2 v = ((const float2*)in)[i];
        __half hx = __float2half(v.x), hy = __float2half(v.y);
        ((__half2*)h)[i] = __halves2half2(hx, hy);
        ((__half2*)l)[i] = __halves2half2(__float2half(v.x - __half2float(hx)),
                                          __float2half(v.y - __half2float(hy)));
    }
}
__global__ void transpose_split(const float* __restrict__ in,
                                __half* __restrict__ th, __half* __restrict__ tl)
{
    __shared__ float t[32][33];
    int bx = blockIdx.x << 5, by = blockIdx.y << 5;
#pragma unroll
    for (int k = 0; k < 32; k += 8)
        t[threadIdx.y + k][threadIdx.x] = in[(size_t)(by + threadIdx.y + k) * DD + bx + threadIdx.x];
    __syncthreads();
#pragma unroll
    for (int k = 0; k < 32; k += 8) {
        int r = bx + threadIdx.y + k, c = by + threadIdx.x;
        float v = t[threadIdx.x][threadIdx.y + k];
        __half h = __float2half(v);
        th[(size_t)r * DD + c] = h;
        tl[(size_t)r * DD + c] = __float2half(v - __half2float(h));
    }
}

// ---------------------------------------------------------------------------
// band softmax + fp16 P emit over padded window
// ---------------------------------------------------------------------------
__global__ void __launch_bounds__(128) band_softmax(
    float* __restrict__ att, __half* __restrict__ Ph)
{
    __shared__ float red[4];
    const int gid = blockIdx.x;
    const int b = gid >> 12;
    const int i = gid & (NN - 1);
    const size_t rowbase = ((size_t)b << 24) + ((size_t)i << 12);
    float* row = att + rowbase;
    int jlo = i - (AP - 1); if (jlo < 0) jlo = 0;
    int jhi = i + (AP - 1); if (jhi > NN - 1) jhi = NN - 1;
    const int cnt = jhi - jlo + 1;

    float v[4];
    int nc = 0;
    float m = -1e30f;
    for (int t = threadIdx.x; t < cnt; t += 128) { v[nc] = row[jlo + t]; m = fmaxf(m, v[nc]); nc++; }
    for (int o = 16; o > 0; o >>= 1) m = fmaxf(m, __shfl_xor_sync(0xffffffffu, m, o));
    const int w = threadIdx.x >> 5;
    if ((threadIdx.x & 31) == 0) red[w] = m;
    __syncthreads();
    m = fmaxf(fmaxf(red[0], red[1]), fmaxf(red[2], red[3]));
    __syncthreads();

    float s = 0.f;
    for (int c = 0; c < nc; c++) { v[c] = __expf(v[c] - m); s += v[c]; }
    for (int o = 16; o > 0; o >>= 1) s += __shfl_xor_sync(0xffffffffu, s, o);
    if ((threadIdx.x & 31) == 0) red[w] = s;
    __syncthreads();
    s = red[0] + red[1] + red[2] + red[3];
    const float inv = 1.0f / s;

    nc = 0;
    for (int t = threadIdx.x; t < cnt; t += 128) { row[jlo + t] = v[nc] * inv; nc++; }
    __syncthreads();

    int wlo = i - 256; wlo &= ~127; if (wlo < 0) wlo = 0;
    int whi = (i + 384) & ~127; if (whi > NN) whi = NN;
    for (int n = wlo + threadIdx.x; n < whi; n += 128) {
        float f = (n >= jlo && n <= jhi) ? row[n] : 0.f;
        Ph[rowbase + n] = __float2half(f);
    }
}

// ===========================================================================
// ptv: y[b,n,i] = sum_m P[b,m,n] * U[b,m,i]   (banded, 1-term, trans-ldsm)
// writes final fp32 y directly
// ===========================================================================
__device__ __forceinline__ void ptv_issue(
    uint32_t sbase, int tid,
    const __half* Phg, const __half* Uhg, int m0, int n0, int o0)
{
#pragma unroll
    for (int j = 0; j < 2; j++) {
        int e = tid + (j << 8);
        int r = e >> 4, c16 = e & 15;
        uint32_t sw = SW256((uint32_t)(r << 8) + (c16 << 4));
        cp16(sbase +         sw, Phg + (size_t)(m0 + r) * NN + n0 + (c16 << 3));
        cp16(sbase + 8192u + sw, Uhg + (size_t)(m0 + r) * DD + o0 + (c16 << 3));
    }
    asm volatile("cp.async.commit_group;" ::: "memory");
}

__device__ __forceinline__ void ptv_compute(
    float acc[4][4][4], uint32_t sb, int lane, int warp_m, int warp_n)
{
#pragma unroll
    for (int ks = 0; ks < 2; ks++) {
        const int m16 = ks << 4;
        uint32_t ah[4][4], bh[4][2];
        const int ar = m16 + ((lane >> 4) << 3) + (lane & 7);
        const int acsel = ((lane >> 3) & 1) << 3;
#pragma unroll
        for (int mi = 0; mi < 4; mi++) {
            int nb = warp_m*64 + mi*16 + acsel;
            ldsm4t(ah[mi], sb + SW256((uint32_t)(ar << 8) + (nb << 1)));
        }
        const int br = m16 + (((lane >> 3) & 1) << 3) + (lane & 7);
        const int bcsel = (lane >> 4) << 3;
#pragma unroll
        for (int jb = 0; jb < 2; jb++) {
            int ob = warp_n*32 + jb*16 + bcsel;
            uint32_t t4[4];
            ldsm4t(t4, sb + 8192u + SW256((uint32_t)(br << 8) + (ob << 1)));
            bh[jb*2][0] = t4[0]; bh[jb*2][1] = t4[1];
            bh[jb*2+1][0] = t4[2]; bh[jb*2+1][1] = t4[3];
        }
#pragma unroll
        for (int mi = 0; mi < 4; mi++)
#pragma unroll
            for (int ni = 0; ni < 4; ni++)
                mmah(acc[mi][ni], ah[mi], bh[ni]);
    }
}

__global__ void __launch_bounds__(256, 1) ptv_tc(
    const __half* __restrict__ Phg, const __half* __restrict__ Uhg,
    float* __restrict__ yout)
{
    const int bz = blockIdx.z;
    const int n0 = blockIdx.y << 7;
    const int o0 = blockIdx.x << 7;
    const __half* Pb = Phg + ((size_t)bz << 24);
    const __half* Ub = Uhg + ((size_t)bz << 22);

    extern __shared__ char smem[];
    uint32_t sb0 = smem_u32(smem);
    const int tid = threadIdx.x, lane = tid & 31, wid = tid >> 5;
    const int warp_m = wid >> 2, warp_n = wid & 3;

    int mlo = n0 - 256; if (mlo < 0) mlo = 0;
    int mhe = n0 + 384; if (mhe > NN) mhe = NN;
    const int NC = (mhe - mlo) >> 5;

    float acc[4][4][4] = {};

    ptv_issue(sb0,          tid, Pb, Ub, mlo,      n0, o0);
    ptv_issue(sb0 + 16384u, tid, Pb, Ub, mlo + 32, n0, o0);

    for (int i = 0; i < NC; i++) {
        if (i + 2 < NC) {
            ptv_issue(sb0 + ((i + 2) % NSTAGE)*16384u, tid,
                      Pb, Ub, mlo + ((i + 2) << 5), n0, o0);
            asm volatile("cp.async.wait_group 2;" ::: "memory");
        } else {
            asm volatile("cp.async.wait_group 0;" ::: "memory");
        }
        __syncthreads();
        ptv_compute(acc, sb0 + (i % NSTAGE)*16384u, lane, warp_m, warp_n);
        __syncthreads();
    }

    float* yb = yout + ((size_t)bz << 22);
    const int rb = n0 + warp_m*64 + (lane >> 2);
    const int cb = o0 + warp_n*32 + (lane & 3)*2;
#pragma unroll
    for (int mi = 0; mi < 4; mi++)
#pragma unroll
        for (int ni = 0; ni < 4; ni++)
#pragma unroll
            for (int h = 0; h < 2; h++) {
                size_t off = (size_t)(rb + mi*16 + 8*h) * DD + cb + ni*8;
                *(float2*)&yb[off] = make_float2(acc[mi][ni][2*h + 0],
                                                 acc[mi][ni][2*h + 1]);
            }
}

// ---------------------------------------------------------------------------
extern "C" void kernel_launch(void* const* d_in, const int* in_sizes, int n_in,
                              void* d_out, int out_size)
{
    const float* x  = (const float*)d_in[0];
    const float* Wk = (const float*)d_in[1];
    const float* Wq = (const float*)d_in[2];
    const float* Wv = (const float*)d_in[3];
    const float* Wo = (const float*)d_in[4];

    float* y_out   = (float*)d_out;
    float* att_out = y_out + (size_t)BB * NN * DD;

    __half *xh, *xl, *WkTh, *WkTl, *WqTh, *WqTl, *WvTh, *WvTl, *Woh, *Wol;
    __half *Gh, *W2h, *Zh, *Zl, *Uh, *Ph;
    cudaGetSymbolAddress((void**)&xh,   g_xh);   cudaGetSymbolAddress((void**)&xl,   g_xl);
    cudaGetSymbolAddress((void**)&WkTh, g_WkTh); cudaGetSymbolAddress((void**)&WkTl, g_WkTl);
    cudaGetSymbolAddress((void**)&WqTh, g_WqTh); cudaGetSymbolAddress((void**)&WqTl, g_WqTl);
    cudaGetSymbolAddress((void**)&WvTh, g_WvTh); cudaGetSymbolAddress((void**)&WvTl, g_WvTl);
    cudaGetSymbolAddress((void**)&Woh,  g_Woh);  cudaGetSymbolAddress((void**)&Wol,  g_Wol);
    cudaGetSymbolAddress((void**)&Gh,   g_Gh);   cudaGetSymbolAddress((void**)&W2h,  g_W2h);
    cudaGetSymbolAddress((void**)&Zh,   g_Zh);   cudaGetSymbolAddress((void**)&Zl,   g_Zl);
    cudaGetSymbolAddress((void**)&Uh,   g_Uh);   cudaGetSymbolAddress((void**)&Ph,   g_Ph);

    cudaFuncSetAttribute((const void*)gemm_tc<3,2>, cudaFuncAttributeMaxDynamicSharedMemorySize, SM3);
    cudaFuncSetAttribute((const void*)gemm_tc<2,1>, cudaFuncAttributeMaxDynamicSharedMemorySize, SM2);
    cudaFuncSetAttribute((const void*)gemm_tc<1,2>, cudaFuncAttributeMaxDynamicSharedMemorySize, SM1);
    cudaFuncSetAttribute((const void*)band_tc,      cudaFuncAttributeMaxDynamicSharedMemorySize, SM2);
    cudaFuncSetAttribute((const void*)ptv_tc,       cudaFuncAttributeMaxDynamicSharedMemorySize, SM1);

    // 1. operand prep
    split2<<<4096, 256>>>(x, xh, xl, (BB * NN * DD) / 2);
    transpose_split<<<dim3(32, 32), dim3(32, 8)>>>(Wk, WkTh, WkTl);
    transpose_split<<<dim3(32, 32), dim3(32, 8)>>>(Wq, WqTh, WqTl);
    transpose_split<<<dim3(32, 32), dim3(32, 8)>>>(Wv, WvTh, WvTl);
    split2<<<512, 256>>>(Wo, Woh, Wol, (DD * DD) / 2);

    // 2. G[d2,d1]  = sum_o WkT[d2,o]*WqT[d1,o]     (3-term, high-only)
    gemm_tc<3,2><<<dim3(8, 8), 256, SM3>>>(WkTh, WkTl, WqTh, WqTl,
                                           nullptr, Gh, nullptr, DD, DD, 1.0f);
    //    W2[i,d]  = sum_o Wo[i,o]*WvT[d,o]         (3-term, high-only)
    gemm_tc<3,2><<<dim3(8, 8), 256, SM3>>>(Woh, Wol, WvTh, WvTl,
                                           nullptr, W2h, nullptr, DD, DD, 1.0f);

    // 3. Z[n,d2] = sum_d1 x[n,d1]*G[d2,d1]         (2-term, split out)
    dim3 gP(DD / 128, (BB * NN) / 128);
    gemm_tc<2,1><<<gP, 256, SM2>>>(xh, xl, Gh, nullptr, nullptr, Zh, Zl, DD, DD, 1.0f);

    // 4. U[n,i] = sum_d xh[n,d]*W2[i,d]            (1-term, single-h out)
    gemm_tc<1,2><<<gP, 256, SM1>>>(xh, nullptr, W2h, nullptr, nullptr, Uh, nullptr, DD, DD, 1.0f);

    // 5. banded logits = QS * Z·x^T  (2-term; zeroes out-of-band att)
    band_tc<<<dim3(5, NN / 128, BB), 256, SM2>>>(Zh, Zl, xh, att_out);

    // 6. softmax + P emit
    band_softmax<<<BB * NN, 128>>>(att_out, Ph);

    // 7. y = P^T @ U (banded, 1-term, fp32 out — final)
    ptv_tc<<<dim3(DD / 128, NN / 128, BB), 256, SM1>>>(Ph, Uh, y_out);
}

// round 12
// speedup vs baseline: 7.3680x; 1.0959x over previous
#include <cuda_runtime.h>
#include <cuda_fp16.h>
#include <cstdint>

#define BB   4
#define NN   4096
#define DD   1024
#define AP   256
#define QS   0.06f

#define NSTAGE 3
#define ST_OF(T) ((T)==3 ? 32768u : (T)==2 ? 24576u : 16384u)
#define SM3    (NSTAGE*32768)
#define SM2    (NSTAGE*24576)
#define SM1    (NSTAGE*16384)

// ---------------------------------------------------------------------------
// device scratch (allocation-free rule)
// ---------------------------------------------------------------------------
__device__ __align__(16) __half g_xh[BB*NN*DD], g_xl[BB*NN*DD];
__device__ __align__(16) __half g_WkTh[DD*DD], g_WkTl[DD*DD];
__device__ __align__(16) __half g_WqTh[DD*DD], g_WqTl[DD*DD];
__device__ __align__(16) __half g_WvTh[DD*DD], g_WvTl[DD*DD];
__device__ __align__(16) __half g_Woh[DD*DD], g_Wol[DD*DD];
__device__ __align__(16) __half g_Gh[DD*DD];
__device__ __align__(16) __half g_W2h[DD*DD];
__device__ __align__(16) __half g_Zh[BB*NN*DD];
__device__ __align__(16) __half g_Uh[BB*NN*DD];
__device__ __align__(16) __half g_Ph[(size_t)BB*NN*NN];

// ---------------------------------------------------------------------------
// PTX helpers — baseline (non-arch-specific) instructions only
// ---------------------------------------------------------------------------
__device__ __forceinline__ uint32_t smem_u32(const void* p) {
    uint32_t a;
    asm("{ .reg .u64 t; cvta.to.shared.u64 t, %1; cvt.u32.u64 %0, t; }" : "=r"(a) : "l"(p));
    return a;
}
__device__ __forceinline__ void cp16(uint32_t s, const void* g) {
    asm volatile("cp.async.cg.shared.global [%0], [%1], 16;" :: "r"(s), "l"(g));
}
__device__ __forceinline__ void ldsm4(uint32_t* r, uint32_t a) {
    asm volatile("ldmatrix.sync.aligned.m8n8.x4.shared.b16 {%0,%1,%2,%3}, [%4];"
        : "=r"(r[0]), "=r"(r[1]), "=r"(r[2]), "=r"(r[3]) : "r"(a));
}
__device__ __forceinline__ void ldsm4t(uint32_t* r, uint32_t a) {
    asm volatile("ldmatrix.sync.aligned.m8n8.x4.trans.shared.b16 {%0,%1,%2,%3}, [%4];"
        : "=r"(r[0]), "=r"(r[1]), "=r"(r[2]), "=r"(r[3]) : "r"(a));
}
__device__ __forceinline__ void mmah(float* d, const uint32_t* a, const uint32_t* b) {
    asm volatile("mma.sync.aligned.m16n8k16.row.col.f32.f16.f16.f32 "
        "{%0,%1,%2,%3}, {%4,%5,%6,%7}, {%8,%9}, {%0,%1,%2,%3};"
        : "+f"(d[0]), "+f"(d[1]), "+f"(d[2]), "+f"(d[3])
        : "r"(a[0]), "r"(a[1]), "r"(a[2]), "r"(a[3]), "r"(b[0]), "r"(b[1]));
}
#define SW64(off)  ((off) ^ (((off) >> 3) & 0x30))
#define SW256(off) ((off) ^ (((off) >> 4) & 0x70))

// ===========================================================================
// dense NT GEMM pipeline (fp16 split; 64B smem rows, K-chunks of 32)
// TERMS==3: Ah·Bh + Al·Bh + Ah·Bl  | TERMS==2: Ah·Bh + Al·Bh | TERMS==1: Ah·Bh
// ===========================================================================
template<int TERMS>
__device__ __forceinline__ void issue_chunk(
    uint32_t sbase, int tid,
    const __half* pAh, const __half* pAl, const __half* pBh, const __half* pBl,
    int Kd, int k0)
{
    const uint32_t BOFF = (TERMS >= 2) ? 16384u : 8192u;
#pragma unroll
    for (int j = 0; j < 2; j++) {
        int e = tid + (j << 8);
        int r = e >> 2, c = e & 3;
        uint32_t sw = SW64((uint32_t)(r << 6) + (c << 4));
        size_t g = (size_t)r * Kd + k0 + (c << 3);
        cp16(sbase + sw, pAh + g);
        if (TERMS >= 2) cp16(sbase + 8192u + sw, pAl + g);
        cp16(sbase + BOFF + sw, pBh + g);
        if (TERMS == 3) cp16(sbase + 24576u + sw, pBl + g);
    }
    asm volatile("cp.async.commit_group;" ::: "memory");
}

template<int TERMS>
__device__ __forceinline__ void compute_chunk(
    float acc[4][4][4], uint32_t sb, int lane, int warp_m, int warp_n)
{
    const uint32_t BOFF = (TERMS >= 2) ? 16384u : 8192u;
#pragma unroll
    for (int ks = 0; ks < 2; ks++) {
        uint32_t ah[4][4], al[4][4], bh[4][2], bl[4][2];
#pragma unroll
        for (int mi = 0; mi < 4; mi++) {
            int row = warp_m*64 + mi*16 + ((lane >> 3) & 1)*8 + (lane & 7);
            int kb  = ks*32 + (lane >> 4)*16;
            uint32_t a = sb + SW64((uint32_t)(row << 6) + kb);
            ldsm4(ah[mi], a);
            if (TERMS >= 2) ldsm4(al[mi], a + 8192u);
        }
#pragma unroll
        for (int nj = 0; nj < 2; nj++) {
            int nr = warp_n*32 + nj*16 + (lane >> 4)*8 + (lane & 7);
            int kb = ks*32 + ((lane >> 3) & 1)*16;
            uint32_t a = sb + BOFF + SW64((uint32_t)(nr << 6) + kb);
            uint32_t t[4];
            ldsm4(t, a);
            bh[nj*2][0] = t[0]; bh[nj*2][1] = t[1];
            bh[nj*2+1][0] = t[2]; bh[nj*2+1][1] = t[3];
            if (TERMS == 3) {
                ldsm4(t, a + 8192u);
                bl[nj*2][0] = t[0]; bl[nj*2][1] = t[1];
                bl[nj*2+1][0] = t[2]; bl[nj*2+1][1] = t[3];
            }
        }
#pragma unroll
        for (int mi = 0; mi < 4; mi++)
#pragma unroll
            for (int ni = 0; ni < 4; ni++) {
                mmah(acc[mi][ni], ah[mi], bh[ni]);
                if (TERMS >= 2) mmah(acc[mi][ni], al[mi], bh[ni]);
                if (TERMS == 3) mmah(acc[mi][ni], ah[mi], bl[ni]);
            }
    }
}

template<int TERMS>
__device__ __forceinline__ void hmma_loop(
    float acc[4][4][4], char* smem, int tid,
    const __half* pAh, const __half* pAl,
    const __half* pBh, const __half* pBl, int Kd)
{
    const int lane = tid & 31, wid = tid >> 5;
    const int warp_m = wid >> 2, warp_n = wid & 3;
    const uint32_t STG = ST_OF(TERMS);
    uint32_t sb0 = smem_u32(smem);
    const int KC = Kd >> 5;

    issue_chunk<TERMS>(sb0,       tid, pAh, pAl, pBh, pBl, Kd, 0);
    issue_chunk<TERMS>(sb0 + STG, tid, pAh, pAl, pBh, pBl, Kd, 32);

    for (int i = 0; i < KC; i++) {
        if (i + 2 < KC) {
            issue_chunk<TERMS>(sb0 + ((i + 2) % NSTAGE)*STG, tid,
                               pAh, pAl, pBh, pBl, Kd, (i + 2) << 5);
            asm volatile("cp.async.wait_group 2;" ::: "memory");
        } else {
            asm volatile("cp.async.wait_group 0;" ::: "memory");
        }
        __syncthreads();
        compute_chunk<TERMS>(acc, sb0 + (i % NSTAGE)*STG, lane, warp_m, warp_n);
        __syncthreads();
    }
}

// ---------------------------------------------------------------------------
// NT GEMM: C = scale*(A@B^T). MODE 0: fp32 out; 1: split h/l; 2: single h
// ---------------------------------------------------------------------------
template<int TERMS, int MODE>
__global__ void __launch_bounds__(256, 1) gemm_tc(
    const __half* __restrict__ Ah, const __half* __restrict__ Al,
    const __half* __restrict__ Bh, const __half* __restrict__ Bl,
    float* __restrict__ Cf, __half* __restrict__ Ch, __half* __restrict__ Cl,
    int Kd, int Cstride, float scale)
{
    extern __shared__ char smem[];
    const int tid = threadIdx.x, lane = tid & 31, wid = tid >> 5;
    const int warp_m = wid >> 2, warp_n = wid & 3;
    const int row0 = blockIdx.y << 7, col0 = blockIdx.x << 7;

    float acc[4][4][4] = {};
    hmma_loop<TERMS>(acc, smem, tid,
                     Ah + (size_t)row0 * Kd,
                     (TERMS >= 2) ? Al + (size_t)row0 * Kd : Ah,
                     Bh + (size_t)col0 * Kd,
                     (TERMS == 3) ? Bl + (size_t)col0 * Kd : Bh, Kd);

    const int rb = row0 + warp_m*64 + (lane >> 2);
    const int cb = col0 + warp_n*32 + (lane & 3)*2;
#pragma unroll
    for (int mi = 0; mi < 4; mi++)
#pragma unroll
        for (int ni = 0; ni < 4; ni++)
#pragma unroll
            for (int h = 0; h < 2; h++) {
                int r = rb + mi*16 + 8*h;
                int c = cb + ni*8;
                float v0 = acc[mi][ni][2*h + 0] * scale;
                float v1 = acc[mi][ni][2*h + 1] * scale;
                if (MODE == 0) {
                    *(float2*)&Cf[(size_t)r * Cstride + c] = make_float2(v0, v1);
                } else if (MODE == 1) {
                    __half h0 = __float2half(v0), h1 = __float2half(v1);
                    __half l0 = __float2half(v0 - __half2float(h0));
                    __half l1 = __float2half(v1 - __half2float(h1));
                    size_t o = (size_t)r * Cstride + c;
                    *(__half2*)&Ch[o] = __halves2half2(h0, h1);
                    *(__half2*)&Cl[o] = __halves2half2(l0, l1);
                } else {
                    size_t o = (size_t)r * Cstride + c;
                    *(__half2*)&Ch[o] = __halves2half2(__float2half(v0), __float2half(v1));
                }
            }
}

// ---------------------------------------------------------------------------
// banded logits: att[b,n,m] = QS * Zh[b,n]·xh[b,m], |n-m| < AP  (1-term)
// All 5 blocks of a strip share the zeroing of out-of-window columns
// (rows round-robin by blockIdx.x mod 5); in-window out-of-band cells get 0
// from the epilogue.
// ---------------------------------------------------------------------------
__global__ void __launch_bounds__(256, 1) band_tc(
    const __half* __restrict__ Zh, const __half* __restrict__ xh,
    float* __restrict__ att)
{
    const int it = blockIdx.y;
    const int jt = it + (int)blockIdx.x - 2;
    const int bz = blockIdx.z;
    const int tid = threadIdx.x;
    float* attb = att + ((size_t)bz << 24);
    const int row0 = it << 7;
    const int lane = tid & 31, wid = tid >> 5;

    // distributed zeroing of out-of-window columns (all 5 blocks)
    {
        int lo_t = it - 2; if (lo_t < 0) lo_t = 0;
        int hi_t = it + 2; if (hi_t > 31) hi_t = 31;
        const int cL4 = lo_t << 5;          // left region f4 count
        const int cR0 = (hi_t + 1) << 5;    // right region f4 start
        float4 z4 = make_float4(0.f, 0.f, 0.f, 0.f);
        for (int j = wid; ; j += 8) {
            int r = (int)blockIdx.x + 5 * j;
            if (r >= 128) break;
            float4* rp = (float4*)(attb + (size_t)(row0 + r) * NN);
            for (int c = lane; c < cL4; c += 32) rp[c] = z4;
            for (int c = cR0 + lane; c < (NN >> 2); c += 32) rp[c] = z4;
        }
    }
    if (jt < 0 || jt >= (NN >> 7)) return;

    extern __shared__ char smem[];
    const int warp_m = wid >> 2, warp_n = wid & 3;
    const int col0 = jt << 7;
    const size_t boff = (size_t)bz << 22;

    float acc[4][4][4] = {};
    hmma_loop<1>(acc, smem, tid,
                 Zh + boff + (size_t)row0 * DD, nullptr,
                 xh + boff + (size_t)col0 * DD, nullptr, DD);

    const int rb = row0 + warp_m*64 + (lane >> 2);
    const int cb = col0 + warp_n*32 + (lane & 3)*2;
#pragma unroll
    for (int mi = 0; mi < 4; mi++)
#pragma unroll
        for (int ni = 0; ni < 4; ni++)
#pragma unroll
            for (int h = 0; h < 2; h++) {
                int gi = rb + mi*16 + 8*h;
                int gj = cb + ni*8;
                int d0 = gi - gj, d1 = gi - gj - 1;
                float w0 = (d0 > -AP && d0 < AP) ? acc[mi][ni][2*h + 0] * QS : 0.f;
                float w1 = (d1 > -AP && d1 < AP) ? acc[mi][ni][2*h + 1] * QS : 0.f;
                *(float2*)&attb[(size_t)gi * NN + gj] = make_float2(w0, w1);
            }
}

// ---------------------------------------------------------------------------
// splits & batched transpose
// ---------------------------------------------------------------------------
__global__ void split2(const float* __restrict__ in,
                       __half* __restrict__ h, __half* __restrict__ l, int n2)
{
    int i = blockIdx.x * blockDim.x + threadIdx.x;
    int st = gridDim.x * blockDim.x;
    for (; i < n2; i += st) {
        float2 v = ((const float2*)in)[i];
        __half hx = __float2half(v.x), hy = __float2half(v.y);
        ((__half2*)h)[i] = __halves2half2(hx, hy);
        ((__half2*)l)[i] = __halves2half2(__float2half(v.x - __half2float(hx)),
                                          __float2half(v.y - __half2float(hy)));
    }
}
// z = 0: Wk, 1: Wq, 2: Wv
__global__ void transpose_split3(
    const float* __restrict__ w0, __half* __restrict__ t0h, __half* __restrict__ t0l,
    const float* __restrict__ w1, __half* __restrict__ t1h, __half* __restrict__ t1l,
    const float* __restrict__ w2, __half* __restrict__ t2h, __half* __restrict__ t2l)
{
    const float* in = (blockIdx.z == 0) ? w0 : (blockIdx.z == 1) ? w1 : w2;
    __half* th = (blockIdx.z == 0) ? t0h : (blockIdx.z == 1) ? t1h : t2h;
    __half* tl = (blockIdx.z == 0) ? t0l : (blockIdx.z == 1) ? t1l : t2l;
    __shared__ float t[32][33];
    int bx = blockIdx.x << 5, by = blockIdx.y << 5;
#pragma unroll
    for (int k = 0; k < 32; k += 8)
        t[threadIdx.y + k][threadIdx.x] = in[(size_t)(by + threadIdx.y + k) * DD + bx + threadIdx.x];
    __syncthreads();
#pragma unroll
    for (int k = 0; k < 32; k += 8) {
        int r = bx + threadIdx.y + k, c = by + threadIdx.x;
        float v = t[threadIdx.x][threadIdx.y + k];
        __half h = __float2half(v);
        th[(size_t)r * DD + c] = h;
        tl[(size_t)r * DD + c] = __float2half(v - __half2float(h));
    }
}

// ---------------------------------------------------------------------------
// band softmax + fp16 P emit over padded window
// ---------------------------------------------------------------------------
__global__ void __launch_bounds__(128) band_softmax(
    float* __restrict__ att, __half* __restrict__ Ph)
{
    __shared__ float red[4];
    const int gid = blockIdx.x;
    const int b = gid >> 12;
    const int i = gid & (NN - 1);
    const size_t rowbase = ((size_t)b << 24) + ((size_t)i << 12);
    float* row = att + rowbase;
    int jlo = i - (AP - 1); if (jlo < 0) jlo = 0;
    int jhi = i + (AP - 1); if (jhi > NN - 1) jhi = NN - 1;
    const int cnt = jhi - jlo + 1;

    float v[4];
    int nc = 0;
    float m = -1e30f;
    for (int t = threadIdx.x; t < cnt; t += 128) { v[nc] = row[jlo + t]; m = fmaxf(m, v[nc]); nc++; }
    for (int o = 16; o > 0; o >>= 1) m = fmaxf(m, __shfl_xor_sync(0xffffffffu, m, o));
    const int w = threadIdx.x >> 5;
    if ((threadIdx.x & 31) == 0) red[w] = m;
    __syncthreads();
    m = fmaxf(fmaxf(red[0], red[1]), fmaxf(red[2], red[3]));
    __syncthreads();

    float s = 0.f;
    for (int c = 0; c < nc; c++) { v[c] = __expf(v[c] - m); s += v[c]; }
    for (int o = 16; o > 0; o >>= 1) s += __shfl_xor_sync(0xffffffffu, s, o);
    if ((threadIdx.x & 31) == 0) red[w] = s;
    __syncthreads();
    s = red[0] + red[1] + red[2] + red[3];
    const float inv = 1.0f / s;

    nc = 0;
    for (int t = threadIdx.x; t < cnt; t += 128) { row[jlo + t] = v[nc] * inv; nc++; }
    __syncthreads();

    int wlo = i - 256; wlo &= ~127; if (wlo < 0) wlo = 0;
    int whi = (i + 384) & ~127; if (whi > NN) whi = NN;
    for (int n = wlo + threadIdx.x; n < whi; n += 128) {
        float f = (n >= jlo && n <= jhi) ? row[n] : 0.f;
        Ph[rowbase + n] = __float2half(f);
    }
}

// ===========================================================================
// ptv: y[b,n,i] = sum_m P[b,m,n] * U[b,m,i]   (banded, 1-term, trans-ldsm)
// writes final fp32 y directly
// ===========================================================================
__device__ __forceinline__ void ptv_issue(
    uint32_t sbase, int tid,
    const __half* Phg, const __half* Uhg, int m0, int n0, int o0)
{
#pragma unroll
    for (int j = 0; j < 2; j++) {
        int e = tid + (j << 8);
        int r = e >> 4, c16 = e & 15;
        uint32_t sw = SW256((uint32_t)(r << 8) + (c16 << 4));
        cp16(sbase +         sw, Phg + (size_t)(m0 + r) * NN + n0 + (c16 << 3));
        cp16(sbase + 8192u + sw, Uhg + (size_t)(m0 + r) * DD + o0 + (c16 << 3));
    }
    asm volatile("cp.async.commit_group;" ::: "memory");
}

__device__ __forceinline__ void ptv_compute(
    float acc[4][4][4], uint32_t sb, int lane, int warp_m, int warp_n)
{
#pragma unroll
    for (int ks = 0; ks < 2; ks++) {
        const int m16 = ks << 4;
        uint32_t ah[4][4], bh[4][2];
        const int ar = m16 + ((lane >> 4) << 3) + (lane & 7);
        const int acsel = ((lane >> 3) & 1) << 3;
#pragma unroll
        for (int mi = 0; mi < 4; mi++) {
            int nb = warp_m*64 + mi*16 + acsel;
            ldsm4t(ah[mi], sb + SW256((uint32_t)(ar << 8) + (nb << 1)));
        }
        const int br = m16 + (((lane >> 3) & 1) << 3) + (lane & 7);
        const int bcsel = (lane >> 4) << 3;
#pragma unroll
        for (int jb = 0; jb < 2; jb++) {
            int ob = warp_n*32 + jb*16 + bcsel;
            uint32_t t4[4];
            ldsm4t(t4, sb + 8192u + SW256((uint32_t)(br << 8) + (ob << 1)));
            bh[jb*2][0] = t4[0]; bh[jb*2][1] = t4[1];
            bh[jb*2+1][0] = t4[2]; bh[jb*2+1][1] = t4[3];
        }
#pragma unroll
        for (int mi = 0; mi < 4; mi++)
#pragma unroll
            for (int ni = 0; ni < 4; ni++)
                mmah(acc[mi][ni], ah[mi], bh[ni]);
    }
}

__global__ void __launch_bounds__(256, 1) ptv_tc(
    const __half* __restrict__ Phg, const __half* __restrict__ Uhg,
    float* __restrict__ yout)
{
    const int bz = blockIdx.z;
    const int n0 = blockIdx.y << 7;
    const int o0 = blockIdx.x << 7;
    const __half* Pb = Phg + ((size_t)bz << 24);
    const __half* Ub = Uhg + ((size_t)bz << 22);

    extern __shared__ char smem[];
    uint32_t sb0 = smem_u32(smem);
    const int tid = threadIdx.x, lane = tid & 31, wid = tid >> 5;
    const int warp_m = wid >> 2, warp_n = wid & 3;

    int mlo = n0 - 256; if (mlo < 0) mlo = 0;
    int mhe = n0 + 384; if (mhe > NN) mhe = NN;
    const int NC = (mhe - mlo) >> 5;

    float acc[4][4][4] = {};

    ptv_issue(sb0,          tid, Pb, Ub, mlo,      n0, o0);
    ptv_issue(sb0 + 16384u, tid, Pb, Ub, mlo + 32, n0, o0);

    for (int i = 0; i < NC; i++) {
        if (i + 2 < NC) {
            ptv_issue(sb0 + ((i + 2) % NSTAGE)*16384u, tid,
                      Pb, Ub, mlo + ((i + 2) << 5), n0, o0);
            asm volatile("cp.async.wait_group 2;" ::: "memory");
        } else {
            asm volatile("cp.async.wait_group 0;" ::: "memory");
        }
        __syncthreads();
        ptv_compute(acc, sb0 + (i % NSTAGE)*16384u, lane, warp_m, warp_n);
        __syncthreads();
    }

    float* yb = yout + ((size_t)bz << 22);
    const int rb = n0 + warp_m*64 + (lane >> 2);
    const int cb = o0 + warp_n*32 + (lane & 3)*2;
#pragma unroll
    for (int mi = 0; mi < 4; mi++)
#pragma unroll
        for (int ni = 0; ni < 4; ni++)
#pragma unroll
            for (int h = 0; h < 2; h++) {
                size_t off = (size_t)(rb + mi*16 + 8*h) * DD + cb + ni*8;
                *(float2*)&yb[off] = make_float2(acc[mi][ni][2*h + 0],
                                                 acc[mi][ni][2*h + 1]);
            }
}

// ---------------------------------------------------------------------------
extern "C" void kernel_launch(void* const* d_in, const int* in_sizes, int n_in,
                              void* d_out, int out_size)
{
    const float* x  = (const float*)d_in[0];
    const float* Wk = (const float*)d_in[1];
    const float* Wq = (const float*)d_in[2];
    const float* Wv = (const float*)d_in[3];
    const float* Wo = (const float*)d_in[4];

    float* y_out   = (float*)d_out;
    float* att_out = y_out + (size_t)BB * NN * DD;

    __half *xh, *xl, *WkTh, *WkTl, *WqTh, *WqTl, *WvTh, *WvTl, *Woh, *Wol;
    __half *Gh, *W2h, *Zh, *Uh, *Ph;
    cudaGetSymbolAddress((void**)&xh,   g_xh);   cudaGetSymbolAddress((void**)&xl,   g_xl);
    cudaGetSymbolAddress((void**)&WkTh, g_WkTh); cudaGetSymbolAddress((void**)&WkTl, g_WkTl);
    cudaGetSymbolAddress((void**)&WqTh, g_WqTh); cudaGetSymbolAddress((void**)&WqTl, g_WqTl);
    cudaGetSymbolAddress((void**)&WvTh, g_WvTh); cudaGetSymbolAddress((void**)&WvTl, g_WvTl);
    cudaGetSymbolAddress((void**)&Woh,  g_Woh);  cudaGetSymbolAddress((void**)&Wol,  g_Wol);
    cudaGetSymbolAddress((void**)&Gh,   g_Gh);   cudaGetSymbolAddress((void**)&W2h,  g_W2h);
    cudaGetSymbolAddress((void**)&Zh,   g_Zh);
    cudaGetSymbolAddress((void**)&Uh,   g_Uh);   cudaGetSymbolAddress((void**)&Ph,   g_Ph);

    cudaFuncSetAttribute((const void*)gemm_tc<3,2>, cudaFuncAttributeMaxDynamicSharedMemorySize, SM3);
    cudaFuncSetAttribute((const void*)gemm_tc<2,2>, cudaFuncAttributeMaxDynamicSharedMemorySize, SM2);
    cudaFuncSetAttribute((const void*)gemm_tc<1,2>, cudaFuncAttributeMaxDynamicSharedMemorySize, SM1);
    cudaFuncSetAttribute((const void*)band_tc,      cudaFuncAttributeMaxDynamicSharedMemorySize, SM1);
    cudaFuncSetAttribute((const void*)ptv_tc,       cudaFuncAttributeMaxDynamicSharedMemorySize, SM1);

    // 1. operand prep
    split2<<<4096, 256>>>(x, xh, xl, (BB * NN * DD) / 2);
    transpose_split3<<<dim3(32, 32, 3), dim3(32, 8)>>>(
        Wk, WkTh, WkTl, Wq, WqTh, WqTl, Wv, WvTh, WvTl);
    split2<<<512, 256>>>(Wo, Woh, Wol, (DD * DD) / 2);

    // 2. G[d2,d1] = sum_o WkT[d2,o]*WqT[d1,o]      (3-term, high-only)
    gemm_tc<3,2><<<dim3(8, 8), 256, SM3>>>(WkTh, WkTl, WqTh, WqTl,
                                           nullptr, Gh, nullptr, DD, DD, 1.0f);
    //    W2[i,d] = sum_o Wo[i,o]*WvT[d,o]          (3-term, high-only)
    gemm_tc<3,2><<<dim3(8, 8), 256, SM3>>>(Woh, Wol, WvTh, WvTl,
                                           nullptr, W2h, nullptr, DD, DD, 1.0f);

    // 3. Z[n,d2] = sum_d1 x[n,d1]*G[d2,d1]         (2-term, single-h out)
    dim3 gP(DD / 128, (BB * NN) / 128);
    gemm_tc<2,2><<<gP, 256, SM2>>>(xh, xl, Gh, nullptr, nullptr, Zh, nullptr, DD, DD, 1.0f);

    // 4. U[n,i] = sum_d xh[n,d]*W2[i,d]            (1-term, single-h out)
    gemm_tc<1,2><<<gP, 256, SM1>>>(xh, nullptr, W2h, nullptr, nullptr, Uh, nullptr, DD, DD, 1.0f);

    // 5. banded logits = QS * Zh·xh^T (1-term; zeroes out-of-band att, distributed)
    band_tc<<<dim3(5, NN / 128, BB), 256, SM1>>>(Zh, xh, att_out);

    // 6. softmax + P emit
    band_softmax<<<BB * NN, 128>>>(att_out, Ph);

    // 7. y = P^T @ U (banded, 1-term, fp32 out — final)
    ptv_tc<<<dim3(DD / 128, NN / 128, BB), 256, SM1>>>(Ph, Uh, y_out);
}

// round 13
// speedup vs baseline: 7.8270x; 1.0623x over previous
#include <cuda_runtime.h>
#include <cuda_fp16.h>
#include <cstdint>

#define BB   4
#define NN   4096
#define DD   1024
#define AP   256
#define QS   0.06f

#define NSTAGE 3
#define ST_OF(T) ((T)==3 ? 32768u : (T)==2 ? 24576u : 16384u)
#define SM3    (NSTAGE*32768)
#define SM2    (NSTAGE*24576)
#define SM1    (NSTAGE*16384)

// ---------------------------------------------------------------------------
// device scratch (allocation-free rule)
// ---------------------------------------------------------------------------
__device__ __align__(16) __half g_xh[BB*NN*DD], g_xl[BB*NN*DD];
__device__ __align__(16) __half g_WkTh[DD*DD], g_WkTl[DD*DD];
__device__ __align__(16) __half g_WqTh[DD*DD], g_WqTl[DD*DD];
__device__ __align__(16) __half g_WvTh[DD*DD], g_WvTl[DD*DD];
__device__ __align__(16) __half g_Woh[DD*DD], g_Wol[DD*DD];
__device__ __align__(16) __half g_Gh[DD*DD];
__device__ __align__(16) __half g_W2h[DD*DD];
__device__ __align__(16) __half g_Zh[BB*NN*DD];
__device__ __align__(16) __half g_Uh[BB*NN*DD];
__device__ __align__(16) __half g_Ph[(size_t)BB*NN*NN];

// ---------------------------------------------------------------------------
// PTX helpers — baseline (non-arch-specific) instructions only
// ---------------------------------------------------------------------------
__device__ __forceinline__ uint32_t smem_u32(const void* p) {
    uint32_t a;
    asm("{ .reg .u64 t; cvta.to.shared.u64 t, %1; cvt.u32.u64 %0, t; }" : "=r"(a) : "l"(p));
    return a;
}
__device__ __forceinline__ void cp16(uint32_t s, const void* g) {
    asm volatile("cp.async.cg.shared.global [%0], [%1], 16;" :: "r"(s), "l"(g));
}
__device__ __forceinline__ void ldsm4(uint32_t* r, uint32_t a) {
    asm volatile("ldmatrix.sync.aligned.m8n8.x4.shared.b16 {%0,%1,%2,%3}, [%4];"
        : "=r"(r[0]), "=r"(r[1]), "=r"(r[2]), "=r"(r[3]) : "r"(a));
}
__device__ __forceinline__ void ldsm4t(uint32_t* r, uint32_t a) {
    asm volatile("ldmatrix.sync.aligned.m8n8.x4.trans.shared.b16 {%0,%1,%2,%3}, [%4];"
        : "=r"(r[0]), "=r"(r[1]), "=r"(r[2]), "=r"(r[3]) : "r"(a));
}
__device__ __forceinline__ void mmah(float* d, const uint32_t* a, const uint32_t* b) {
    asm volatile("mma.sync.aligned.m16n8k16.row.col.f32.f16.f16.f32 "
        "{%0,%1,%2,%3}, {%4,%5,%6,%7}, {%8,%9}, {%0,%1,%2,%3};"
        : "+f"(d[0]), "+f"(d[1]), "+f"(d[2]), "+f"(d[3])
        : "r"(a[0]), "r"(a[1]), "r"(a[2]), "r"(a[3]), "r"(b[0]), "r"(b[1]));
}
#define SW64(off)  ((off) ^ (((off) >> 3) & 0x30))
#define SW256(off) ((off) ^ (((off) >> 4) & 0x70))

// ===========================================================================
// dense NT GEMM pipeline (fp16 split; 64B smem rows, K-chunks of 32)
// TERMS==3: Ah·Bh + Al·Bh + Ah·Bl  | TERMS==2: Ah·Bh + Al·Bh | TERMS==1: Ah·Bh
// ===========================================================================
template<int TERMS>
__device__ __forceinline__ void issue_chunk(
    uint32_t sbase, int tid,
    const __half* pAh, const __half* pAl, const __half* pBh, const __half* pBl,
    int Kd, int k0)
{
    const uint32_t BOFF = (TERMS >= 2) ? 16384u : 8192u;
#pragma unroll
    for (int j = 0; j < 2; j++) {
        int e = tid + (j << 8);
        int r = e >> 2, c = e & 3;
        uint32_t sw = SW64((uint32_t)(r << 6) + (c << 4));
        size_t g = (size_t)r * Kd + k0 + (c << 3);
        cp16(sbase + sw, pAh + g);
        if (TERMS >= 2) cp16(sbase + 8192u + sw, pAl + g);
        cp16(sbase + BOFF + sw, pBh + g);
        if (TERMS == 3) cp16(sbase + 24576u + sw, pBl + g);
    }
    asm volatile("cp.async.commit_group;" ::: "memory");
}

template<int TERMS>
__device__ __forceinline__ void compute_chunk(
    float acc[4][4][4], uint32_t sb, int lane, int warp_m, int warp_n)
{
    const uint32_t BOFF = (TERMS >= 2) ? 16384u : 8192u;
#pragma unroll
    for (int ks = 0; ks < 2; ks++) {
        uint32_t ah[4][4], al[4][4], bh[4][2], bl[4][2];
#pragma unroll
        for (int mi = 0; mi < 4; mi++) {
            int row = warp_m*64 + mi*16 + ((lane >> 3) & 1)*8 + (lane & 7);
            int kb  = ks*32 + (lane >> 4)*16;
            uint32_t a = sb + SW64((uint32_t)(row << 6) + kb);
            ldsm4(ah[mi], a);
            if (TERMS >= 2) ldsm4(al[mi], a + 8192u);
        }
#pragma unroll
        for (int nj = 0; nj < 2; nj++) {
            int nr = warp_n*32 + nj*16 + (lane >> 4)*8 + (lane & 7);
            int kb = ks*32 + ((lane >> 3) & 1)*16;
            uint32_t a = sb + BOFF + SW64((uint32_t)(nr << 6) + kb);
            uint32_t t[4];
            ldsm4(t, a);
            bh[nj*2][0] = t[0]; bh[nj*2][1] = t[1];
            bh[nj*2+1][0] = t[2]; bh[nj*2+1][1] = t[3];
            if (TERMS == 3) {
                ldsm4(t, a + 8192u);
                bl[nj*2][0] = t[0]; bl[nj*2][1] = t[1];
                bl[nj*2+1][0] = t[2]; bl[nj*2+1][1] = t[3];
            }
        }
#pragma unroll
        for (int mi = 0; mi < 4; mi++)
#pragma unroll
            for (int ni = 0; ni < 4; ni++) {
                mmah(acc[mi][ni], ah[mi], bh[ni]);
                if (TERMS >= 2) mmah(acc[mi][ni], al[mi], bh[ni]);
                if (TERMS == 3) mmah(acc[mi][ni], ah[mi], bl[ni]);
            }
    }
}

template<int TERMS>
__device__ __forceinline__ void hmma_loop(
    float acc[4][4][4], char* smem, int tid,
    const __half* pAh, const __half* pAl,
    const __half* pBh, const __half* pBl, int Kd)
{
    const int lane = tid & 31, wid = tid >> 5;
    const int warp_m = wid >> 2, warp_n = wid & 3;
    const uint32_t STG = ST_OF(TERMS);
    uint32_t sb0 = smem_u32(smem);
    const int KC = Kd >> 5;

    issue_chunk<TERMS>(sb0,       tid, pAh, pAl, pBh, pBl, Kd, 0);
    issue_chunk<TERMS>(sb0 + STG, tid, pAh, pAl, pBh, pBl, Kd, 32);

    for (int i = 0; i < KC; i++) {
        if (i + 2 < KC) {
            issue_chunk<TERMS>(sb0 + ((i + 2) % NSTAGE)*STG, tid,
                               pAh, pAl, pBh, pBl, Kd, (i + 2) << 5);
            asm volatile("cp.async.wait_group 2;" ::: "memory");
        } else {
            asm volatile("cp.async.wait_group 0;" ::: "memory");
        }
        __syncthreads();
        compute_chunk<TERMS>(acc, sb0 + (i % NSTAGE)*STG, lane, warp_m, warp_n);
        __syncthreads();
    }
}

// epilogue: single-h fp16 store
__device__ __forceinline__ void store_h(
    float acc[4][4][4], __half* C, int row0, int col0, int lane, int warp_m, int warp_n)
{
    const int rb = row0 + warp_m*64 + (lane >> 2);
    const int cb = col0 + warp_n*32 + (lane & 3)*2;
#pragma unroll
    for (int mi = 0; mi < 4; mi++)
#pragma unroll
        for (int ni = 0; ni < 4; ni++)
#pragma unroll
            for (int h = 0; h < 2; h++) {
                size_t o = (size_t)(rb + mi*16 + 8*h) * DD + cb + ni*8;
                *(__half2*)&C[o] = __halves2half2(
                    __float2half(acc[mi][ni][2*h + 0]),
                    __float2half(acc[mi][ni][2*h + 1]));
            }
}

// ---------------------------------------------------------------------------
// merged weight GEMMs: z==0: G = WkT @ WqT^T ; z==1: W2 = Wo @ WvT^T (3-term)
// grid (8, 8, 2)
// ---------------------------------------------------------------------------
__global__ void __launch_bounds__(256, 1) wgemm_tc(
    const __half* __restrict__ A0h, const __half* __restrict__ A0l,
    const __half* __restrict__ B0h, const __half* __restrict__ B0l,
    __half* __restrict__ C0,
    const __half* __restrict__ A1h, const __half* __restrict__ A1l,
    const __half* __restrict__ B1h, const __half* __restrict__ B1l,
    __half* __restrict__ C1)
{
    extern __shared__ char smem[];
    const int tid = threadIdx.x, lane = tid & 31, wid = tid >> 5;
    const int warp_m = wid >> 2, warp_n = wid & 3;
    const int row0 = blockIdx.y << 7, col0 = blockIdx.x << 7;
    const bool z1 = (blockIdx.z != 0);
    const __half* Ah = (z1 ? A1h : A0h) + (size_t)row0 * DD;
    const __half* Al = (z1 ? A1l : A0l) + (size_t)row0 * DD;
    const __half* Bh = (z1 ? B1h : B0h) + (size_t)col0 * DD;
    const __half* Bl = (z1 ? B1l : B0l) + (size_t)col0 * DD;
    __half* C = z1 ? C1 : C0;

    float acc[4][4][4] = {};
    hmma_loop<3>(acc, smem, tid, Ah, Al, Bh, Bl, DD);
    store_h(acc, C, row0, col0, lane, warp_m, warp_n);
}

// ---------------------------------------------------------------------------
// merged activation GEMMs: z==0: Z = x @ G^T (2-term) ; z==1: U = xh @ W2^T (1-term)
// grid (8, 128, 2)
// ---------------------------------------------------------------------------
__global__ void __launch_bounds__(256, 1) zu_tc(
    const __half* __restrict__ xh, const __half* __restrict__ xl,
    const __half* __restrict__ Gh, const __half* __restrict__ W2h,
    __half* __restrict__ Zh, __half* __restrict__ Uh)
{
    extern __shared__ char smem[];
    const int tid = threadIdx.x, lane = tid & 31, wid = tid >> 5;
    const int warp_m = wid >> 2, warp_n = wid & 3;
    const int row0 = blockIdx.y << 7, col0 = blockIdx.x << 7;

    float acc[4][4][4] = {};
    if (blockIdx.z == 0) {
        hmma_loop<2>(acc, smem, tid,
                     xh + (size_t)row0 * DD, xl + (size_t)row0 * DD,
                     Gh + (size_t)col0 * DD, nullptr, DD);
        store_h(acc, Zh, row0, col0, lane, warp_m, warp_n);
    } else {
        hmma_loop<1>(acc, smem, tid,
                     xh + (size_t)row0 * DD, nullptr,
                     W2h + (size_t)col0 * DD, nullptr, DD);
        store_h(acc, Uh, row0, col0, lane, warp_m, warp_n);
    }
}

// ---------------------------------------------------------------------------
// banded logits: att[b,n,m] = QS * Zh[b,n]·xh[b,m], |n-m| < AP  (1-term)
// distributed zeroing of out-of-window columns across the 5 blocks per strip
// ---------------------------------------------------------------------------
__global__ void __launch_bounds__(256, 1) band_tc(
    const __half* __restrict__ Zh, const __half* __restrict__ xh,
    float* __restrict__ att)
{
    const int it = blockIdx.y;
    const int jt = it + (int)blockIdx.x - 2;
    const int bz = blockIdx.z;
    const int tid = threadIdx.x;
    float* attb = att + ((size_t)bz << 24);
    const int row0 = it << 7;
    const int lane = tid & 31, wid = tid >> 5;

    {
        int lo_t = it - 2; if (lo_t < 0) lo_t = 0;
        int hi_t = it + 2; if (hi_t > 31) hi_t = 31;
        const int cL4 = lo_t << 5;
        const int cR0 = (hi_t + 1) << 5;
        float4 z4 = make_float4(0.f, 0.f, 0.f, 0.f);
        for (int j = wid; ; j += 8) {
            int r = (int)blockIdx.x + 5 * j;
            if (r >= 128) break;
            float4* rp = (float4*)(attb + (size_t)(row0 + r) * NN);
            for (int c = lane; c < cL4; c += 32) rp[c] = z4;
            for (int c = cR0 + lane; c < (NN >> 2); c += 32) rp[c] = z4;
        }
    }
    if (jt < 0 || jt >= (NN >> 7)) return;

    extern __shared__ char smem[];
    const int warp_m = wid >> 2, warp_n = wid & 3;
    const int col0 = jt << 7;
    const size_t boff = (size_t)bz << 22;

    float acc[4][4][4] = {};
    hmma_loop<1>(acc, smem, tid,
                 Zh + boff + (size_t)row0 * DD, nullptr,
                 xh + boff + (size_t)col0 * DD, nullptr, DD);

    const int rb = row0 + warp_m*64 + (lane >> 2);
    const int cb = col0 + warp_n*32 + (lane & 3)*2;
#pragma unroll
    for (int mi = 0; mi < 4; mi++)
#pragma unroll
        for (int ni = 0; ni < 4; ni++)
#pragma unroll
            for (int h = 0; h < 2; h++) {
                int gi = rb + mi*16 + 8*h;
                int gj = cb + ni*8;
                int d0 = gi - gj, d1 = gi - gj - 1;
                float w0 = (d0 > -AP && d0 < AP) ? acc[mi][ni][2*h + 0] * QS : 0.f;
                float w1 = (d1 > -AP && d1 < AP) ? acc[mi][ni][2*h + 1] * QS : 0.f;
                *(float2*)&attb[(size_t)gi * NN + gj] = make_float2(w0, w1);
            }
}

// ---------------------------------------------------------------------------
// splits & batched transpose
// ---------------------------------------------------------------------------
__global__ void split2(const float* __restrict__ in,
                       __half* __restrict__ h, __half* __restrict__ l, int n2)
{
    int i = blockIdx.x * blockDim.x + threadIdx.x;
    int st = gridDim.x * blockDim.x;
    for (; i < n2; i += st) {
        float2 v = ((const float2*)in)[i];
        __half hx = __float2half(v.x), hy = __float2half(v.y);
        ((__half2*)h)[i] = __halves2half2(hx, hy);
        ((__half2*)l)[i] = __halves2half2(__float2half(v.x - __half2float(hx)),
                                          __float2half(v.y - __half2float(hy)));
    }
}
__global__ void transpose_split3(
    const float* __restrict__ w0, __half* __restrict__ t0h, __half* __restrict__ t0l,
    const float* __restrict__ w1, __half* __restrict__ t1h, __half* __restrict__ t1l,
    const float* __restrict__ w2, __half* __restrict__ t2h, __half* __restrict__ t2l)
{
    const float* in = (blockIdx.z == 0) ? w0 : (blockIdx.z == 1) ? w1 : w2;
    __half* th = (blockIdx.z == 0) ? t0h : (blockIdx.z == 1) ? t1h : t2h;
    __half* tl = (blockIdx.z == 0) ? t0l : (blockIdx.z == 1) ? t1l : t2l;
    __shared__ float t[32][33];
    int bx = blockIdx.x << 5, by = blockIdx.y << 5;
#pragma unroll
    for (int k = 0; k < 32; k += 8)
        t[threadIdx.y + k][threadIdx.x] = in[(size_t)(by + threadIdx.y + k) * DD + bx + threadIdx.x];
    __syncthreads();
#pragma unroll
    for (int k = 0; k < 32; k += 8) {
        int r = bx + threadIdx.y + k, c = by + threadIdx.x;
        float v = t[threadIdx.x][threadIdx.y + k];
        __half h = __float2half(v);
        th[(size_t)r * DD + c] = h;
        tl[(size_t)r * DD + c] = __float2half(v - __half2float(h));
    }
}

// ---------------------------------------------------------------------------
// band softmax + fp16 P emit over padded window
// ---------------------------------------------------------------------------
__global__ void __launch_bounds__(128) band_softmax(
    float* __restrict__ att, __half* __restrict__ Ph)
{
    __shared__ float red[4];
    const int gid = blockIdx.x;
    const int b = gid >> 12;
    const int i = gid & (NN - 1);
    const size_t rowbase = ((size_t)b << 24) + ((size_t)i << 12);
    float* row = att + rowbase;
    int jlo = i - (AP - 1); if (jlo < 0) jlo = 0;
    int jhi = i + (AP - 1); if (jhi > NN - 1) jhi = NN - 1;
    const int cnt = jhi - jlo + 1;

    float v[4];
    int nc = 0;
    float m = -1e30f;
    for (int t = threadIdx.x; t < cnt; t += 128) { v[nc] = row[jlo + t]; m = fmaxf(m, v[nc]); nc++; }
    for (int o = 16; o > 0; o >>= 1) m = fmaxf(m, __shfl_xor_sync(0xffffffffu, m, o));
    const int w = threadIdx.x >> 5;
    if ((threadIdx.x & 31) == 0) red[w] = m;
    __syncthreads();
    m = fmaxf(fmaxf(red[0], red[1]), fmaxf(red[2], red[3]));
    __syncthreads();

    float s = 0.f;
    for (int c = 0; c < nc; c++) { v[c] = __expf(v[c] - m); s += v[c]; }
    for (int o = 16; o > 0; o >>= 1) s += __shfl_xor_sync(0xffffffffu, s, o);
    if ((threadIdx.x & 31) == 0) red[w] = s;
    __syncthreads();
    s = red[0] + red[1] + red[2] + red[3];
    const float inv = 1.0f / s;

    nc = 0;
    for (int t = threadIdx.x; t < cnt; t += 128) { row[jlo + t] = v[nc] * inv; nc++; }
    __syncthreads();

    int wlo = i - 256; wlo &= ~127; if (wlo < 0) wlo = 0;
    int whi = (i + 384) & ~127; if (whi > NN) whi = NN;
    for (int n = wlo + threadIdx.x; n < whi; n += 128) {
        float f = (n >= jlo && n <= jhi) ? row[n] : 0.f;
        Ph[rowbase + n] = __float2half(f);
    }
}

// ===========================================================================
// ptv: y[b,n,i] = sum_m P[b,m,n] * U[b,m,i]   (banded, 1-term, trans-ldsm)
// ===========================================================================
__device__ __forceinline__ void ptv_issue(
    uint32_t sbase, int tid,
    const __half* Phg, const __half* Uhg, int m0, int n0, int o0)
{
#pragma unroll
    for (int j = 0; j < 2; j++) {
        int e = tid + (j << 8);
        int r = e >> 4, c16 = e & 15;
        uint32_t sw = SW256((uint32_t)(r << 8) + (c16 << 4));
        cp16(sbase +         sw, Phg + (size_t)(m0 + r) * NN + n0 + (c16 << 3));
        cp16(sbase + 8192u + sw, Uhg + (size_t)(m0 + r) * DD + o0 + (c16 << 3));
    }
    asm volatile("cp.async.commit_group;" ::: "memory");
}

__device__ __forceinline__ void ptv_compute(
    float acc[4][4][4], uint32_t sb, int lane, int warp_m, int warp_n)
{
#pragma unroll
    for (int ks = 0; ks < 2; ks++) {
        const int m16 = ks << 4;
        uint32_t ah[4][4], bh[4][2];
        const int ar = m16 + ((lane >> 4) << 3) + (lane & 7);
        const int acsel = ((lane >> 3) & 1) << 3;
#pragma unroll
        for (int mi = 0; mi < 4; mi++) {
            int nb = warp_m*64 + mi*16 + acsel;
            ldsm4t(ah[mi], sb + SW256((uint32_t)(ar << 8) + (nb << 1)));
        }
        const int br = m16 + (((lane >> 3) & 1) << 3) + (lane & 7);
        const int bcsel = (lane >> 4) << 3;
#pragma unroll
        for (int jb = 0; jb < 2; jb++) {
            int ob = warp_n*32 + jb*16 + bcsel;
            uint32_t t4[4];
            ldsm4t(t4, sb + 8192u + SW256((uint32_t)(br << 8) + (ob << 1)));
            bh[jb*2][0] = t4[0]; bh[jb*2][1] = t4[1];
            bh[jb*2+1][0] = t4[2]; bh[jb*2+1][1] = t4[3];
        }
#pragma unroll
        for (int mi = 0; mi < 4; mi++)
#pragma unroll
            for (int ni = 0; ni < 4; ni++)
                mmah(acc[mi][ni], ah[mi], bh[ni]);
    }
}

__global__ void __launch_bounds__(256, 1) ptv_tc(
    const __half* __restrict__ Phg, const __half* __restrict__ Uhg,
    float* __restrict__ yout)
{
    const int bz = blockIdx.z;
    const int n0 = blockIdx.y << 7;
    const int o0 = blockIdx.x << 7;
    const __half* Pb = Phg + ((size_t)bz << 24);
    const __half* Ub = Uhg + ((size_t)bz << 22);

    extern __shared__ char smem[];
    uint32_t sb0 = smem_u32(smem);
    const int tid = threadIdx.x, lane = tid & 31, wid = tid >> 5;
    const int warp_m = wid >> 2, warp_n = wid & 3;

    int mlo = n0 - 256; if (mlo < 0) mlo = 0;
    int mhe = n0 + 384; if (mhe > NN) mhe = NN;
    const int NC = (mhe - mlo) >> 5;

    float acc[4][4][4] = {};

    ptv_issue(sb0,          tid, Pb, Ub, mlo,      n0, o0);
    ptv_issue(sb0 + 16384u, tid, Pb, Ub, mlo + 32, n0, o0);

    for (int i = 0; i < NC; i++) {
        if (i + 2 < NC) {
            ptv_issue(sb0 + ((i + 2) % NSTAGE)*16384u, tid,
                      Pb, Ub, mlo + ((i + 2) << 5), n0, o0);
            asm volatile("cp.async.wait_group 2;" ::: "memory");
        } else {
            asm volatile("cp.async.wait_group 0;" ::: "memory");
        }
        __syncthreads();
        ptv_compute(acc, sb0 + (i % NSTAGE)*16384u, lane, warp_m, warp_n);
        __syncthreads();
    }

    float* yb = yout + ((size_t)bz << 22);
    const int rb = n0 + warp_m*64 + (lane >> 2);
    const int cb = o0 + warp_n*32 + (lane & 3)*2;
#pragma unroll
    for (int mi = 0; mi < 4; mi++)
#pragma unroll
        for (int ni = 0; ni < 4; ni++)
#pragma unroll
            for (int h = 0; h < 2; h++) {
                size_t off = (size_t)(rb + mi*16 + 8*h) * DD + cb + ni*8;
                *(float2*)&yb[off] = make_float2(acc[mi][ni][2*h + 0],
                                                 acc[mi][ni][2*h + 1]);
            }
}

// ---------------------------------------------------------------------------
extern "C" void kernel_launch(void* const* d_in, const int* in_sizes, int n_in,
                              void* d_out, int out_size)
{
    const float* x  = (const float*)d_in[0];
    const float* Wk = (const float*)d_in[1];
    const float* Wq = (const float*)d_in[2];
    const float* Wv = (const float*)d_in[3];
    const float* Wo = (const float*)d_in[4];

    float* y_out   = (float*)d_out;
    float* att_out = y_out + (size_t)BB * NN * DD;

    __half *xh, *xl, *WkTh, *WkTl, *WqTh, *WqTl, *WvTh, *WvTl, *Woh, *Wol;
    __half *Gh, *W2h, *Zh, *Uh, *Ph;
    cudaGetSymbolAddress((void**)&xh,   g_xh);   cudaGetSymbolAddress((void**)&xl,   g_xl);
    cudaGetSymbolAddress((void**)&WkTh, g_WkTh); cudaGetSymbolAddress((void**)&WkTl, g_WkTl);
    cudaGetSymbolAddress((void**)&WqTh, g_WqTh); cudaGetSymbolAddress((void**)&WqTl, g_WqTl);
    cudaGetSymbolAddress((void**)&WvTh, g_WvTh); cudaGetSymbolAddress((void**)&WvTl, g_WvTl);
    cudaGetSymbolAddress((void**)&Woh,  g_Woh);  cudaGetSymbolAddress((void**)&Wol,  g_Wol);
    cudaGetSymbolAddress((void**)&Gh,   g_Gh);   cudaGetSymbolAddress((void**)&W2h,  g_W2h);
    cudaGetSymbolAddress((void**)&Zh,   g_Zh);
    cudaGetSymbolAddress((void**)&Uh,   g_Uh);   cudaGetSymbolAddress((void**)&Ph,   g_Ph);

    cudaFuncSetAttribute((const void*)wgemm_tc, cudaFuncAttributeMaxDynamicSharedMemorySize, SM3);
    cudaFuncSetAttribute((const void*)zu_tc,    cudaFuncAttributeMaxDynamicSharedMemorySize, SM2);
    cudaFuncSetAttribute((const void*)band_tc,  cudaFuncAttributeMaxDynamicSharedMemorySize, SM1);
    cudaFuncSetAttribute((const void*)ptv_tc,   cudaFuncAttributeMaxDynamicSharedMemorySize, SM1);

    // 1. operand prep
    split2<<<4096, 256>>>(x, xh, xl, (BB * NN * DD) / 2);
    transpose_split3<<<dim3(32, 32, 3), dim3(32, 8)>>>(
        Wk, WkTh, WkTl, Wq, WqTh, WqTl, Wv, WvTh, WvTl);
    split2<<<512, 256>>>(Wo, Woh, Wol, (DD * DD) / 2);

    // 2. G = WkT @ WqT^T  and  W2 = Wo @ WvT^T  (one launch, 128 CTAs)
    wgemm_tc<<<dim3(8, 8, 2), 256, SM3>>>(WkTh, WkTl, WqTh, WqTl, Gh,
                                          Woh, Wol, WvTh, WvTl, W2h);

    // 3+4. Z = x @ G^T (2-term)  and  U = xh @ W2^T (1-term)  (one launch)
    zu_tc<<<dim3(8, 128, 2), 256, SM2>>>(xh, xl, Gh, W2h, Zh, Uh);

    // 5. banded logits = QS * Zh·xh^T (1-term; zeroes out-of-band att)
    band_tc<<<dim3(5, NN / 128, BB), 256, SM1>>>(Zh, xh, att_out);

    // 6. softmax + P emit
    band_softmax<<<BB * NN, 128>>>(att_out, Ph);

    // 7. y = P^T @ U (banded, 1-term, fp32 out — final)
    ptv_tc<<<dim3(DD / 128, NN / 128, BB), 256, SM1>>>(Ph, Uh, y_out);
}